// round 8
// baseline (speedup 1.0000x reference)
#include <cuda_runtime.h>
#include <cuda_bf16.h>
#include <cstdint>
#include <math.h>

#define BATCH 2
#define SEQ   2048
#define DM    1024
#define NH    16
#define DEPTH 64
#define MTOT  (BATCH*SEQ)   // 4096

#define QSCALE 0.1803368801111204f   // 0.125 * log2(e): scores in log2 domain

// Pre-split bf16 scratch
__device__ __nv_bfloat16 g_Ihi[3*MTOT*DM];           // q,k,v inputs, flat [M,K]
__device__ __nv_bfloat16 g_Ilo[3*MTOT*DM];
__device__ __nv_bfloat16 g_Whi[4*DM*DM];             // wq,wk,wv,wo
__device__ __nv_bfloat16 g_Wlo[4*DM*DM];
__device__ __nv_bfloat16 g_Qhi[BATCH*NH*SEQ*DEPTH];  // [B,H,S,D], pre-scaled
__device__ __nv_bfloat16 g_Qlo[BATCH*NH*SEQ*DEPTH];
__device__ __nv_bfloat16 g_Khi[BATCH*NH*SEQ*DEPTH];  // [B,H,S,D]
__device__ __nv_bfloat16 g_Klo[BATCH*NH*SEQ*DEPTH];
__device__ __nv_bfloat16 g_VThi[BATCH*NH*DEPTH*SEQ]; // [B,H,D,S]
__device__ __nv_bfloat16 g_VTlo[BATCH*NH*DEPTH*SEQ];
__device__ __nv_bfloat16 g_Ohi[MTOT*DM];             // attn out, flat [M,1024]
__device__ __nv_bfloat16 g_Olo[MTOT*DM];

// ===========================================================================
// helpers
// ===========================================================================
__device__ __forceinline__ uint32_t smem_u32(const void* p) {
    uint32_t a;
    asm("{ .reg .u64 t; cvta.to.shared.u64 t, %1; cvt.u32.u64 %0, t; }"
        : "=r"(a) : "l"(p));
    return a;
}
__device__ __forceinline__ uint32_t pack_bf16(float x, float y) {
    uint32_t lo = __bfloat16_as_ushort(__float2bfloat16(x));
    uint32_t hi = __bfloat16_as_ushort(__float2bfloat16(y));
    return lo | (hi << 16);
}
__device__ __forceinline__ float rb(float x) {
    return __bfloat162float(__float2bfloat16(x));
}
__device__ __forceinline__ float ex2(float x) {
    float y; asm("ex2.approx.ftz.f32 %0, %1;" : "=f"(y) : "f"(x)); return y;
}

#define LDSM4(R, addr) \
    asm volatile("ldmatrix.sync.aligned.m8n8.x4.shared.b16 {%0,%1,%2,%3}, [%4];" \
        : "=r"((R)[0]), "=r"((R)[1]), "=r"((R)[2]), "=r"((R)[3]) : "r"(addr))

#define MMA16816(D, A, B0, B1) \
    asm volatile("mma.sync.aligned.m16n8k16.row.col.f32.bf16.bf16.f32 " \
        "{%0,%1,%2,%3}, {%4,%5,%6,%7}, {%8,%9}, {%0,%1,%2,%3};" \
        : "+f"((D)[0]), "+f"((D)[1]), "+f"((D)[2]), "+f"((D)[3]) \
        : "r"((A)[0]), "r"((A)[1]), "r"((A)[2]), "r"((A)[3]), "r"(B0), "r"(B1))

#define CP16(dst, src) \
    asm volatile("cp.async.cg.shared.global [%0], [%1], 16;" \
        :: "r"(dst), "l"(src) : "memory")
#define CP_COMMIT()  asm volatile("cp.async.commit_group;" ::: "memory")
#define CP_WAIT0()   asm volatile("cp.async.wait_group 0;" ::: "memory")

// ===========================================================================
// Pre-split: fp32 -> bf16 hi/lo (grid-stride over float4)
// ===========================================================================
__global__ __launch_bounds__(256)
void split_k(const float* __restrict__ src, __nv_bfloat16* __restrict__ hi,
             __nv_bfloat16* __restrict__ lo, int n4)
{
    int i = blockIdx.x * 256 + threadIdx.x;
    if (i < n4) {
        float4 v = ((const float4*)src)[i];
        ((uint2*)hi)[i] = make_uint2(pack_bf16(v.x, v.y), pack_bf16(v.z, v.w));
        ((uint2*)lo)[i] = make_uint2(
            pack_bf16(v.x - rb(v.x), v.y - rb(v.y)),
            pack_bf16(v.z - rb(v.z), v.w - rb(v.w)));
    }
}

// ===========================================================================
// Pure-bf16 split GEMM: C = A @ W.T (+bias, *scale). All operands pre-split.
// CTA 128x128, BK=32, 8 warps (2m x 4n). cp.async -> ldmatrix smem (80B rows),
// double-buffered, 1 barrier/iter. OMODE: 0 fp32 [M,N]; 1 hi/lo [B,H,S,D];
// 2 hi/lo [B,H,D,S].
// ===========================================================================
#define ROWB 80
#define GMAT 10240                       // 128 rows x 80B
#define GBUF 40960                       // 4 matrices per buffer
#define GEMM_SMEM (2 * GBUF)             // 81920 -> 2 CTAs/SM

template<int OMODE>
__global__ __launch_bounds__(256, 2)
void gemm_bf(const __nv_bfloat16* __restrict__ Ahi,
             const __nv_bfloat16* __restrict__ Alo,
             const __nv_bfloat16* __restrict__ Whi,
             const __nv_bfloat16* __restrict__ Wlo,
             const float* __restrict__ bias, float* __restrict__ C32,
             __nv_bfloat16* __restrict__ Chi, __nv_bfloat16* __restrict__ Clo,
             float scale)
{
    extern __shared__ char smem[];
    const uint32_t sb = smem_u32(smem);

    const int tid = threadIdx.x;
    const int wid = tid >> 5, lid = tid & 31;
    const int warp_m = wid >> 2;
    const int warp_n = wid & 3;
    const int bm = blockIdx.x * 128, bn = blockIdx.y * 128;

    const int grp = lid >> 3, r = lid & 7;
    const uint32_t apat = (uint32_t)(warp_m * 64 + ((grp & 1) << 3) + r) * ROWB
                        + (uint32_t)(((grp >> 1) & 1) << 4);
    const uint32_t wpat = (uint32_t)(warp_n * 32 + (((grp >> 1) & 1) << 3) + r) * ROWB
                        + (uint32_t)((grp & 1) << 4);

    const int crow = tid >> 1;           // 0..127
    const int cch  = tid & 1;            // chunk pair index

    auto issue_tile = [&](int it) {
        const int k0 = it * 32;
        const uint32_t buf = sb + (uint32_t)(it & 1) * GBUF;
        // 4 matrices x 128 rows x 4 chunks(16B) = 2048 chunks; 8 per thread
#pragma unroll
        for (int l = 0; l < 2; l++) {
            int ch = cch * 2 + l;        // 0..3
            uint32_t doff = (uint32_t)crow * ROWB + (uint32_t)ch * 16;
            size_t aoff = (size_t)(bm + crow) * DM + k0 + ch * 8;
            size_t woff = (size_t)(bn + crow) * DM + k0 + ch * 8;
            CP16(buf + doff,            Ahi + aoff);
            CP16(buf + GMAT + doff,     Alo + aoff);
            CP16(buf + 2 * GMAT + doff, Whi + woff);
            CP16(buf + 3 * GMAT + doff, Wlo + woff);
        }
    };

    float acc[4][4][4];
#pragma unroll
    for (int i = 0; i < 4; i++)
#pragma unroll
        for (int j = 0; j < 4; j++)
#pragma unroll
            for (int e = 0; e < 4; e++) acc[i][j][e] = 0.f;

    issue_tile(0);
    CP_COMMIT();

    for (int it = 0; it < DM / 32; it++) {
        CP_WAIT0();
        __syncthreads();   // buffer it&1 ready; prev-iter reads done
        if (it + 1 < DM / 32) { issue_tile(it + 1); CP_COMMIT(); }

        const uint32_t buf = sb + (uint32_t)(it & 1) * GBUF;
#pragma unroll
        for (int ks = 0; ks < 2; ks++) {
            const uint32_t offk = (uint32_t)ks * 32;
            uint32_t ah[4][4], al[4][4], bh[2][4], bl[2][4];
#pragma unroll
            for (int fm = 0; fm < 4; fm++) {
                LDSM4(ah[fm], buf + apat + fm * (16 * ROWB) + offk);
                LDSM4(al[fm], buf + GMAT + apat + fm * (16 * ROWB) + offk);
            }
#pragma unroll
            for (int p = 0; p < 2; p++) {
                LDSM4(bh[p], buf + 2 * GMAT + wpat + p * (16 * ROWB) + offk);
                LDSM4(bl[p], buf + 3 * GMAT + wpat + p * (16 * ROWB) + offk);
            }
#pragma unroll
            for (int fm = 0; fm < 4; fm++)
#pragma unroll
                for (int fn = 0; fn < 4; fn++) {
                    const int p = fn >> 1, o = (fn & 1) << 1;
                    MMA16816(acc[fm][fn], ah[fm], bh[p][o], bh[p][o + 1]);
                    MMA16816(acc[fm][fn], ah[fm], bl[p][o], bl[p][o + 1]);
                    MMA16816(acc[fm][fn], al[fm], bh[p][o], bh[p][o + 1]);
                }
        }
    }

    const int qrow = lid >> 2;
    const int qcol = (lid & 3) << 1;
#pragma unroll
    for (int fm = 0; fm < 4; fm++) {
        int m1 = bm + warp_m * 64 + fm * 16 + qrow;
        int m2 = m1 + 8;
#pragma unroll
        for (int fn = 0; fn < 4; fn++) {
            int n = bn + warp_n * 32 + fn * 8 + qcol;
            float2 bb = *(const float2*)(bias + n);
            float x1 = (acc[fm][fn][0] + bb.x) * scale;
            float y1 = (acc[fm][fn][1] + bb.y) * scale;
            float x2 = (acc[fm][fn][2] + bb.x) * scale;
            float y2 = (acc[fm][fn][3] + bb.y) * scale;
            if (OMODE == 0) {
                *(float2*)(C32 + (size_t)m1 * DM + n) = make_float2(x1, y1);
                *(float2*)(C32 + (size_t)m2 * DM + n) = make_float2(x2, y2);
            } else {
                int h = n >> 6, dl = n & 63;
                int b1 = m1 >> 11, s1 = m1 & 2047;
                int b2 = m2 >> 11, s2 = m2 & 2047;
                if (OMODE == 1) {
                    size_t i1 = (size_t)((((b1 << 4) + h) * SEQ + s1) << 6) + dl;
                    size_t i2 = (size_t)((((b2 << 4) + h) * SEQ + s2) << 6) + dl;
                    *(uint32_t*)(Chi + i1) = pack_bf16(x1, y1);
                    *(uint32_t*)(Clo + i1) = pack_bf16(x1 - rb(x1), y1 - rb(y1));
                    *(uint32_t*)(Chi + i2) = pack_bf16(x2, y2);
                    *(uint32_t*)(Clo + i2) = pack_bf16(x2 - rb(x2), y2 - rb(y2));
                } else {
                    size_t t1 = ((size_t)((b1 << 4) + h) * 64 + dl) * SEQ + s1;
                    size_t t2 = ((size_t)((b2 << 4) + h) * 64 + dl) * SEQ + s2;
                    Chi[t1] = __float2bfloat16(x1);
                    Clo[t1] = __float2bfloat16(x1 - rb(x1));
                    Chi[t1 + SEQ] = __float2bfloat16(y1);
                    Clo[t1 + SEQ] = __float2bfloat16(y1 - rb(y1));
                    Chi[t2] = __float2bfloat16(x2);
                    Clo[t2] = __float2bfloat16(x2 - rb(x2));
                    Chi[t2 + SEQ] = __float2bfloat16(y2);
                    Clo[t2 + SEQ] = __float2bfloat16(y2 - rb(y2));
                }
            }
        }
    }
}

// ===========================================================================
// Tensor-core flash attention (round-7 validated), epilogue now emits
// bf16 hi/lo flat [M,1024] for the output projection.
// ===========================================================================
#define AROWB 144
#define AQHI  0
#define AQLO  18432
#define ABUF  36864
#define ATT_SMEM (ABUF + 2 * 36864)   // 110592 -> 2 CTAs/SM

__global__ __launch_bounds__(256, 2)
void attn_mma(const __nv_bfloat16* __restrict__ Qhi,
              const __nv_bfloat16* __restrict__ Qlo,
              const __nv_bfloat16* __restrict__ Khi,
              const __nv_bfloat16* __restrict__ Klo,
              const __nv_bfloat16* __restrict__ VThi,
              const __nv_bfloat16* __restrict__ VTlo,
              __nv_bfloat16* __restrict__ Ohi,
              __nv_bfloat16* __restrict__ Olo)
{
    extern __shared__ char smem[];
    const uint32_t sb = smem_u32(smem);
    const int tid = threadIdx.x, wid = tid >> 5, lid = tid & 31;
    const int grp = lid >> 3, r = lid & 7;

    const int b = blockIdx.z, h = blockIdx.y;
    const int bh = b * NH + h;
    const int q0 = blockIdx.x * 128;
    const __nv_bfloat16* Qhp = Qhi + (size_t)(bh * SEQ + q0) * DEPTH;
    const __nv_bfloat16* Qlp = Qlo + (size_t)(bh * SEQ + q0) * DEPTH;
    const __nv_bfloat16* Khp = Khi + (size_t)bh * SEQ * DEPTH;
    const __nv_bfloat16* Klp = Klo + (size_t)bh * SEQ * DEPTH;
    const __nv_bfloat16* Vhp = VThi + (size_t)bh * DEPTH * SEQ;
    const __nv_bfloat16* Vlp = VTlo + (size_t)bh * DEPTH * SEQ;

    const int crow = tid >> 3;
    const int cch  = tid & 7;

    auto issue_tile = [&](int kt) {
        const uint32_t buf = sb + ABUF + (uint32_t)(kt & 1) * 36864u;
        const int s0 = kt * 64;
#pragma unroll
        for (int l = 0; l < 8; l++) {
            int mat = l >> 1;
            int row = ((l & 1) << 5) + crow;
            uint32_t dst = buf + (uint32_t)mat * 9216u
                         + (uint32_t)row * AROWB + (uint32_t)cch * 16;
            const __nv_bfloat16* src;
            if (mat == 0)      src = Khp + (size_t)(s0 + row) * DEPTH + cch * 8;
            else if (mat == 1) src = Klp + (size_t)(s0 + row) * DEPTH + cch * 8;
            else if (mat == 2) src = Vhp + (size_t)row * SEQ + s0 + cch * 8;
            else               src = Vlp + (size_t)row * SEQ + s0 + cch * 8;
            CP16(dst, src);
        }
    };

#pragma unroll
    for (int l = 0; l < 8; l++) {
        int mat = l >> 2;
        int row = ((l & 3) << 5) + crow;
        uint32_t dst = sb + (uint32_t)mat * 18432u
                     + (uint32_t)row * AROWB + (uint32_t)cch * 16;
        const __nv_bfloat16* src = (mat == 0 ? Qhp : Qlp)
                                 + (size_t)row * DEPTH + cch * 8;
        CP16(dst, src);
    }
    issue_tile(0);
    CP_COMMIT();

    const uint32_t qbase = sb + (uint32_t)(wid * 16 + ((grp & 1) << 3) + r) * AROWB
                         + (uint32_t)(((grp >> 1) & 1) << 4);
    const uint32_t bpat  = (uint32_t)(((grp & 2) << 2) + r) * AROWB
                         + (uint32_t)((grp & 1) << 4);

    float o[8][4];
#pragma unroll
    for (int fn = 0; fn < 8; fn++)
#pragma unroll
        for (int e = 0; e < 4; e++) o[fn][e] = 0.f;
    float m1 = -1e30f, m2 = -1e30f, l1 = 0.f, l2 = 0.f;

    for (int kt = 0; kt < SEQ / 64; kt++) {
        CP_WAIT0();
        __syncthreads();
        if (kt + 1 < SEQ / 64) { issue_tile(kt + 1); CP_COMMIT(); }

        const uint32_t kvb = sb + ABUF + (uint32_t)(kt & 1) * 36864u + bpat;

        float s[8][4];
#pragma unroll
        for (int fn = 0; fn < 8; fn++)
#pragma unroll
            for (int e = 0; e < 4; e++) s[fn][e] = 0.f;

#pragma unroll
        for (int ks = 0; ks < 4; ks++) {
            uint32_t qh[4], ql[4];
            LDSM4(qh, qbase + AQHI + ks * 32);
            LDSM4(ql, qbase + AQLO + ks * 32);
            uint32_t kh[4][4], kl[4][4];
#pragma unroll
            for (int p = 0; p < 4; p++) {
                LDSM4(kh[p], kvb + p * (16 * AROWB) + ks * 32);
                LDSM4(kl[p], kvb + 9216 + p * (16 * AROWB) + ks * 32);
            }
#pragma unroll
            for (int fn = 0; fn < 8; fn++) {
                const int p = fn >> 1, o2 = (fn & 1) << 1;
                MMA16816(s[fn], qh, kh[p][o2], kh[p][o2 + 1]);
                MMA16816(s[fn], qh, kl[p][o2], kl[p][o2 + 1]);
                MMA16816(s[fn], ql, kh[p][o2], kh[p][o2 + 1]);
            }
        }

        float mx1 = -1e30f, mx2 = -1e30f;
#pragma unroll
        for (int fn = 0; fn < 8; fn++) {
            mx1 = fmaxf(mx1, fmaxf(s[fn][0], s[fn][1]));
            mx2 = fmaxf(mx2, fmaxf(s[fn][2], s[fn][3]));
        }
        mx1 = fmaxf(mx1, __shfl_xor_sync(0xffffffffu, mx1, 1));
        mx1 = fmaxf(mx1, __shfl_xor_sync(0xffffffffu, mx1, 2));
        mx2 = fmaxf(mx2, __shfl_xor_sync(0xffffffffu, mx2, 1));
        mx2 = fmaxf(mx2, __shfl_xor_sync(0xffffffffu, mx2, 2));

        float mn1 = fmaxf(m1, mx1), mn2 = fmaxf(m2, mx2);
        float c1 = ex2(m1 - mn1), c2 = ex2(m2 - mn2);
        m1 = mn1; m2 = mn2;

        float rs1 = 0.f, rs2 = 0.f;
#pragma unroll
        for (int fn = 0; fn < 8; fn++) {
            s[fn][0] = ex2(s[fn][0] - m1);
            s[fn][1] = ex2(s[fn][1] - m1);
            s[fn][2] = ex2(s[fn][2] - m2);
            s[fn][3] = ex2(s[fn][3] - m2);
            rs1 += s[fn][0] + s[fn][1];
            rs2 += s[fn][2] + s[fn][3];
        }
        rs1 += __shfl_xor_sync(0xffffffffu, rs1, 1);
        rs1 += __shfl_xor_sync(0xffffffffu, rs1, 2);
        rs2 += __shfl_xor_sync(0xffffffffu, rs2, 1);
        rs2 += __shfl_xor_sync(0xffffffffu, rs2, 2);
        l1 = l1 * c1 + rs1;
        l2 = l2 * c2 + rs2;
#pragma unroll
        for (int fn = 0; fn < 8; fn++) {
            o[fn][0] *= c1; o[fn][1] *= c1;
            o[fn][2] *= c2; o[fn][3] *= c2;
        }

#pragma unroll
        for (int ks = 0; ks < 4; ks++) {
            uint32_t pah[4], pal[4];
            {
                float p0 = s[2 * ks][0],     p1 = s[2 * ks][1];
                float p2 = s[2 * ks][2],     p3 = s[2 * ks][3];
                float p4 = s[2 * ks + 1][0], p5 = s[2 * ks + 1][1];
                float p6 = s[2 * ks + 1][2], p7 = s[2 * ks + 1][3];
                pah[0] = pack_bf16(p0, p1);  pah[1] = pack_bf16(p2, p3);
                pah[2] = pack_bf16(p4, p5);  pah[3] = pack_bf16(p6, p7);
                pal[0] = pack_bf16(p0 - rb(p0), p1 - rb(p1));
                pal[1] = pack_bf16(p2 - rb(p2), p3 - rb(p3));
                pal[2] = pack_bf16(p4 - rb(p4), p5 - rb(p5));
                pal[3] = pack_bf16(p6 - rb(p6), p7 - rb(p7));
            }
            uint32_t vh[4][4], vl[4][4];
#pragma unroll
            for (int p = 0; p < 4; p++) {
                LDSM4(vh[p], kvb + 18432 + p * (16 * AROWB) + ks * 32);
                LDSM4(vl[p], kvb + 27648 + p * (16 * AROWB) + ks * 32);
            }
#pragma unroll
            for (int fn = 0; fn < 8; fn++) {
                const int p = fn >> 1, o2 = (fn & 1) << 1;
                MMA16816(o[fn], pah, vh[p][o2], vh[p][o2 + 1]);
                MMA16816(o[fn], pah, vl[p][o2], vl[p][o2 + 1]);
                MMA16816(o[fn], pal, vh[p][o2], vh[p][o2 + 1]);
            }
        }
    }

    // ---- epilogue: normalize, split hi/lo, store flat [M,1024] ----
    float inv1 = 1.f / l1, inv2 = 1.f / l2;
    int m1r = b * SEQ + q0 + wid * 16 + (lid >> 2);
    int m2r = m1r + 8;
#pragma unroll
    for (int fn = 0; fn < 8; fn++) {
        int n = h * 64 + fn * 8 + (lid & 3) * 2;
        float x1 = o[fn][0] * inv1, y1 = o[fn][1] * inv1;
        float x2 = o[fn][2] * inv2, y2 = o[fn][3] * inv2;
        size_t i1 = (size_t)m1r * DM + n;
        size_t i2 = (size_t)m2r * DM + n;
        *(uint32_t*)(Ohi + i1) = pack_bf16(x1, y1);
        *(uint32_t*)(Olo + i1) = pack_bf16(x1 - rb(x1), y1 - rb(y1));
        *(uint32_t*)(Ohi + i2) = pack_bf16(x2, y2);
        *(uint32_t*)(Olo + i2) = pack_bf16(x2 - rb(x2), y2 - rb(y2));
    }
}

// ---------------------------------------------------------------------------
extern "C" void kernel_launch(void* const* d_in, const int* in_sizes, int n_in,
                              void* d_out, int out_size)
{
    const float* q  = (const float*)d_in[0];
    const float* k  = (const float*)d_in[1];
    const float* v  = (const float*)d_in[2];
    const float* wq = (const float*)d_in[3];
    const float* bq = (const float*)d_in[4];
    const float* wk = (const float*)d_in[5];
    const float* bk = (const float*)d_in[6];
    const float* wv = (const float*)d_in[7];
    const float* bv = (const float*)d_in[8];
    const float* wo = (const float*)d_in[9];
    const float* bo = (const float*)d_in[10];
    float* out = (float*)d_out;

    __nv_bfloat16 *gIh, *gIl, *gWh, *gWl;
    __nv_bfloat16 *gQh, *gQl, *gKh, *gKl, *gVh, *gVl, *gOh, *gOl;
    cudaGetSymbolAddress((void**)&gIh, g_Ihi);
    cudaGetSymbolAddress((void**)&gIl, g_Ilo);
    cudaGetSymbolAddress((void**)&gWh, g_Whi);
    cudaGetSymbolAddress((void**)&gWl, g_Wlo);
    cudaGetSymbolAddress((void**)&gQh, g_Qhi);
    cudaGetSymbolAddress((void**)&gQl, g_Qlo);
    cudaGetSymbolAddress((void**)&gKh, g_Khi);
    cudaGetSymbolAddress((void**)&gKl, g_Klo);
    cudaGetSymbolAddress((void**)&gVh, g_VThi);
    cudaGetSymbolAddress((void**)&gVl, g_VTlo);
    cudaGetSymbolAddress((void**)&gOh, g_Ohi);
    cudaGetSymbolAddress((void**)&gOl, g_Olo);

    cudaFuncSetAttribute(gemm_bf<0>,
                         cudaFuncAttributeMaxDynamicSharedMemorySize, GEMM_SMEM);
    cudaFuncSetAttribute(gemm_bf<1>,
                         cudaFuncAttributeMaxDynamicSharedMemorySize, GEMM_SMEM);
    cudaFuncSetAttribute(gemm_bf<2>,
                         cudaFuncAttributeMaxDynamicSharedMemorySize, GEMM_SMEM);
    cudaFuncSetAttribute(attn_mma,
                         cudaFuncAttributeMaxDynamicSharedMemorySize, ATT_SMEM);

    const int NIN = MTOT * DM / 4;   // 1M float4 per input
    const int NW  = DM * DM / 4;     // 256K float4 per weight
    split_k<<<NIN / 256, 256>>>(q, gIh,              gIl,              NIN);
    split_k<<<NIN / 256, 256>>>(k, gIh + MTOT*DM,    gIl + MTOT*DM,    NIN);
    split_k<<<NIN / 256, 256>>>(v, gIh + 2*MTOT*DM,  gIl + 2*MTOT*DM,  NIN);
    split_k<<<NW / 256, 256>>>(wq, gWh,              gWl,              NW);
    split_k<<<NW / 256, 256>>>(wk, gWh + DM*DM,      gWl + DM*DM,      NW);
    split_k<<<NW / 256, 256>>>(wv, gWh + 2*DM*DM,    gWl + 2*DM*DM,    NW);
    split_k<<<NW / 256, 256>>>(wo, gWh + 3*DM*DM,    gWl + 3*DM*DM,    NW);

    dim3 gproj(MTOT / 128, DM / 128);  // (32, 8)

    gemm_bf<1><<<gproj, 256, GEMM_SMEM>>>(gIh, gIl, gWh, gWl, bq,
                                          nullptr, gQh, gQl, QSCALE);
    gemm_bf<1><<<gproj, 256, GEMM_SMEM>>>(gIh + MTOT*DM, gIl + MTOT*DM,
                                          gWh + DM*DM, gWl + DM*DM, bk,
                                          nullptr, gKh, gKl, 1.0f);
    gemm_bf<2><<<gproj, 256, GEMM_SMEM>>>(gIh + 2*MTOT*DM, gIl + 2*MTOT*DM,
                                          gWh + 2*DM*DM, gWl + 2*DM*DM, bv,
                                          nullptr, gVh, gVl, 1.0f);

    attn_mma<<<dim3(SEQ / 128, NH, BATCH), 256, ATT_SMEM>>>(gQh, gQl, gKh, gKl,
                                                            gVh, gVl, gOh, gOl);

    gemm_bf<0><<<gproj, 256, GEMM_SMEM>>>(gOh, gOl, gWh + 3*DM*DM,
                                          gWl + 3*DM*DM, bo,
                                          out, nullptr, nullptr, 1.0f);
}

// round 9
// speedup vs baseline: 1.0656x; 1.0656x over previous
#include <cuda_runtime.h>
#include <cuda_bf16.h>
#include <cstdint>
#include <math.h>

#define BATCH 2
#define SEQ   2048
#define DM    1024
#define NH    16
#define DEPTH 64
#define MTOT  (BATCH*SEQ)   // 4096

#define QSCALE 0.1803368801111204f   // 0.125 * log2(e): scores in log2 domain

// Scratch
__device__ __nv_bfloat16 g_Whi[4*DM*DM];             // wq,wk,wv,wo pre-split
__device__ __nv_bfloat16 g_Wlo[4*DM*DM];
__device__ __nv_bfloat16 g_Qhi[BATCH*NH*SEQ*DEPTH];  // [B,H,S,D], pre-scaled
__device__ __nv_bfloat16 g_Qlo[BATCH*NH*SEQ*DEPTH];
__device__ __nv_bfloat16 g_Khi[BATCH*NH*SEQ*DEPTH];  // [B,H,S,D]
__device__ __nv_bfloat16 g_Klo[BATCH*NH*SEQ*DEPTH];
__device__ __nv_bfloat16 g_VThi[BATCH*NH*DEPTH*SEQ]; // [B,H,D,S]
__device__ __nv_bfloat16 g_VTlo[BATCH*NH*DEPTH*SEQ];
__device__ float g_O[BATCH*NH*SEQ*DEPTH];            // attn out fp32 [B,H,S,D]

// ===========================================================================
// helpers
// ===========================================================================
__device__ __forceinline__ uint32_t smem_u32(const void* p) {
    uint32_t a;
    asm("{ .reg .u64 t; cvta.to.shared.u64 t, %1; cvt.u32.u64 %0, t; }"
        : "=r"(a) : "l"(p));
    return a;
}
__device__ __forceinline__ uint32_t pack_bf16(float x, float y) {
    uint32_t lo = __bfloat16_as_ushort(__float2bfloat16(x));
    uint32_t hi = __bfloat16_as_ushort(__float2bfloat16(y));
    return lo | (hi << 16);
}
__device__ __forceinline__ float rb(float x) {
    return __bfloat162float(__float2bfloat16(x));
}
__device__ __forceinline__ float ex2(float x) {
    float y; asm("ex2.approx.ftz.f32 %0, %1;" : "=f"(y) : "f"(x)); return y;
}

#define LDSM4(R, addr) \
    asm volatile("ldmatrix.sync.aligned.m8n8.x4.shared.b16 {%0,%1,%2,%3}, [%4];" \
        : "=r"((R)[0]), "=r"((R)[1]), "=r"((R)[2]), "=r"((R)[3]) : "r"(addr))

#define MMA16816(D, A, B0, B1) \
    asm volatile("mma.sync.aligned.m16n8k16.row.col.f32.bf16.bf16.f32 " \
        "{%0,%1,%2,%3}, {%4,%5,%6,%7}, {%8,%9}, {%0,%1,%2,%3};" \
        : "+f"((D)[0]), "+f"((D)[1]), "+f"((D)[2]), "+f"((D)[3]) \
        : "r"((A)[0]), "r"((A)[1]), "r"((A)[2]), "r"((A)[3]), "r"(B0), "r"(B1))

#define CP16(dst, src) \
    asm volatile("cp.async.cg.shared.global [%0], [%1], 16;" \
        :: "r"(dst), "l"(src) : "memory")
#define CP_COMMIT()  asm volatile("cp.async.commit_group;" ::: "memory")
#define CP_WAIT0()   asm volatile("cp.async.wait_group 0;" ::: "memory")

// ===========================================================================
// Weight pre-split: fp32 -> bf16 hi/lo
// ===========================================================================
__global__ __launch_bounds__(256)
void split_k(const float* __restrict__ src, __nv_bfloat16* __restrict__ hi,
             __nv_bfloat16* __restrict__ lo, int n4)
{
    int i = blockIdx.x * 256 + threadIdx.x;
    if (i < n4) {
        float4 v = ((const float4*)src)[i];
        ((uint2*)hi)[i] = make_uint2(pack_bf16(v.x, v.y), pack_bf16(v.z, v.w));
        ((uint2*)lo)[i] = make_uint2(
            pack_bf16(v.x - rb(v.x), v.y - rb(v.y)),
            pack_bf16(v.z - rb(v.z), v.w - rb(v.w)));
    }
}

// ===========================================================================
// Split-bf16 GEMM: C = A @ W.T (+bias, *scale).
// A: fp32 (staged via cp.async, converted inline — round-7 proven path).
// W: PRE-SPLIT bf16 hi/lo, cp.async direct to ldmatrix layout (double-buf).
// CTA 128x128, BK=32, 8 warps (2m x 4n), 2 CTAs/SM.
// OMODE: 0 fp32 [M,N]; 1 bf16 hi/lo [B,H,S,D]; 2 bf16 hi/lo [B,H,D,S].
// ===========================================================================
#define ROWB 80
#define OFF_AHI 0                       // A bf16 hi (single buffer, STS)
#define OFF_ALO 10240                   // A bf16 lo
#define OFF_W   20480                   // W double buffer: +20480*(it&1); lo +10240
#define GSTG_A  61440                   // A fp32 staging: 2 x 16384
#define GEMM_SMEM 94208                 // 2 CTAs/SM (188 KB < 227 KB)

template<bool GATHER_A, int OMODE>
__global__ __launch_bounds__(256, 2)
void gemm_mma(const float* __restrict__ A,
              const __nv_bfloat16* __restrict__ Whi,
              const __nv_bfloat16* __restrict__ Wlo,
              const float* __restrict__ bias, float* __restrict__ C32,
              __nv_bfloat16* __restrict__ Chi, __nv_bfloat16* __restrict__ Clo,
              float scale)
{
    extern __shared__ char smem[];
    const uint32_t sb = smem_u32(smem);

    const int tid = threadIdx.x;
    const int wid = tid >> 5, lid = tid & 31;
    const int warp_m = wid >> 2;
    const int warp_n = wid & 3;
    const int bm = blockIdx.x * 128, bn = blockIdx.y * 128;

    const int grp = lid >> 3, r = lid & 7;
    const uint32_t apat = (uint32_t)(warp_m * 64 + ((grp & 1) << 3) + r) * ROWB
                        + (uint32_t)(((grp >> 1) & 1) << 4);
    const uint32_t wpat = (uint32_t)(warp_n * 32 + (((grp >> 1) & 1) << 3) + r) * ROWB
                        + (uint32_t)((grp & 1) << 4);

    // A staging coords (round-7): 8 threads per 128B fp32 row
    // W coords: 4 threads per 64B bf16 row
    const int wrow = tid >> 2, wch = tid & 3;

    auto issue_tile = [&](int it) {
        const int k0 = it * 32;
        // A fp32 -> staging[(it&1)]
        const uint32_t abuf = sb + GSTG_A + (uint32_t)(it & 1) * 16384u;
#pragma unroll
        for (int l = 0; l < 4; l++) {
            int idx = tid + l * 256;
            int row = idx >> 3;
            int cf  = (idx & 7) << 2;
            const float* srcA;
            if (GATHER_A) {
                int m = bm + row;
                int b = m >> 11, s = m & 2047;
                int h = it >> 1, dl = ((it & 1) << 5) + cf;
                srcA = A + ((((b << 4) + h) * SEQ + s) << 6) + dl;
            } else {
                srcA = A + (size_t)(bm + row) * DM + k0 + cf;
            }
            CP16(abuf + (uint32_t)row * 128 + (uint32_t)cf * 4, srcA);
        }
        // W hi/lo (pre-split) -> ldmatrix layout W[(it&1)]
        const uint32_t wbuf = sb + OFF_W + (uint32_t)(it & 1) * 20480u;
#pragma unroll
        for (int l = 0; l < 4; l++) {
            int mat = l >> 1;                 // 0 hi, 1 lo
            int row = ((l & 1) << 6) + wrow;  // 0..127
            uint32_t dst = wbuf + (uint32_t)mat * 10240u
                         + (uint32_t)row * ROWB + (uint32_t)wch * 16;
            const __nv_bfloat16* src = (mat == 0 ? Whi : Wlo)
                                     + (size_t)(bn + row) * DM + k0 + wch * 8;
            CP16(dst, src);
        }
    };

    float acc[4][4][4];
#pragma unroll
    for (int i = 0; i < 4; i++)
#pragma unroll
        for (int j = 0; j < 4; j++)
#pragma unroll
            for (int e = 0; e < 4; e++) acc[i][j][e] = 0.f;

    issue_tile(0);
    CP_COMMIT();

    for (int it = 0; it < DM / 32; it++) {
        CP_WAIT0();
        __syncthreads();   // staging A[it] + W[it] landed; prev-iter reads done
        if (it + 1 < DM / 32) { issue_tile(it + 1); CP_COMMIT(); }

        // ---- convert A fp32 staging -> bf16 hi/lo (A only) ----
        const float* stA = (const float*)(smem + GSTG_A + (it & 1) * 16384);
#pragma unroll
        for (int l = 0; l < 4; l++) {
            int idx = tid + l * 256;
            int row = idx >> 3;
            int cf  = (idx & 7) << 2;
            uint32_t soff = (uint32_t)row * ROWB + (uint32_t)cf * 2;
            float4 va = *(const float4*)(stA + row * 32 + cf);
            *(uint2*)(smem + OFF_AHI + soff) =
                make_uint2(pack_bf16(va.x, va.y), pack_bf16(va.z, va.w));
            *(uint2*)(smem + OFF_ALO + soff) =
                make_uint2(pack_bf16(va.x - rb(va.x), va.y - rb(va.y)),
                           pack_bf16(va.z - rb(va.z), va.w - rb(va.w)));
        }
        __syncthreads();

        const uint32_t wbuf = sb + OFF_W + (uint32_t)(it & 1) * 20480u;
#pragma unroll
        for (int ks = 0; ks < 2; ks++) {
            const uint32_t offk = (uint32_t)ks * 32;
            uint32_t ah[4][4], al[4][4], bh[2][4], bl[2][4];
#pragma unroll
            for (int fm = 0; fm < 4; fm++) {
                LDSM4(ah[fm], sb + OFF_AHI + apat + fm * (16 * ROWB) + offk);
                LDSM4(al[fm], sb + OFF_ALO + apat + fm * (16 * ROWB) + offk);
            }
#pragma unroll
            for (int p = 0; p < 2; p++) {
                LDSM4(bh[p], wbuf + wpat + p * (16 * ROWB) + offk);
                LDSM4(bl[p], wbuf + 10240 + wpat + p * (16 * ROWB) + offk);
            }
#pragma unroll
            for (int fm = 0; fm < 4; fm++)
#pragma unroll
                for (int fn = 0; fn < 4; fn++) {
                    const int p = fn >> 1, o = (fn & 1) << 1;
                    MMA16816(acc[fm][fn], ah[fm], bh[p][o], bh[p][o + 1]);
                    MMA16816(acc[fm][fn], ah[fm], bl[p][o], bl[p][o + 1]);
                    MMA16816(acc[fm][fn], al[fm], bh[p][o], bh[p][o + 1]);
                }
        }
    }

    const int qrow = lid >> 2;
    const int qcol = (lid & 3) << 1;
#pragma unroll
    for (int fm = 0; fm < 4; fm++) {
        int m1 = bm + warp_m * 64 + fm * 16 + qrow;
        int m2 = m1 + 8;
#pragma unroll
        for (int fn = 0; fn < 4; fn++) {
            int n = bn + warp_n * 32 + fn * 8 + qcol;
            float2 bb = *(const float2*)(bias + n);
            float x1 = (acc[fm][fn][0] + bb.x) * scale;
            float y1 = (acc[fm][fn][1] + bb.y) * scale;
            float x2 = (acc[fm][fn][2] + bb.x) * scale;
            float y2 = (acc[fm][fn][3] + bb.y) * scale;
            if (OMODE == 0) {
                *(float2*)(C32 + (size_t)m1 * DM + n) = make_float2(x1, y1);
                *(float2*)(C32 + (size_t)m2 * DM + n) = make_float2(x2, y2);
            } else {
                int h = n >> 6, dl = n & 63;
                int b1 = m1 >> 11, s1 = m1 & 2047;
                int b2 = m2 >> 11, s2 = m2 & 2047;
                if (OMODE == 1) {
                    size_t i1 = (size_t)((((b1 << 4) + h) * SEQ + s1) << 6) + dl;
                    size_t i2 = (size_t)((((b2 << 4) + h) * SEQ + s2) << 6) + dl;
                    *(uint32_t*)(Chi + i1) = pack_bf16(x1, y1);
                    *(uint32_t*)(Clo + i1) = pack_bf16(x1 - rb(x1), y1 - rb(y1));
                    *(uint32_t*)(Chi + i2) = pack_bf16(x2, y2);
                    *(uint32_t*)(Clo + i2) = pack_bf16(x2 - rb(x2), y2 - rb(y2));
                } else {
                    size_t t1 = ((size_t)((b1 << 4) + h) * 64 + dl) * SEQ + s1;
                    size_t t2 = ((size_t)((b2 << 4) + h) * 64 + dl) * SEQ + s2;
                    Chi[t1] = __float2bfloat16(x1);
                    Clo[t1] = __float2bfloat16(x1 - rb(x1));
                    Chi[t1 + SEQ] = __float2bfloat16(y1);
                    Clo[t1 + SEQ] = __float2bfloat16(y1 - rb(y1));
                    Chi[t2] = __float2bfloat16(x2);
                    Clo[t2] = __float2bfloat16(x2 - rb(x2));
                    Chi[t2 + SEQ] = __float2bfloat16(y2);
                    Clo[t2 + SEQ] = __float2bfloat16(y2 - rb(y2));
                }
            }
        }
    }
}

// ===========================================================================
// Tensor-core flash attention — round-7 kernel verbatim (validated 284us).
// ===========================================================================
#define AROWB 144
#define AQHI  0
#define AQLO  18432
#define ABUF  36864
#define ATT_SMEM (ABUF + 2 * 36864)   // 110592 -> 2 CTAs/SM

__global__ __launch_bounds__(256, 2)
void attn_mma(const __nv_bfloat16* __restrict__ Qhi,
              const __nv_bfloat16* __restrict__ Qlo,
              const __nv_bfloat16* __restrict__ Khi,
              const __nv_bfloat16* __restrict__ Klo,
              const __nv_bfloat16* __restrict__ VThi,
              const __nv_bfloat16* __restrict__ VTlo,
              float* __restrict__ O)
{
    extern __shared__ char smem[];
    const uint32_t sb = smem_u32(smem);
    const int tid = threadIdx.x, wid = tid >> 5, lid = tid & 31;
    const int grp = lid >> 3, r = lid & 7;

    const int bh = blockIdx.z * NH + blockIdx.y;
    const int q0 = blockIdx.x * 128;
    const __nv_bfloat16* Qhp = Qhi + (size_t)(bh * SEQ + q0) * DEPTH;
    const __nv_bfloat16* Qlp = Qlo + (size_t)(bh * SEQ + q0) * DEPTH;
    const __nv_bfloat16* Khp = Khi + (size_t)bh * SEQ * DEPTH;
    const __nv_bfloat16* Klp = Klo + (size_t)bh * SEQ * DEPTH;
    const __nv_bfloat16* Vhp = VThi + (size_t)bh * DEPTH * SEQ;
    const __nv_bfloat16* Vlp = VTlo + (size_t)bh * DEPTH * SEQ;
    float* Op = O + (size_t)(bh * SEQ + q0) * DEPTH;

    const int crow = tid >> 3;
    const int cch  = tid & 7;

    auto issue_tile = [&](int kt) {
        const uint32_t buf = sb + ABUF + (uint32_t)(kt & 1) * 36864u;
        const int s0 = kt * 64;
#pragma unroll
        for (int l = 0; l < 8; l++) {
            int mat = l >> 1;
            int row = ((l & 1) << 5) + crow;
            uint32_t dst = buf + (uint32_t)mat * 9216u
                         + (uint32_t)row * AROWB + (uint32_t)cch * 16;
            const __nv_bfloat16* src;
            if (mat == 0)      src = Khp + (size_t)(s0 + row) * DEPTH + cch * 8;
            else if (mat == 1) src = Klp + (size_t)(s0 + row) * DEPTH + cch * 8;
            else if (mat == 2) src = Vhp + (size_t)row * SEQ + s0 + cch * 8;
            else               src = Vlp + (size_t)row * SEQ + s0 + cch * 8;
            CP16(dst, src);
        }
    };

#pragma unroll
    for (int l = 0; l < 8; l++) {
        int mat = l >> 2;
        int row = ((l & 3) << 5) + crow;
        uint32_t dst = sb + (uint32_t)mat * 18432u
                     + (uint32_t)row * AROWB + (uint32_t)cch * 16;
        const __nv_bfloat16* src = (mat == 0 ? Qhp : Qlp)
                                 + (size_t)row * DEPTH + cch * 8;
        CP16(dst, src);
    }
    issue_tile(0);
    CP_COMMIT();

    const uint32_t qbase = sb + (uint32_t)(wid * 16 + ((grp & 1) << 3) + r) * AROWB
                         + (uint32_t)(((grp >> 1) & 1) << 4);
    const uint32_t bpat  = (uint32_t)(((grp & 2) << 2) + r) * AROWB
                         + (uint32_t)((grp & 1) << 4);

    float o[8][4];
#pragma unroll
    for (int fn = 0; fn < 8; fn++)
#pragma unroll
        for (int e = 0; e < 4; e++) o[fn][e] = 0.f;
    float m1 = -1e30f, m2 = -1e30f, l1 = 0.f, l2 = 0.f;

    for (int kt = 0; kt < SEQ / 64; kt++) {
        CP_WAIT0();
        __syncthreads();
        if (kt + 1 < SEQ / 64) { issue_tile(kt + 1); CP_COMMIT(); }

        const uint32_t kvb = sb + ABUF + (uint32_t)(kt & 1) * 36864u + bpat;

        float s[8][4];
#pragma unroll
        for (int fn = 0; fn < 8; fn++)
#pragma unroll
            for (int e = 0; e < 4; e++) s[fn][e] = 0.f;

#pragma unroll
        for (int ks = 0; ks < 4; ks++) {
            uint32_t qh[4], ql[4];
            LDSM4(qh, qbase + AQHI + ks * 32);
            LDSM4(ql, qbase + AQLO + ks * 32);
            uint32_t kh[4][4], kl[4][4];
#pragma unroll
            for (int p = 0; p < 4; p++) {
                LDSM4(kh[p], kvb + p * (16 * AROWB) + ks * 32);
                LDSM4(kl[p], kvb + 9216 + p * (16 * AROWB) + ks * 32);
            }
#pragma unroll
            for (int fn = 0; fn < 8; fn++) {
                const int p = fn >> 1, o2 = (fn & 1) << 1;
                MMA16816(s[fn], qh, kh[p][o2], kh[p][o2 + 1]);
                MMA16816(s[fn], qh, kl[p][o2], kl[p][o2 + 1]);
                MMA16816(s[fn], ql, kh[p][o2], kh[p][o2 + 1]);
            }
        }

        float mx1 = -1e30f, mx2 = -1e30f;
#pragma unroll
        for (int fn = 0; fn < 8; fn++) {
            mx1 = fmaxf(mx1, fmaxf(s[fn][0], s[fn][1]));
            mx2 = fmaxf(mx2, fmaxf(s[fn][2], s[fn][3]));
        }
        mx1 = fmaxf(mx1, __shfl_xor_sync(0xffffffffu, mx1, 1));
        mx1 = fmaxf(mx1, __shfl_xor_sync(0xffffffffu, mx1, 2));
        mx2 = fmaxf(mx2, __shfl_xor_sync(0xffffffffu, mx2, 1));
        mx2 = fmaxf(mx2, __shfl_xor_sync(0xffffffffu, mx2, 2));

        float mn1 = fmaxf(m1, mx1), mn2 = fmaxf(m2, mx2);
        float c1 = ex2(m1 - mn1), c2 = ex2(m2 - mn2);
        m1 = mn1; m2 = mn2;

        float rs1 = 0.f, rs2 = 0.f;
#pragma unroll
        for (int fn = 0; fn < 8; fn++) {
            s[fn][0] = ex2(s[fn][0] - m1);
            s[fn][1] = ex2(s[fn][1] - m1);
            s[fn][2] = ex2(s[fn][2] - m2);
            s[fn][3] = ex2(s[fn][3] - m2);
            rs1 += s[fn][0] + s[fn][1];
            rs2 += s[fn][2] + s[fn][3];
        }
        rs1 += __shfl_xor_sync(0xffffffffu, rs1, 1);
        rs1 += __shfl_xor_sync(0xffffffffu, rs1, 2);
        rs2 += __shfl_xor_sync(0xffffffffu, rs2, 1);
        rs2 += __shfl_xor_sync(0xffffffffu, rs2, 2);
        l1 = l1 * c1 + rs1;
        l2 = l2 * c2 + rs2;
#pragma unroll
        for (int fn = 0; fn < 8; fn++) {
            o[fn][0] *= c1; o[fn][1] *= c1;
            o[fn][2] *= c2; o[fn][3] *= c2;
        }

#pragma unroll
        for (int ks = 0; ks < 4; ks++) {
            uint32_t pah[4], pal[4];
            {
                float p0 = s[2 * ks][0],     p1 = s[2 * ks][1];
                float p2 = s[2 * ks][2],     p3 = s[2 * ks][3];
                float p4 = s[2 * ks + 1][0], p5 = s[2 * ks + 1][1];
                float p6 = s[2 * ks + 1][2], p7 = s[2 * ks + 1][3];
                pah[0] = pack_bf16(p0, p1);  pah[1] = pack_bf16(p2, p3);
                pah[2] = pack_bf16(p4, p5);  pah[3] = pack_bf16(p6, p7);
                pal[0] = pack_bf16(p0 - rb(p0), p1 - rb(p1));
                pal[1] = pack_bf16(p2 - rb(p2), p3 - rb(p3));
                pal[2] = pack_bf16(p4 - rb(p4), p5 - rb(p5));
                pal[3] = pack_bf16(p6 - rb(p6), p7 - rb(p7));
            }
            uint32_t vh[4][4], vl[4][4];
#pragma unroll
            for (int p = 0; p < 4; p++) {
                LDSM4(vh[p], kvb + 18432 + p * (16 * AROWB) + ks * 32);
                LDSM4(vl[p], kvb + 27648 + p * (16 * AROWB) + ks * 32);
            }
#pragma unroll
            for (int fn = 0; fn < 8; fn++) {
                const int p = fn >> 1, o2 = (fn & 1) << 1;
                MMA16816(o[fn], pah, vh[p][o2], vh[p][o2 + 1]);
                MMA16816(o[fn], pah, vl[p][o2], vl[p][o2 + 1]);
                MMA16816(o[fn], pal, vh[p][o2], vh[p][o2 + 1]);
            }
        }
    }

    float inv1 = 1.f / l1, inv2 = 1.f / l2;
    int qr1 = wid * 16 + (lid >> 2);
    int qr2 = qr1 + 8;
#pragma unroll
    for (int fn = 0; fn < 8; fn++) {
        int col = fn * 8 + (lid & 3) * 2;
        *(float2*)(Op + qr1 * DEPTH + col) =
            make_float2(o[fn][0] * inv1, o[fn][1] * inv1);
        *(float2*)(Op + qr2 * DEPTH + col) =
            make_float2(o[fn][2] * inv2, o[fn][3] * inv2);
    }
}

// ---------------------------------------------------------------------------
extern "C" void kernel_launch(void* const* d_in, const int* in_sizes, int n_in,
                              void* d_out, int out_size)
{
    const float* q  = (const float*)d_in[0];
    const float* k  = (const float*)d_in[1];
    const float* v  = (const float*)d_in[2];
    const float* wq = (const float*)d_in[3];
    const float* bq = (const float*)d_in[4];
    const float* wk = (const float*)d_in[5];
    const float* bk = (const float*)d_in[6];
    const float* wv = (const float*)d_in[7];
    const float* bv = (const float*)d_in[8];
    const float* wo = (const float*)d_in[9];
    const float* bo = (const float*)d_in[10];
    float* out = (float*)d_out;

    __nv_bfloat16 *gWh, *gWl;
    __nv_bfloat16 *gQh, *gQl, *gKh, *gKl, *gVh, *gVl;
    float *gO;
    cudaGetSymbolAddress((void**)&gWh, g_Whi);
    cudaGetSymbolAddress((void**)&gWl, g_Wlo);
    cudaGetSymbolAddress((void**)&gQh, g_Qhi);
    cudaGetSymbolAddress((void**)&gQl, g_Qlo);
    cudaGetSymbolAddress((void**)&gKh, g_Khi);
    cudaGetSymbolAddress((void**)&gKl, g_Klo);
    cudaGetSymbolAddress((void**)&gVh, g_VThi);
    cudaGetSymbolAddress((void**)&gVl, g_VTlo);
    cudaGetSymbolAddress((void**)&gO,  g_O);

    cudaFuncSetAttribute(gemm_mma<false, 1>,
                         cudaFuncAttributeMaxDynamicSharedMemorySize, GEMM_SMEM);
    cudaFuncSetAttribute(gemm_mma<false, 2>,
                         cudaFuncAttributeMaxDynamicSharedMemorySize, GEMM_SMEM);
    cudaFuncSetAttribute(gemm_mma<true, 0>,
                         cudaFuncAttributeMaxDynamicSharedMemorySize, GEMM_SMEM);
    cudaFuncSetAttribute(attn_mma,
                         cudaFuncAttributeMaxDynamicSharedMemorySize, ATT_SMEM);

    const int NW = DM * DM / 4;      // 256K float4 per weight
    split_k<<<NW / 256, 256>>>(wq, gWh,           gWl,           NW);
    split_k<<<NW / 256, 256>>>(wk, gWh + DM*DM,   gWl + DM*DM,   NW);
    split_k<<<NW / 256, 256>>>(wv, gWh + 2*DM*DM, gWl + 2*DM*DM, NW);
    split_k<<<NW / 256, 256>>>(wo, gWh + 3*DM*DM, gWl + 3*DM*DM, NW);

    dim3 gproj(MTOT / 128, DM / 128);  // (32, 8)

    gemm_mma<false, 1><<<gproj, 256, GEMM_SMEM>>>(q, gWh, gWl, bq,
                                                  nullptr, gQh, gQl, QSCALE);
    gemm_mma<false, 1><<<gproj, 256, GEMM_SMEM>>>(k, gWh + DM*DM, gWl + DM*DM,
                                                  bk, nullptr, gKh, gKl, 1.0f);
    gemm_mma<false, 2><<<gproj, 256, GEMM_SMEM>>>(v, gWh + 2*DM*DM,
                                                  gWl + 2*DM*DM, bv,
                                                  nullptr, gVh, gVl, 1.0f);

    attn_mma<<<dim3(SEQ / 128, NH, BATCH), 256, ATT_SMEM>>>(gQh, gQl, gKh, gKl,
                                                            gVh, gVl, gO);

    gemm_mma<true, 0><<<gproj, 256, GEMM_SMEM>>>(gO, gWh + 3*DM*DM,
                                                 gWl + 3*DM*DM, bo,
                                                 out, nullptr, nullptr, 1.0f);
}

// round 10
// speedup vs baseline: 1.0831x; 1.0164x over previous
#include <cuda_runtime.h>
#include <cuda_bf16.h>
#include <cstdint>
#include <math.h>

#define BATCH 2
#define SEQ   2048
#define DM    1024
#define NH    16
#define DEPTH 64
#define MTOT  (BATCH*SEQ)   // 4096

#define QSCALE 0.1803368801111204f   // 0.125 * log2(e): scores in log2 domain

// Scratch
__device__ __nv_bfloat16 g_Qhi[BATCH*NH*SEQ*DEPTH];  // [B,H,S,D], pre-scaled
__device__ __nv_bfloat16 g_Qlo[BATCH*NH*SEQ*DEPTH];
__device__ __nv_bfloat16 g_Khi[BATCH*NH*SEQ*DEPTH];  // [B,H,S,D]
__device__ __nv_bfloat16 g_Klo[BATCH*NH*SEQ*DEPTH];
__device__ __nv_bfloat16 g_VThi[BATCH*NH*DEPTH*SEQ]; // [B,H,D,S]
__device__ __nv_bfloat16 g_VTlo[BATCH*NH*DEPTH*SEQ];
__device__ float g_O[BATCH*NH*SEQ*DEPTH];            // attn out fp32 [B,H,S,D]

// ===========================================================================
// helpers
// ===========================================================================
__device__ __forceinline__ uint32_t smem_u32(const void* p) {
    uint32_t a;
    asm("{ .reg .u64 t; cvta.to.shared.u64 t, %1; cvt.u32.u64 %0, t; }"
        : "=r"(a) : "l"(p));
    return a;
}
__device__ __forceinline__ uint32_t pack_bf16(float x, float y) {
    uint32_t lo = __bfloat16_as_ushort(__float2bfloat16(x));
    uint32_t hi = __bfloat16_as_ushort(__float2bfloat16(y));
    return lo | (hi << 16);
}
__device__ __forceinline__ float rb(float x) {
    return __bfloat162float(__float2bfloat16(x));
}
__device__ __forceinline__ float ex2(float x) {
    float y; asm("ex2.approx.ftz.f32 %0, %1;" : "=f"(y) : "f"(x)); return y;
}

#define LDSM4(R, addr) \
    asm volatile("ldmatrix.sync.aligned.m8n8.x4.shared.b16 {%0,%1,%2,%3}, [%4];" \
        : "=r"((R)[0]), "=r"((R)[1]), "=r"((R)[2]), "=r"((R)[3]) : "r"(addr))

#define MMA16816(D, A, B0, B1) \
    asm volatile("mma.sync.aligned.m16n8k16.row.col.f32.bf16.bf16.f32 " \
        "{%0,%1,%2,%3}, {%4,%5,%6,%7}, {%8,%9}, {%0,%1,%2,%3};" \
        : "+f"((D)[0]), "+f"((D)[1]), "+f"((D)[2]), "+f"((D)[3]) \
        : "r"((A)[0]), "r"((A)[1]), "r"((A)[2]), "r"((A)[3]), "r"(B0), "r"(B1))

#define CP16(dst, src) \
    asm volatile("cp.async.cg.shared.global [%0], [%1], 16;" \
        :: "r"(dst), "l"(src) : "memory")
#define CP_COMMIT()  asm volatile("cp.async.commit_group;" ::: "memory")
#define CP_WAIT0()   asm volatile("cp.async.wait_group 0;" ::: "memory")

// ===========================================================================
// Split-bf16 GEMM core (round-7 validated): fp32 A/W staged via cp.async,
// converted inline to bf16 hi/lo, double-buffered, 1 barrier + 1 conv-barrier
// per iter. CTA 128x128, BK=32, 8 warps (2m x 4n), 2 CTAs/SM.
// ===========================================================================
#define ROWB 80
#define MAT_BYTES (128 * ROWB)
#define OFF_AHI 0
#define OFF_ALO (MAT_BYTES)
#define OFF_BHI (2 * MAT_BYTES)
#define OFF_BLO (3 * MAT_BYTES)
#define GSTG_A  (4 * MAT_BYTES)
#define GSTG_W  (GSTG_A + 2 * 16384)
#define GEMM_SMEM (GSTG_W + 2 * 16384)  // 106496

// Fused QKV projection: blockIdx.z selects (input, weight, bias, output mode).
// z=0: Q -> g_Q hi/lo [B,H,S,D] scaled by QSCALE
// z=1: K -> g_K hi/lo [B,H,S,D]
// z=2: V -> g_VT hi/lo [B,H,D,S] (transposed)
__global__ __launch_bounds__(256, 2)
void gemm_qkv(const float* __restrict__ q, const float* __restrict__ k,
              const float* __restrict__ v,
              const float* __restrict__ wq, const float* __restrict__ wk,
              const float* __restrict__ wv,
              const float* __restrict__ bq, const float* __restrict__ bk,
              const float* __restrict__ bv,
              __nv_bfloat16* __restrict__ Qhi, __nv_bfloat16* __restrict__ Qlo,
              __nv_bfloat16* __restrict__ Khi, __nv_bfloat16* __restrict__ Klo,
              __nv_bfloat16* __restrict__ Vhi, __nv_bfloat16* __restrict__ Vlo)
{
    extern __shared__ char smem[];
    const uint32_t sb = smem_u32(smem);

    const int z = blockIdx.z;
    const float* A    = (z == 0) ? q  : (z == 1) ? k  : v;
    const float* W    = (z == 0) ? wq : (z == 1) ? wk : wv;
    const float* bias = (z == 0) ? bq : (z == 1) ? bk : bv;
    __nv_bfloat16* Chi = (z == 0) ? Qhi : (z == 1) ? Khi : Vhi;
    __nv_bfloat16* Clo = (z == 0) ? Qlo : (z == 1) ? Klo : Vlo;
    const float scale = (z == 0) ? QSCALE : 1.0f;

    const int tid = threadIdx.x;
    const int wid = tid >> 5, lid = tid & 31;
    const int warp_m = wid >> 2;
    const int warp_n = wid & 3;
    const int bm = blockIdx.x * 128, bn = blockIdx.y * 128;

    const int grp = lid >> 3, r = lid & 7;
    const uint32_t a_base = sb + OFF_AHI
        + (uint32_t)(warp_m * 64 + ((grp & 1) << 3) + r) * ROWB
        + (uint32_t)(((grp >> 1) & 1) << 4);
    const uint32_t b_base = sb + OFF_BHI
        + (uint32_t)(warp_n * 32 + (((grp >> 1) & 1) << 3) + r) * ROWB
        + (uint32_t)((grp & 1) << 4);

    auto issue_tile = [&](int it) {
        const int k0 = it * 32;
        const uint32_t buf = (uint32_t)(it & 1) * 16384u;
#pragma unroll
        for (int l = 0; l < 4; l++) {
            int idx = tid + l * 256;
            int row = idx >> 3;
            int cf  = (idx & 7) << 2;
            uint32_t doff = (uint32_t)row * 128 + (uint32_t)cf * 4;
            CP16(sb + GSTG_A + buf + doff,
                 A + (size_t)(bm + row) * DM + k0 + cf);
            CP16(sb + GSTG_W + buf + doff,
                 W + (size_t)(bn + row) * DM + k0 + cf);
        }
    };

    float acc[4][4][4];
#pragma unroll
    for (int i = 0; i < 4; i++)
#pragma unroll
        for (int j = 0; j < 4; j++)
#pragma unroll
            for (int e = 0; e < 4; e++) acc[i][j][e] = 0.f;

    issue_tile(0);
    CP_COMMIT();

    for (int it = 0; it < DM / 32; it++) {
        CP_WAIT0();
        __syncthreads();
        if (it + 1 < DM / 32) { issue_tile(it + 1); CP_COMMIT(); }

        const float* stA = (const float*)(smem + GSTG_A + (it & 1) * 16384);
        const float* stW = (const float*)(smem + GSTG_W + (it & 1) * 16384);
#pragma unroll
        for (int l = 0; l < 4; l++) {
            int idx = tid + l * 256;
            int row = idx >> 3;
            int cf  = (idx & 7) << 2;
            uint32_t soff = (uint32_t)row * ROWB + (uint32_t)cf * 2;
            float4 va = *(const float4*)(stA + row * 32 + cf);
            *(uint2*)(smem + OFF_AHI + soff) =
                make_uint2(pack_bf16(va.x, va.y), pack_bf16(va.z, va.w));
            *(uint2*)(smem + OFF_ALO + soff) =
                make_uint2(pack_bf16(va.x - rb(va.x), va.y - rb(va.y)),
                           pack_bf16(va.z - rb(va.z), va.w - rb(va.w)));
            float4 vw = *(const float4*)(stW + row * 32 + cf);
            *(uint2*)(smem + OFF_BHI + soff) =
                make_uint2(pack_bf16(vw.x, vw.y), pack_bf16(vw.z, vw.w));
            *(uint2*)(smem + OFF_BLO + soff) =
                make_uint2(pack_bf16(vw.x - rb(vw.x), vw.y - rb(vw.y)),
                           pack_bf16(vw.z - rb(vw.z), vw.w - rb(vw.w)));
        }
        __syncthreads();

#pragma unroll
        for (int ks = 0; ks < 2; ks++) {
            const uint32_t offk = (uint32_t)ks * 32;
            uint32_t ah[4][4], al[4][4], bh[2][4], bl[2][4];
#pragma unroll
            for (int fm = 0; fm < 4; fm++) {
                LDSM4(ah[fm], a_base + fm * (16 * ROWB) + offk);
                LDSM4(al[fm], a_base + (OFF_ALO - OFF_AHI) + fm * (16 * ROWB) + offk);
            }
#pragma unroll
            for (int p = 0; p < 2; p++) {
                LDSM4(bh[p], b_base + p * (16 * ROWB) + offk);
                LDSM4(bl[p], b_base + (OFF_BLO - OFF_BHI) + p * (16 * ROWB) + offk);
            }
#pragma unroll
            for (int fm = 0; fm < 4; fm++)
#pragma unroll
                for (int fn = 0; fn < 4; fn++) {
                    const int p = fn >> 1, o = (fn & 1) << 1;
                    MMA16816(acc[fm][fn], ah[fm], bh[p][o], bh[p][o + 1]);
                    MMA16816(acc[fm][fn], ah[fm], bl[p][o], bl[p][o + 1]);
                    MMA16816(acc[fm][fn], al[fm], bh[p][o], bh[p][o + 1]);
                }
        }
    }

    const int qrow = lid >> 2;
    const int qcol = (lid & 3) << 1;
#pragma unroll
    for (int fm = 0; fm < 4; fm++) {
        int m1 = bm + warp_m * 64 + fm * 16 + qrow;
        int m2 = m1 + 8;
#pragma unroll
        for (int fn = 0; fn < 4; fn++) {
            int n = bn + warp_n * 32 + fn * 8 + qcol;
            float2 bb = *(const float2*)(bias + n);
            float x1 = (acc[fm][fn][0] + bb.x) * scale;
            float y1 = (acc[fm][fn][1] + bb.y) * scale;
            float x2 = (acc[fm][fn][2] + bb.x) * scale;
            float y2 = (acc[fm][fn][3] + bb.y) * scale;
            int h = n >> 6, dl = n & 63;
            int b1 = m1 >> 11, s1 = m1 & 2047;
            int b2 = m2 >> 11, s2 = m2 & 2047;
            if (z != 2) {
                size_t i1 = (size_t)((((b1 << 4) + h) * SEQ + s1) << 6) + dl;
                size_t i2 = (size_t)((((b2 << 4) + h) * SEQ + s2) << 6) + dl;
                *(uint32_t*)(Chi + i1) = pack_bf16(x1, y1);
                *(uint32_t*)(Clo + i1) = pack_bf16(x1 - rb(x1), y1 - rb(y1));
                *(uint32_t*)(Chi + i2) = pack_bf16(x2, y2);
                *(uint32_t*)(Clo + i2) = pack_bf16(x2 - rb(x2), y2 - rb(y2));
            } else {
                size_t t1 = ((size_t)((b1 << 4) + h) * 64 + dl) * SEQ + s1;
                size_t t2 = ((size_t)((b2 << 4) + h) * 64 + dl) * SEQ + s2;
                Chi[t1] = __float2bfloat16(x1);
                Clo[t1] = __float2bfloat16(x1 - rb(x1));
                Chi[t1 + SEQ] = __float2bfloat16(y1);
                Clo[t1 + SEQ] = __float2bfloat16(y1 - rb(y1));
                Chi[t2] = __float2bfloat16(x2);
                Clo[t2] = __float2bfloat16(x2 - rb(x2));
                Chi[t2 + SEQ] = __float2bfloat16(y2);
                Clo[t2 + SEQ] = __float2bfloat16(y2 - rb(y2));
            }
        }
    }
}

// Output projection (round-7 gemm, GATHER_A from [B,H,S,D], fp32 out)
__global__ __launch_bounds__(256, 2)
void gemm_out(const float* __restrict__ A, const float* __restrict__ W,
              const float* __restrict__ bias, float* __restrict__ C32)
{
    extern __shared__ char smem[];
    const uint32_t sb = smem_u32(smem);

    const int tid = threadIdx.x;
    const int wid = tid >> 5, lid = tid & 31;
    const int warp_m = wid >> 2;
    const int warp_n = wid & 3;
    const int bm = blockIdx.x * 128, bn = blockIdx.y * 128;

    const int grp = lid >> 3, r = lid & 7;
    const uint32_t a_base = sb + OFF_AHI
        + (uint32_t)(warp_m * 64 + ((grp & 1) << 3) + r) * ROWB
        + (uint32_t)(((grp >> 1) & 1) << 4);
    const uint32_t b_base = sb + OFF_BHI
        + (uint32_t)(warp_n * 32 + (((grp >> 1) & 1) << 3) + r) * ROWB
        + (uint32_t)((grp & 1) << 4);

    auto issue_tile = [&](int it) {
        const int k0 = it * 32;
        const uint32_t buf = (uint32_t)(it & 1) * 16384u;
#pragma unroll
        for (int l = 0; l < 4; l++) {
            int idx = tid + l * 256;
            int row = idx >> 3;
            int cf  = (idx & 7) << 2;
            uint32_t doff = (uint32_t)row * 128 + (uint32_t)cf * 4;
            int m = bm + row;
            int b = m >> 11, s = m & 2047;
            int h = it >> 1, dl = ((it & 1) << 5) + cf;
            CP16(sb + GSTG_A + buf + doff,
                 A + ((((b << 4) + h) * SEQ + s) << 6) + dl);
            CP16(sb + GSTG_W + buf + doff,
                 W + (size_t)(bn + row) * DM + k0 + cf);
        }
    };

    float acc[4][4][4];
#pragma unroll
    for (int i = 0; i < 4; i++)
#pragma unroll
        for (int j = 0; j < 4; j++)
#pragma unroll
            for (int e = 0; e < 4; e++) acc[i][j][e] = 0.f;

    issue_tile(0);
    CP_COMMIT();

    for (int it = 0; it < DM / 32; it++) {
        CP_WAIT0();
        __syncthreads();
        if (it + 1 < DM / 32) { issue_tile(it + 1); CP_COMMIT(); }

        const float* stA = (const float*)(smem + GSTG_A + (it & 1) * 16384);
        const float* stW = (const float*)(smem + GSTG_W + (it & 1) * 16384);
#pragma unroll
        for (int l = 0; l < 4; l++) {
            int idx = tid + l * 256;
            int row = idx >> 3;
            int cf  = (idx & 7) << 2;
            uint32_t soff = (uint32_t)row * ROWB + (uint32_t)cf * 2;
            float4 va = *(const float4*)(stA + row * 32 + cf);
            *(uint2*)(smem + OFF_AHI + soff) =
                make_uint2(pack_bf16(va.x, va.y), pack_bf16(va.z, va.w));
            *(uint2*)(smem + OFF_ALO + soff) =
                make_uint2(pack_bf16(va.x - rb(va.x), va.y - rb(va.y)),
                           pack_bf16(va.z - rb(va.z), va.w - rb(va.w)));
            float4 vw = *(const float4*)(stW + row * 32 + cf);
            *(uint2*)(smem + OFF_BHI + soff) =
                make_uint2(pack_bf16(vw.x, vw.y), pack_bf16(vw.z, vw.w));
            *(uint2*)(smem + OFF_BLO + soff) =
                make_uint2(pack_bf16(vw.x - rb(vw.x), vw.y - rb(vw.y)),
                           pack_bf16(vw.z - rb(vw.z), vw.w - rb(vw.w)));
        }
        __syncthreads();

#pragma unroll
        for (int ks = 0; ks < 2; ks++) {
            const uint32_t offk = (uint32_t)ks * 32;
            uint32_t ah[4][4], al[4][4], bh[2][4], bl[2][4];
#pragma unroll
            for (int fm = 0; fm < 4; fm++) {
                LDSM4(ah[fm], a_base + fm * (16 * ROWB) + offk);
                LDSM4(al[fm], a_base + (OFF_ALO - OFF_AHI) + fm * (16 * ROWB) + offk);
            }
#pragma unroll
            for (int p = 0; p < 2; p++) {
                LDSM4(bh[p], b_base + p * (16 * ROWB) + offk);
                LDSM4(bl[p], b_base + (OFF_BLO - OFF_BHI) + p * (16 * ROWB) + offk);
            }
#pragma unroll
            for (int fm = 0; fm < 4; fm++)
#pragma unroll
                for (int fn = 0; fn < 4; fn++) {
                    const int p = fn >> 1, o = (fn & 1) << 1;
                    MMA16816(acc[fm][fn], ah[fm], bh[p][o], bh[p][o + 1]);
                    MMA16816(acc[fm][fn], ah[fm], bl[p][o], bl[p][o + 1]);
                    MMA16816(acc[fm][fn], al[fm], bh[p][o], bh[p][o + 1]);
                }
        }
    }

    const int qrow = lid >> 2;
    const int qcol = (lid & 3) << 1;
#pragma unroll
    for (int fm = 0; fm < 4; fm++) {
        int m1 = bm + warp_m * 64 + fm * 16 + qrow;
        int m2 = m1 + 8;
#pragma unroll
        for (int fn = 0; fn < 4; fn++) {
            int n = bn + warp_n * 32 + fn * 8 + qcol;
            float2 bb = *(const float2*)(bias + n);
            *(float2*)(C32 + (size_t)m1 * DM + n) =
                make_float2(acc[fm][fn][0] + bb.x, acc[fm][fn][1] + bb.y);
            *(float2*)(C32 + (size_t)m2 * DM + n) =
                make_float2(acc[fm][fn][2] + bb.x, acc[fm][fn][3] + bb.y);
        }
    }
}

// ===========================================================================
// Tensor-core flash attention — round-7 kernel verbatim (validated 284us).
// ===========================================================================
#define AROWB 144
#define AQHI  0
#define AQLO  18432
#define ABUF  36864
#define ATT_SMEM (ABUF + 2 * 36864)   // 110592 -> 2 CTAs/SM

__global__ __launch_bounds__(256, 2)
void attn_mma(const __nv_bfloat16* __restrict__ Qhi,
              const __nv_bfloat16* __restrict__ Qlo,
              const __nv_bfloat16* __restrict__ Khi,
              const __nv_bfloat16* __restrict__ Klo,
              const __nv_bfloat16* __restrict__ VThi,
              const __nv_bfloat16* __restrict__ VTlo,
              float* __restrict__ O)
{
    extern __shared__ char smem[];
    const uint32_t sb = smem_u32(smem);
    const int tid = threadIdx.x, wid = tid >> 5, lid = tid & 31;
    const int grp = lid >> 3, r = lid & 7;

    const int bh = blockIdx.z * NH + blockIdx.y;
    const int q0 = blockIdx.x * 128;
    const __nv_bfloat16* Qhp = Qhi + (size_t)(bh * SEQ + q0) * DEPTH;
    const __nv_bfloat16* Qlp = Qlo + (size_t)(bh * SEQ + q0) * DEPTH;
    const __nv_bfloat16* Khp = Khi + (size_t)bh * SEQ * DEPTH;
    const __nv_bfloat16* Klp = Klo + (size_t)bh * SEQ * DEPTH;
    const __nv_bfloat16* Vhp = VThi + (size_t)bh * DEPTH * SEQ;
    const __nv_bfloat16* Vlp = VTlo + (size_t)bh * DEPTH * SEQ;
    float* Op = O + (size_t)(bh * SEQ + q0) * DEPTH;

    const int crow = tid >> 3;
    const int cch  = tid & 7;

    auto issue_tile = [&](int kt) {
        const uint32_t buf = sb + ABUF + (uint32_t)(kt & 1) * 36864u;
        const int s0 = kt * 64;
#pragma unroll
        for (int l = 0; l < 8; l++) {
            int mat = l >> 1;
            int row = ((l & 1) << 5) + crow;
            uint32_t dst = buf + (uint32_t)mat * 9216u
                         + (uint32_t)row * AROWB + (uint32_t)cch * 16;
            const __nv_bfloat16* src;
            if (mat == 0)      src = Khp + (size_t)(s0 + row) * DEPTH + cch * 8;
            else if (mat == 1) src = Klp + (size_t)(s0 + row) * DEPTH + cch * 8;
            else if (mat == 2) src = Vhp + (size_t)row * SEQ + s0 + cch * 8;
            else               src = Vlp + (size_t)row * SEQ + s0 + cch * 8;
            CP16(dst, src);
        }
    };

#pragma unroll
    for (int l = 0; l < 8; l++) {
        int mat = l >> 2;
        int row = ((l & 3) << 5) + crow;
        uint32_t dst = sb + (uint32_t)mat * 18432u
                     + (uint32_t)row * AROWB + (uint32_t)cch * 16;
        const __nv_bfloat16* src = (mat == 0 ? Qhp : Qlp)
                                 + (size_t)row * DEPTH + cch * 8;
        CP16(dst, src);
    }
    issue_tile(0);
    CP_COMMIT();

    const uint32_t qbase = sb + (uint32_t)(wid * 16 + ((grp & 1) << 3) + r) * AROWB
                         + (uint32_t)(((grp >> 1) & 1) << 4);
    const uint32_t bpat  = (uint32_t)(((grp & 2) << 2) + r) * AROWB
                         + (uint32_t)((grp & 1) << 4);

    float o[8][4];
#pragma unroll
    for (int fn = 0; fn < 8; fn++)
#pragma unroll
        for (int e = 0; e < 4; e++) o[fn][e] = 0.f;
    float m1 = -1e30f, m2 = -1e30f, l1 = 0.f, l2 = 0.f;

    for (int kt = 0; kt < SEQ / 64; kt++) {
        CP_WAIT0();
        __syncthreads();
        if (kt + 1 < SEQ / 64) { issue_tile(kt + 1); CP_COMMIT(); }

        const uint32_t kvb = sb + ABUF + (uint32_t)(kt & 1) * 36864u + bpat;

        float s[8][4];
#pragma unroll
        for (int fn = 0; fn < 8; fn++)
#pragma unroll
            for (int e = 0; e < 4; e++) s[fn][e] = 0.f;

#pragma unroll
        for (int ks = 0; ks < 4; ks++) {
            uint32_t qh[4], ql[4];
            LDSM4(qh, qbase + AQHI + ks * 32);
            LDSM4(ql, qbase + AQLO + ks * 32);
            uint32_t kh[4][4], kl[4][4];
#pragma unroll
            for (int p = 0; p < 4; p++) {
                LDSM4(kh[p], kvb + p * (16 * AROWB) + ks * 32);
                LDSM4(kl[p], kvb + 9216 + p * (16 * AROWB) + ks * 32);
            }
#pragma unroll
            for (int fn = 0; fn < 8; fn++) {
                const int p = fn >> 1, o2 = (fn & 1) << 1;
                MMA16816(s[fn], qh, kh[p][o2], kh[p][o2 + 1]);
                MMA16816(s[fn], qh, kl[p][o2], kl[p][o2 + 1]);
                MMA16816(s[fn], ql, kh[p][o2], kh[p][o2 + 1]);
            }
        }

        float mx1 = -1e30f, mx2 = -1e30f;
#pragma unroll
        for (int fn = 0; fn < 8; fn++) {
            mx1 = fmaxf(mx1, fmaxf(s[fn][0], s[fn][1]));
            mx2 = fmaxf(mx2, fmaxf(s[fn][2], s[fn][3]));
        }
        mx1 = fmaxf(mx1, __shfl_xor_sync(0xffffffffu, mx1, 1));
        mx1 = fmaxf(mx1, __shfl_xor_sync(0xffffffffu, mx1, 2));
        mx2 = fmaxf(mx2, __shfl_xor_sync(0xffffffffu, mx2, 1));
        mx2 = fmaxf(mx2, __shfl_xor_sync(0xffffffffu, mx2, 2));

        float mn1 = fmaxf(m1, mx1), mn2 = fmaxf(m2, mx2);
        float c1 = ex2(m1 - mn1), c2 = ex2(m2 - mn2);
        m1 = mn1; m2 = mn2;

        float rs1 = 0.f, rs2 = 0.f;
#pragma unroll
        for (int fn = 0; fn < 8; fn++) {
            s[fn][0] = ex2(s[fn][0] - m1);
            s[fn][1] = ex2(s[fn][1] - m1);
            s[fn][2] = ex2(s[fn][2] - m2);
            s[fn][3] = ex2(s[fn][3] - m2);
            rs1 += s[fn][0] + s[fn][1];
            rs2 += s[fn][2] + s[fn][3];
        }
        rs1 += __shfl_xor_sync(0xffffffffu, rs1, 1);
        rs1 += __shfl_xor_sync(0xffffffffu, rs1, 2);
        rs2 += __shfl_xor_sync(0xffffffffu, rs2, 1);
        rs2 += __shfl_xor_sync(0xffffffffu, rs2, 2);
        l1 = l1 * c1 + rs1;
        l2 = l2 * c2 + rs2;
#pragma unroll
        for (int fn = 0; fn < 8; fn++) {
            o[fn][0] *= c1; o[fn][1] *= c1;
            o[fn][2] *= c2; o[fn][3] *= c2;
        }

#pragma unroll
        for (int ks = 0; ks < 4; ks++) {
            uint32_t pah[4], pal[4];
            {
                float p0 = s[2 * ks][0],     p1 = s[2 * ks][1];
                float p2 = s[2 * ks][2],     p3 = s[2 * ks][3];
                float p4 = s[2 * ks + 1][0], p5 = s[2 * ks + 1][1];
                float p6 = s[2 * ks + 1][2], p7 = s[2 * ks + 1][3];
                pah[0] = pack_bf16(p0, p1);  pah[1] = pack_bf16(p2, p3);
                pah[2] = pack_bf16(p4, p5);  pah[3] = pack_bf16(p6, p7);
                pal[0] = pack_bf16(p0 - rb(p0), p1 - rb(p1));
                pal[1] = pack_bf16(p2 - rb(p2), p3 - rb(p3));
                pal[2] = pack_bf16(p4 - rb(p4), p5 - rb(p5));
                pal[3] = pack_bf16(p6 - rb(p6), p7 - rb(p7));
            }
            uint32_t vh[4][4], vl[4][4];
#pragma unroll
            for (int p = 0; p < 4; p++) {
                LDSM4(vh[p], kvb + 18432 + p * (16 * AROWB) + ks * 32);
                LDSM4(vl[p], kvb + 27648 + p * (16 * AROWB) + ks * 32);
            }
#pragma unroll
            for (int fn = 0; fn < 8; fn++) {
                const int p = fn >> 1, o2 = (fn & 1) << 1;
                MMA16816(o[fn], pah, vh[p][o2], vh[p][o2 + 1]);
                MMA16816(o[fn], pah, vl[p][o2], vl[p][o2 + 1]);
                MMA16816(o[fn], pal, vh[p][o2], vh[p][o2 + 1]);
            }
        }
    }

    float inv1 = 1.f / l1, inv2 = 1.f / l2;
    int qr1 = wid * 16 + (lid >> 2);
    int qr2 = qr1 + 8;
#pragma unroll
    for (int fn = 0; fn < 8; fn++) {
        int col = fn * 8 + (lid & 3) * 2;
        *(float2*)(Op + qr1 * DEPTH + col) =
            make_float2(o[fn][0] * inv1, o[fn][1] * inv1);
        *(float2*)(Op + qr2 * DEPTH + col) =
            make_float2(o[fn][2] * inv2, o[fn][3] * inv2);
    }
}

// ---------------------------------------------------------------------------
extern "C" void kernel_launch(void* const* d_in, const int* in_sizes, int n_in,
                              void* d_out, int out_size)
{
    const float* q  = (const float*)d_in[0];
    const float* k  = (const float*)d_in[1];
    const float* v  = (const float*)d_in[2];
    const float* wq = (const float*)d_in[3];
    const float* bq = (const float*)d_in[4];
    const float* wk = (const float*)d_in[5];
    const float* bk = (const float*)d_in[6];
    const float* wv = (const float*)d_in[7];
    const float* bv = (const float*)d_in[8];
    const float* wo = (const float*)d_in[9];
    const float* bo = (const float*)d_in[10];
    float* out = (float*)d_out;

    __nv_bfloat16 *gQh, *gQl, *gKh, *gKl, *gVh, *gVl;
    float *gO;
    cudaGetSymbolAddress((void**)&gQh, g_Qhi);
    cudaGetSymbolAddress((void**)&gQl, g_Qlo);
    cudaGetSymbolAddress((void**)&gKh, g_Khi);
    cudaGetSymbolAddress((void**)&gKl, g_Klo);
    cudaGetSymbolAddress((void**)&gVh, g_VThi);
    cudaGetSymbolAddress((void**)&gVl, g_VTlo);
    cudaGetSymbolAddress((void**)&gO,  g_O);

    cudaFuncSetAttribute(gemm_qkv,
                         cudaFuncAttributeMaxDynamicSharedMemorySize, GEMM_SMEM);
    cudaFuncSetAttribute(gemm_out,
                         cudaFuncAttributeMaxDynamicSharedMemorySize, GEMM_SMEM);
    cudaFuncSetAttribute(attn_mma,
                         cudaFuncAttributeMaxDynamicSharedMemorySize, ATT_SMEM);

    // Fused QKV projections: one launch, 768 CTAs (2.59 waves vs 3)
    gemm_qkv<<<dim3(MTOT / 128, DM / 128, 3), 256, GEMM_SMEM>>>(
        q, k, v, wq, wk, wv, bq, bk, bv,
        gQh, gQl, gKh, gKl, gVh, gVl);

    attn_mma<<<dim3(SEQ / 128, NH, BATCH), 256, ATT_SMEM>>>(gQh, gQl, gKh, gKl,
                                                            gVh, gVl, gO);

    gemm_out<<<dim3(MTOT / 128, DM / 128), 256, GEMM_SMEM>>>(gO, wo, bo, out);
}

// round 11
// speedup vs baseline: 1.5565x; 1.4371x over previous
#include <cuda_runtime.h>
#include <cuda_fp16.h>
#include <cstdint>
#include <math.h>

#define BATCH 2
#define SEQ   2048
#define DM    1024
#define NH    16
#define DEPTH 64
#define MTOT  (BATCH*SEQ)   // 4096

#define QSCALE 0.1803368801111204f   // 0.125 * log2(e): scores in log2 domain

// Scratch (fp16)
__device__ __half g_Qhi[BATCH*NH*SEQ*DEPTH];  // [B,H,S,D], pre-scaled, hi
__device__ __half g_Qlo[BATCH*NH*SEQ*DEPTH];  // lo
__device__ __half g_K1 [BATCH*NH*SEQ*DEPTH];  // [B,H,S,D], single fp16
__device__ __half g_VT1[BATCH*NH*DEPTH*SEQ];  // [B,H,D,S], single fp16
__device__ float  g_O  [BATCH*NH*SEQ*DEPTH];  // attn out fp32 [B,H,S,D]

// ===========================================================================
// helpers
// ===========================================================================
__device__ __forceinline__ uint32_t smem_u32(const void* p) {
    uint32_t a;
    asm("{ .reg .u64 t; cvta.to.shared.u64 t, %1; cvt.u32.u64 %0, t; }"
        : "=r"(a) : "l"(p));
    return a;
}
__device__ __forceinline__ uint32_t pack_h(float x, float y) {
    __half2 h = __floats2half2_rn(x, y);
    return *(uint32_t*)&h;
}
__device__ __forceinline__ float rh(float x) {   // round to fp16, back to f32
    return __half2float(__float2half_rn(x));
}
__device__ __forceinline__ float ex2(float x) {
    float y; asm("ex2.approx.ftz.f32 %0, %1;" : "=f"(y) : "f"(x)); return y;
}

#define LDSM4(R, addr) \
    asm volatile("ldmatrix.sync.aligned.m8n8.x4.shared.b16 {%0,%1,%2,%3}, [%4];" \
        : "=r"((R)[0]), "=r"((R)[1]), "=r"((R)[2]), "=r"((R)[3]) : "r"(addr))

#define MMA16816(D, A, B0, B1) \
    asm volatile("mma.sync.aligned.m16n8k16.row.col.f32.f16.f16.f32 " \
        "{%0,%1,%2,%3}, {%4,%5,%6,%7}, {%8,%9}, {%0,%1,%2,%3};" \
        : "+f"((D)[0]), "+f"((D)[1]), "+f"((D)[2]), "+f"((D)[3]) \
        : "r"((A)[0]), "r"((A)[1]), "r"((A)[2]), "r"((A)[3]), "r"(B0), "r"(B1))

#define CP16(dst, src) \
    asm volatile("cp.async.cg.shared.global [%0], [%1], 16;" \
        :: "r"(dst), "l"(src) : "memory")
#define CP_COMMIT()  asm volatile("cp.async.commit_group;" ::: "memory")
#define CP_WAIT0()   asm volatile("cp.async.wait_group 0;" ::: "memory")

// ===========================================================================
// 2-term fp16 GEMM: C = A @ W.T (+bias,*scale). A = Ahi+Alo fp16 (split),
// W single fp16. D = Ahi*W + Alo*W (fp32 accum) -> rel err ~1.4e-4.
// fp32 A/W staged via cp.async, converted inline. CTA 128x128, BK=32,
// 8 warps (2m x 4n), double-buffered staging, 2 CTAs/SM.
// OMODE: 0 fp32 [M,N]; 1 fp16 hi/lo [B,H,S,D] (Q); 2 fp16 single [B,H,S,D]
// (K); 3 fp16 single [B,H,D,S] transposed (V).
// ===========================================================================
#define ROWB 80
#define OFF_AHI 0
#define OFF_ALO 10240
#define OFF_W   20480                    // W single fp16: 10240
#define GSTG_A  30720                    // 2 x 16384
#define GSTG_W  63488                    // 2 x 16384
#define GEMM_SMEM 96256                  // 2 CTAs/SM

template<bool GATHER_A, int OMODE>
__global__ __launch_bounds__(256, 2)
void gemm_mma(const float* __restrict__ A, const float* __restrict__ W,
              const float* __restrict__ bias, float* __restrict__ C32,
              __half* __restrict__ Chi, __half* __restrict__ Clo,
              float scale)
{
    extern __shared__ char smem[];
    const uint32_t sb = smem_u32(smem);

    const int tid = threadIdx.x;
    const int wid = tid >> 5, lid = tid & 31;
    const int warp_m = wid >> 2;
    const int warp_n = wid & 3;
    const int bm = blockIdx.x * 128, bn = blockIdx.y * 128;

    const int grp = lid >> 3, r = lid & 7;
    const uint32_t a_base = sb + OFF_AHI
        + (uint32_t)(warp_m * 64 + ((grp & 1) << 3) + r) * ROWB
        + (uint32_t)(((grp >> 1) & 1) << 4);
    const uint32_t b_base = sb + OFF_W
        + (uint32_t)(warp_n * 32 + (((grp >> 1) & 1) << 3) + r) * ROWB
        + (uint32_t)((grp & 1) << 4);

    auto issue_tile = [&](int it) {
        const int k0 = it * 32;
        const uint32_t buf = (uint32_t)(it & 1) * 16384u;
#pragma unroll
        for (int l = 0; l < 4; l++) {
            int idx = tid + l * 256;
            int row = idx >> 3;
            int cf  = (idx & 7) << 2;
            uint32_t doff = (uint32_t)row * 128 + (uint32_t)cf * 4;
            const float* srcA;
            if (GATHER_A) {
                int m = bm + row;
                int b = m >> 11, s = m & 2047;
                int h = it >> 1, dl = ((it & 1) << 5) + cf;
                srcA = A + ((((b << 4) + h) * SEQ + s) << 6) + dl;
            } else {
                srcA = A + (size_t)(bm + row) * DM + k0 + cf;
            }
            CP16(sb + GSTG_A + buf + doff, srcA);
            CP16(sb + GSTG_W + buf + doff,
                 W + (size_t)(bn + row) * DM + k0 + cf);
        }
    };

    float acc[4][4][4];
#pragma unroll
    for (int i = 0; i < 4; i++)
#pragma unroll
        for (int j = 0; j < 4; j++)
#pragma unroll
            for (int e = 0; e < 4; e++) acc[i][j][e] = 0.f;

    issue_tile(0);
    CP_COMMIT();

    for (int it = 0; it < DM / 32; it++) {
        CP_WAIT0();
        __syncthreads();
        if (it + 1 < DM / 32) { issue_tile(it + 1); CP_COMMIT(); }

        // ---- convert: A -> fp16 hi/lo, W -> fp16 single ----
        const float* stA = (const float*)(smem + GSTG_A + (it & 1) * 16384);
        const float* stW = (const float*)(smem + GSTG_W + (it & 1) * 16384);
#pragma unroll
        for (int l = 0; l < 4; l++) {
            int idx = tid + l * 256;
            int row = idx >> 3;
            int cf  = (idx & 7) << 2;
            uint32_t soff = (uint32_t)row * ROWB + (uint32_t)cf * 2;
            float4 va = *(const float4*)(stA + row * 32 + cf);
            *(uint2*)(smem + OFF_AHI + soff) =
                make_uint2(pack_h(va.x, va.y), pack_h(va.z, va.w));
            *(uint2*)(smem + OFF_ALO + soff) =
                make_uint2(pack_h(va.x - rh(va.x), va.y - rh(va.y)),
                           pack_h(va.z - rh(va.z), va.w - rh(va.w)));
            float4 vw = *(const float4*)(stW + row * 32 + cf);
            *(uint2*)(smem + OFF_W + soff) =
                make_uint2(pack_h(vw.x, vw.y), pack_h(vw.z, vw.w));
        }
        __syncthreads();

#pragma unroll
        for (int ks = 0; ks < 2; ks++) {
            const uint32_t offk = (uint32_t)ks * 32;
            uint32_t ah[4][4], al[4][4], bh[2][4];
#pragma unroll
            for (int fm = 0; fm < 4; fm++) {
                LDSM4(ah[fm], a_base + fm * (16 * ROWB) + offk);
                LDSM4(al[fm], a_base + (OFF_ALO - OFF_AHI) + fm * (16 * ROWB) + offk);
            }
#pragma unroll
            for (int p = 0; p < 2; p++)
                LDSM4(bh[p], b_base + p * (16 * ROWB) + offk);
#pragma unroll
            for (int fm = 0; fm < 4; fm++)
#pragma unroll
                for (int fn = 0; fn < 4; fn++) {
                    const int p = fn >> 1, o = (fn & 1) << 1;
                    MMA16816(acc[fm][fn], ah[fm], bh[p][o], bh[p][o + 1]);
                    MMA16816(acc[fm][fn], al[fm], bh[p][o], bh[p][o + 1]);
                }
        }
    }

    const int qrow = lid >> 2;
    const int qcol = (lid & 3) << 1;
#pragma unroll
    for (int fm = 0; fm < 4; fm++) {
        int m1 = bm + warp_m * 64 + fm * 16 + qrow;
        int m2 = m1 + 8;
#pragma unroll
        for (int fn = 0; fn < 4; fn++) {
            int n = bn + warp_n * 32 + fn * 8 + qcol;
            float2 bb = *(const float2*)(bias + n);
            float x1 = (acc[fm][fn][0] + bb.x) * scale;
            float y1 = (acc[fm][fn][1] + bb.y) * scale;
            float x2 = (acc[fm][fn][2] + bb.x) * scale;
            float y2 = (acc[fm][fn][3] + bb.y) * scale;
            if (OMODE == 0) {
                *(float2*)(C32 + (size_t)m1 * DM + n) = make_float2(x1, y1);
                *(float2*)(C32 + (size_t)m2 * DM + n) = make_float2(x2, y2);
            } else {
                int h = n >> 6, dl = n & 63;
                int b1 = m1 >> 11, s1 = m1 & 2047;
                int b2 = m2 >> 11, s2 = m2 & 2047;
                if (OMODE == 1) {          // Q: fp16 hi/lo
                    size_t i1 = (size_t)((((b1 << 4) + h) * SEQ + s1) << 6) + dl;
                    size_t i2 = (size_t)((((b2 << 4) + h) * SEQ + s2) << 6) + dl;
                    *(uint32_t*)(Chi + i1) = pack_h(x1, y1);
                    *(uint32_t*)(Clo + i1) = pack_h(x1 - rh(x1), y1 - rh(y1));
                    *(uint32_t*)(Chi + i2) = pack_h(x2, y2);
                    *(uint32_t*)(Clo + i2) = pack_h(x2 - rh(x2), y2 - rh(y2));
                } else if (OMODE == 2) {   // K: fp16 single
                    size_t i1 = (size_t)((((b1 << 4) + h) * SEQ + s1) << 6) + dl;
                    size_t i2 = (size_t)((((b2 << 4) + h) * SEQ + s2) << 6) + dl;
                    *(uint32_t*)(Chi + i1) = pack_h(x1, y1);
                    *(uint32_t*)(Chi + i2) = pack_h(x2, y2);
                } else {                   // V: fp16 single, transposed [B,H,D,S]
                    size_t t1 = ((size_t)((b1 << 4) + h) * 64 + dl) * SEQ + s1;
                    size_t t2 = ((size_t)((b2 << 4) + h) * 64 + dl) * SEQ + s2;
                    Chi[t1] = __float2half_rn(x1);
                    Chi[t1 + SEQ] = __float2half_rn(y1);
                    Chi[t2] = __float2half_rn(x2);
                    Chi[t2 + SEQ] = __float2half_rn(y2);
                }
            }
        }
    }
}

// ===========================================================================
// fp16 flash attention: Q = hi/lo fp16 (persistent smem), K/VT single fp16
// (cp.async double-buffered, 1 barrier/iter). scores = Qhi*K + Qlo*K;
// PV: P split hi/lo in regs, O += Phi*V + Plo*V. log2-domain softmax.
// ===========================================================================
#define AROWB 144
#define AQHI  0
#define AQLO  18432
#define ABUF  36864                   // two buffers of 18432 (K 9216 + VT 9216)
#define ATT_SMEM (ABUF + 2 * 18432)   // 73728 -> 2 CTAs/SM

__global__ __launch_bounds__(256, 2)
void attn_mma(const __half* __restrict__ Qhi, const __half* __restrict__ Qlo,
              const __half* __restrict__ K1, const __half* __restrict__ VT1,
              float* __restrict__ O)
{
    extern __shared__ char smem[];
    const uint32_t sb = smem_u32(smem);
    const int tid = threadIdx.x, wid = tid >> 5, lid = tid & 31;
    const int grp = lid >> 3, r = lid & 7;

    const int bh = blockIdx.z * NH + blockIdx.y;
    const int q0 = blockIdx.x * 128;
    const __half* Qhp = Qhi + (size_t)(bh * SEQ + q0) * DEPTH;
    const __half* Qlp = Qlo + (size_t)(bh * SEQ + q0) * DEPTH;
    const __half* Kp  = K1  + (size_t)bh * SEQ * DEPTH;
    const __half* Vp  = VT1 + (size_t)bh * DEPTH * SEQ;
    float* Op = O + (size_t)(bh * SEQ + q0) * DEPTH;

    const int crow = tid >> 3;     // 0..31
    const int cch  = tid & 7;      // 16B chunk

    auto issue_tile = [&](int kt) {
        const uint32_t buf = sb + ABUF + (uint32_t)(kt & 1) * 18432u;
        const int s0 = kt * 64;
        // 2 mats x 64 rows x 8 chunks = 1024 chunks; 4 per thread
#pragma unroll
        for (int l = 0; l < 4; l++) {
            int mat = l >> 1;                  // 0 K, 1 VT
            int row = ((l & 1) << 5) + crow;   // 0..63
            uint32_t dst = buf + (uint32_t)mat * 9216u
                         + (uint32_t)row * AROWB + (uint32_t)cch * 16;
            const __half* src = (mat == 0)
                ? Kp + (size_t)(s0 + row) * DEPTH + cch * 8
                : Vp + (size_t)row * SEQ + s0 + cch * 8;
            CP16(dst, src);
        }
    };

    // prologue: Q persistent (2 mats x 128 rows x 8 chunks = 2048; 8/thread)
#pragma unroll
    for (int l = 0; l < 8; l++) {
        int mat = l >> 2;
        int row = ((l & 3) << 5) + crow;
        uint32_t dst = sb + (uint32_t)mat * 18432u
                     + (uint32_t)row * AROWB + (uint32_t)cch * 16;
        const __half* src = (mat == 0 ? Qhp : Qlp)
                          + (size_t)row * DEPTH + cch * 8;
        CP16(dst, src);
    }
    issue_tile(0);
    CP_COMMIT();

    const uint32_t qbase = sb + (uint32_t)(wid * 16 + ((grp & 1) << 3) + r) * AROWB
                         + (uint32_t)(((grp >> 1) & 1) << 4);
    const uint32_t bpat  = (uint32_t)(((grp & 2) << 2) + r) * AROWB
                         + (uint32_t)((grp & 1) << 4);

    float o[8][4];
#pragma unroll
    for (int fn = 0; fn < 8; fn++)
#pragma unroll
        for (int e = 0; e < 4; e++) o[fn][e] = 0.f;
    float m1 = -1e30f, m2 = -1e30f, l1 = 0.f, l2 = 0.f;

    for (int kt = 0; kt < SEQ / 64; kt++) {
        CP_WAIT0();
        __syncthreads();
        if (kt + 1 < SEQ / 64) { issue_tile(kt + 1); CP_COMMIT(); }

        const uint32_t kvb = sb + ABUF + (uint32_t)(kt & 1) * 18432u + bpat;

        // ---- scores: s(16x64) = Qhi*K + Qlo*K ----
        float s[8][4];
#pragma unroll
        for (int fn = 0; fn < 8; fn++)
#pragma unroll
            for (int e = 0; e < 4; e++) s[fn][e] = 0.f;

#pragma unroll
        for (int ks = 0; ks < 4; ks++) {
            uint32_t qh[4], ql[4];
            LDSM4(qh, qbase + AQHI + ks * 32);
            LDSM4(ql, qbase + AQLO + ks * 32);
            uint32_t kh[4][4];
#pragma unroll
            for (int p = 0; p < 4; p++)
                LDSM4(kh[p], kvb + p * (16 * AROWB) + ks * 32);
#pragma unroll
            for (int fn = 0; fn < 8; fn++) {
                const int p = fn >> 1, o2 = (fn & 1) << 1;
                MMA16816(s[fn], qh, kh[p][o2], kh[p][o2 + 1]);
                MMA16816(s[fn], ql, kh[p][o2], kh[p][o2 + 1]);
            }
        }

        // ---- online softmax (log2 domain) ----
        float mx1 = -1e30f, mx2 = -1e30f;
#pragma unroll
        for (int fn = 0; fn < 8; fn++) {
            mx1 = fmaxf(mx1, fmaxf(s[fn][0], s[fn][1]));
            mx2 = fmaxf(mx2, fmaxf(s[fn][2], s[fn][3]));
        }
        mx1 = fmaxf(mx1, __shfl_xor_sync(0xffffffffu, mx1, 1));
        mx1 = fmaxf(mx1, __shfl_xor_sync(0xffffffffu, mx1, 2));
        mx2 = fmaxf(mx2, __shfl_xor_sync(0xffffffffu, mx2, 1));
        mx2 = fmaxf(mx2, __shfl_xor_sync(0xffffffffu, mx2, 2));

        float mn1 = fmaxf(m1, mx1), mn2 = fmaxf(m2, mx2);
        float c1 = ex2(m1 - mn1), c2 = ex2(m2 - mn2);
        m1 = mn1; m2 = mn2;

        float rs1 = 0.f, rs2 = 0.f;
#pragma unroll
        for (int fn = 0; fn < 8; fn++) {
            s[fn][0] = ex2(s[fn][0] - m1);
            s[fn][1] = ex2(s[fn][1] - m1);
            s[fn][2] = ex2(s[fn][2] - m2);
            s[fn][3] = ex2(s[fn][3] - m2);
            rs1 += s[fn][0] + s[fn][1];
            rs2 += s[fn][2] + s[fn][3];
        }
        rs1 += __shfl_xor_sync(0xffffffffu, rs1, 1);
        rs1 += __shfl_xor_sync(0xffffffffu, rs1, 2);
        rs2 += __shfl_xor_sync(0xffffffffu, rs2, 1);
        rs2 += __shfl_xor_sync(0xffffffffu, rs2, 2);
        l1 = l1 * c1 + rs1;
        l2 = l2 * c2 + rs2;
#pragma unroll
        for (int fn = 0; fn < 8; fn++) {
            o[fn][0] *= c1; o[fn][1] *= c1;
            o[fn][2] *= c2; o[fn][3] *= c2;
        }

        // ---- O += P @ V : Phi*V + Plo*V ----
#pragma unroll
        for (int ks = 0; ks < 4; ks++) {
            uint32_t pah[4], pal[4];
            {
                float p0 = s[2 * ks][0],     p1 = s[2 * ks][1];
                float p2 = s[2 * ks][2],     p3 = s[2 * ks][3];
                float p4 = s[2 * ks + 1][0], p5 = s[2 * ks + 1][1];
                float p6 = s[2 * ks + 1][2], p7 = s[2 * ks + 1][3];
                pah[0] = pack_h(p0, p1);  pah[1] = pack_h(p2, p3);
                pah[2] = pack_h(p4, p5);  pah[3] = pack_h(p6, p7);
                pal[0] = pack_h(p0 - rh(p0), p1 - rh(p1));
                pal[1] = pack_h(p2 - rh(p2), p3 - rh(p3));
                pal[2] = pack_h(p4 - rh(p4), p5 - rh(p5));
                pal[3] = pack_h(p6 - rh(p6), p7 - rh(p7));
            }
            uint32_t vh[4][4];
#pragma unroll
            for (int p = 0; p < 4; p++)
                LDSM4(vh[p], kvb + 9216 + p * (16 * AROWB) + ks * 32);
#pragma unroll
            for (int fn = 0; fn < 8; fn++) {
                const int p = fn >> 1, o2 = (fn & 1) << 1;
                MMA16816(o[fn], pah, vh[p][o2], vh[p][o2 + 1]);
                MMA16816(o[fn], pal, vh[p][o2], vh[p][o2 + 1]);
            }
        }
    }

    // ---- epilogue: normalize, store fp32 ----
    float inv1 = 1.f / l1, inv2 = 1.f / l2;
    int qr1 = wid * 16 + (lid >> 2);
    int qr2 = qr1 + 8;
#pragma unroll
    for (int fn = 0; fn < 8; fn++) {
        int col = fn * 8 + (lid & 3) * 2;
        *(float2*)(Op + qr1 * DEPTH + col) =
            make_float2(o[fn][0] * inv1, o[fn][1] * inv1);
        *(float2*)(Op + qr2 * DEPTH + col) =
            make_float2(o[fn][2] * inv2, o[fn][3] * inv2);
    }
}

// ---------------------------------------------------------------------------
extern "C" void kernel_launch(void* const* d_in, const int* in_sizes, int n_in,
                              void* d_out, int out_size)
{
    const float* q  = (const float*)d_in[0];
    const float* k  = (const float*)d_in[1];
    const float* v  = (const float*)d_in[2];
    const float* wq = (const float*)d_in[3];
    const float* bq = (const float*)d_in[4];
    const float* wk = (const float*)d_in[5];
    const float* bk = (const float*)d_in[6];
    const float* wv = (const float*)d_in[7];
    const float* bv = (const float*)d_in[8];
    const float* wo = (const float*)d_in[9];
    const float* bo = (const float*)d_in[10];
    float* out = (float*)d_out;

    __half *gQh, *gQl, *gK1, *gV1;
    float *gO;
    cudaGetSymbolAddress((void**)&gQh, g_Qhi);
    cudaGetSymbolAddress((void**)&gQl, g_Qlo);
    cudaGetSymbolAddress((void**)&gK1, g_K1);
    cudaGetSymbolAddress((void**)&gV1, g_VT1);
    cudaGetSymbolAddress((void**)&gO,  g_O);

    cudaFuncSetAttribute(gemm_mma<false, 1>,
                         cudaFuncAttributeMaxDynamicSharedMemorySize, GEMM_SMEM);
    cudaFuncSetAttribute(gemm_mma<false, 2>,
                         cudaFuncAttributeMaxDynamicSharedMemorySize, GEMM_SMEM);
    cudaFuncSetAttribute(gemm_mma<false, 3>,
                         cudaFuncAttributeMaxDynamicSharedMemorySize, GEMM_SMEM);
    cudaFuncSetAttribute(gemm_mma<true, 0>,
                         cudaFuncAttributeMaxDynamicSharedMemorySize, GEMM_SMEM);
    cudaFuncSetAttribute(attn_mma,
                         cudaFuncAttributeMaxDynamicSharedMemorySize, ATT_SMEM);

    dim3 gproj(MTOT / 128, DM / 128);  // (32, 8)

    gemm_mma<false, 1><<<gproj, 256, GEMM_SMEM>>>(q, wq, bq, nullptr,
                                                  gQh, gQl, QSCALE);
    gemm_mma<false, 2><<<gproj, 256, GEMM_SMEM>>>(k, wk, bk, nullptr,
                                                  gK1, nullptr, 1.0f);
    gemm_mma<false, 3><<<gproj, 256, GEMM_SMEM>>>(v, wv, bv, nullptr,
                                                  gV1, nullptr, 1.0f);

    attn_mma<<<dim3(SEQ / 128, NH, BATCH), 256, ATT_SMEM>>>(gQh, gQl, gK1, gV1,
                                                            gO);

    gemm_mma<true, 0><<<gproj, 256, GEMM_SMEM>>>(gO, wo, bo, out,
                                                 nullptr, nullptr, 1.0f);
}

// round 12
// speedup vs baseline: 1.8614x; 1.1959x over previous
#include <cuda_runtime.h>
#include <cuda_fp16.h>
#include <cstdint>
#include <math.h>

#define BATCH 2
#define SEQ   2048
#define DM    1024
#define NH    16
#define DEPTH 64
#define MTOT  (BATCH*SEQ)   // 4096

#define QSCALE 0.1803368801111204f   // 0.125 * log2(e): scores in log2 domain

// Scratch (fp16)
__device__ __half g_Q1 [BATCH*NH*SEQ*DEPTH];  // [B,H,S,D], pre-scaled, single
__device__ __half g_K1 [BATCH*NH*SEQ*DEPTH];  // [B,H,S,D], single fp16
__device__ __half g_VT1[BATCH*NH*DEPTH*SEQ];  // [B,H,D,S], single fp16
__device__ float  g_O  [BATCH*NH*SEQ*DEPTH];  // attn out fp32 [B,H,S,D]

// ===========================================================================
// helpers
// ===========================================================================
__device__ __forceinline__ uint32_t smem_u32(const void* p) {
    uint32_t a;
    asm("{ .reg .u64 t; cvta.to.shared.u64 t, %1; cvt.u32.u64 %0, t; }"
        : "=r"(a) : "l"(p));
    return a;
}
__device__ __forceinline__ uint32_t pack_h(float x, float y) {
    __half2 h = __floats2half2_rn(x, y);
    return *(uint32_t*)&h;
}
__device__ __forceinline__ float rh(float x) {   // round to fp16, back to f32
    return __half2float(__float2half_rn(x));
}
__device__ __forceinline__ float ex2(float x) {
    float y; asm("ex2.approx.ftz.f32 %0, %1;" : "=f"(y) : "f"(x)); return y;
}

#define LDSM4(R, addr) \
    asm volatile("ldmatrix.sync.aligned.m8n8.x4.shared.b16 {%0,%1,%2,%3}, [%4];" \
        : "=r"((R)[0]), "=r"((R)[1]), "=r"((R)[2]), "=r"((R)[3]) : "r"(addr))

#define MMA16816(D, A, B0, B1) \
    asm volatile("mma.sync.aligned.m16n8k16.row.col.f32.f16.f16.f32 " \
        "{%0,%1,%2,%3}, {%4,%5,%6,%7}, {%8,%9}, {%0,%1,%2,%3};" \
        : "+f"((D)[0]), "+f"((D)[1]), "+f"((D)[2]), "+f"((D)[3]) \
        : "r"((A)[0]), "r"((A)[1]), "r"((A)[2]), "r"((A)[3]), "r"(B0), "r"(B1))

#define CP16(dst, src) \
    asm volatile("cp.async.cg.shared.global [%0], [%1], 16;" \
        :: "r"(dst), "l"(src) : "memory")
#define CP_COMMIT()  asm volatile("cp.async.commit_group;" ::: "memory")
#define CP_WAIT0()   asm volatile("cp.async.wait_group 0;" ::: "memory")

// ===========================================================================
// 2-term fp16 GEMM (round-11 validated): C = A @ W.T (+bias,*scale).
// A = Ahi+Alo fp16 split, W single fp16; D = Ahi*W + Alo*W (fp32 accum).
// CTA 128x128, BK=32, 8 warps (2m x 4n), double-buffered staging, 2 CTAs/SM.
// OMODE: 0 fp32 [M,N]; 2 fp16 single [B,H,S,D]; 3 fp16 single [B,H,D,S].
// ===========================================================================
#define ROWB 80
#define OFF_AHI 0
#define OFF_ALO 10240
#define OFF_W   20480
#define GSTG_A  30720                    // 2 x 16384
#define GSTG_W  63488                    // 2 x 16384
#define GEMM_SMEM 96256                  // 2 CTAs/SM

template<bool GATHER_A, int OMODE>
__global__ __launch_bounds__(256, 2)
void gemm_mma(const float* __restrict__ A, const float* __restrict__ W,
              const float* __restrict__ bias, float* __restrict__ C32,
              __half* __restrict__ Ch, float scale)
{
    extern __shared__ char smem[];
    const uint32_t sb = smem_u32(smem);

    const int tid = threadIdx.x;
    const int wid = tid >> 5, lid = tid & 31;
    const int warp_m = wid >> 2;
    const int warp_n = wid & 3;
    const int bm = blockIdx.x * 128, bn = blockIdx.y * 128;

    const int grp = lid >> 3, r = lid & 7;
    const uint32_t a_base = sb + OFF_AHI
        + (uint32_t)(warp_m * 64 + ((grp & 1) << 3) + r) * ROWB
        + (uint32_t)(((grp >> 1) & 1) << 4);
    const uint32_t b_base = sb + OFF_W
        + (uint32_t)(warp_n * 32 + (((grp >> 1) & 1) << 3) + r) * ROWB
        + (uint32_t)((grp & 1) << 4);

    auto issue_tile = [&](int it) {
        const int k0 = it * 32;
        const uint32_t buf = (uint32_t)(it & 1) * 16384u;
#pragma unroll
        for (int l = 0; l < 4; l++) {
            int idx = tid + l * 256;
            int row = idx >> 3;
            int cf  = (idx & 7) << 2;
            uint32_t doff = (uint32_t)row * 128 + (uint32_t)cf * 4;
            const float* srcA;
            if (GATHER_A) {
                int m = bm + row;
                int b = m >> 11, s = m & 2047;
                int h = it >> 1, dl = ((it & 1) << 5) + cf;
                srcA = A + ((((b << 4) + h) * SEQ + s) << 6) + dl;
            } else {
                srcA = A + (size_t)(bm + row) * DM + k0 + cf;
            }
            CP16(sb + GSTG_A + buf + doff, srcA);
            CP16(sb + GSTG_W + buf + doff,
                 W + (size_t)(bn + row) * DM + k0 + cf);
        }
    };

    float acc[4][4][4];
#pragma unroll
    for (int i = 0; i < 4; i++)
#pragma unroll
        for (int j = 0; j < 4; j++)
#pragma unroll
            for (int e = 0; e < 4; e++) acc[i][j][e] = 0.f;

    issue_tile(0);
    CP_COMMIT();

    for (int it = 0; it < DM / 32; it++) {
        CP_WAIT0();
        __syncthreads();
        if (it + 1 < DM / 32) { issue_tile(it + 1); CP_COMMIT(); }

        const float* stA = (const float*)(smem + GSTG_A + (it & 1) * 16384);
        const float* stW = (const float*)(smem + GSTG_W + (it & 1) * 16384);
#pragma unroll
        for (int l = 0; l < 4; l++) {
            int idx = tid + l * 256;
            int row = idx >> 3;
            int cf  = (idx & 7) << 2;
            uint32_t soff = (uint32_t)row * ROWB + (uint32_t)cf * 2;
            float4 va = *(const float4*)(stA + row * 32 + cf);
            *(uint2*)(smem + OFF_AHI + soff) =
                make_uint2(pack_h(va.x, va.y), pack_h(va.z, va.w));
            *(uint2*)(smem + OFF_ALO + soff) =
                make_uint2(pack_h(va.x - rh(va.x), va.y - rh(va.y)),
                           pack_h(va.z - rh(va.z), va.w - rh(va.w)));
            float4 vw = *(const float4*)(stW + row * 32 + cf);
            *(uint2*)(smem + OFF_W + soff) =
                make_uint2(pack_h(vw.x, vw.y), pack_h(vw.z, vw.w));
        }
        __syncthreads();

#pragma unroll
        for (int ks = 0; ks < 2; ks++) {
            const uint32_t offk = (uint32_t)ks * 32;
            uint32_t ah[4][4], al[4][4], bh[2][4];
#pragma unroll
            for (int fm = 0; fm < 4; fm++) {
                LDSM4(ah[fm], a_base + fm * (16 * ROWB) + offk);
                LDSM4(al[fm], a_base + (OFF_ALO - OFF_AHI) + fm * (16 * ROWB) + offk);
            }
#pragma unroll
            for (int p = 0; p < 2; p++)
                LDSM4(bh[p], b_base + p * (16 * ROWB) + offk);
#pragma unroll
            for (int fm = 0; fm < 4; fm++)
#pragma unroll
                for (int fn = 0; fn < 4; fn++) {
                    const int p = fn >> 1, o = (fn & 1) << 1;
                    MMA16816(acc[fm][fn], ah[fm], bh[p][o], bh[p][o + 1]);
                    MMA16816(acc[fm][fn], al[fm], bh[p][o], bh[p][o + 1]);
                }
        }
    }

    const int qrow = lid >> 2;
    const int qcol = (lid & 3) << 1;
#pragma unroll
    for (int fm = 0; fm < 4; fm++) {
        int m1 = bm + warp_m * 64 + fm * 16 + qrow;
        int m2 = m1 + 8;
#pragma unroll
        for (int fn = 0; fn < 4; fn++) {
            int n = bn + warp_n * 32 + fn * 8 + qcol;
            float2 bb = *(const float2*)(bias + n);
            float x1 = (acc[fm][fn][0] + bb.x) * scale;
            float y1 = (acc[fm][fn][1] + bb.y) * scale;
            float x2 = (acc[fm][fn][2] + bb.x) * scale;
            float y2 = (acc[fm][fn][3] + bb.y) * scale;
            if (OMODE == 0) {
                *(float2*)(C32 + (size_t)m1 * DM + n) = make_float2(x1, y1);
                *(float2*)(C32 + (size_t)m2 * DM + n) = make_float2(x2, y2);
            } else {
                int h = n >> 6, dl = n & 63;
                int b1 = m1 >> 11, s1 = m1 & 2047;
                int b2 = m2 >> 11, s2 = m2 & 2047;
                if (OMODE == 2) {          // fp16 single [B,H,S,D]
                    size_t i1 = (size_t)((((b1 << 4) + h) * SEQ + s1) << 6) + dl;
                    size_t i2 = (size_t)((((b2 << 4) + h) * SEQ + s2) << 6) + dl;
                    *(uint32_t*)(Ch + i1) = pack_h(x1, y1);
                    *(uint32_t*)(Ch + i2) = pack_h(x2, y2);
                } else {                   // fp16 single transposed [B,H,D,S]
                    size_t t1 = ((size_t)((b1 << 4) + h) * 64 + dl) * SEQ + s1;
                    size_t t2 = ((size_t)((b2 << 4) + h) * 64 + dl) * SEQ + s2;
                    Ch[t1] = __float2half_rn(x1);
                    Ch[t1 + SEQ] = __float2half_rn(y1);
                    Ch[t2] = __float2half_rn(x2);
                    Ch[t2 + SEQ] = __float2half_rn(y2);
                }
            }
        }
    }
}

// ===========================================================================
// fp16 flash attention, all single fp16 operands: Q persistent smem,
// K/VT cp.async double-buffered (1 barrier/iter), scores = Q*K (1 MMA),
// PV: O += P*V (1 MMA). log2-domain softmax. 2 CTAs/SM.
// ===========================================================================
#define AROWB 144
#define AQ1   0                       // Q single: 128 x 144 = 18432
#define ABUF  18432                   // two buffers of 18432 (K 9216 + VT 9216)
#define ATT_SMEM (ABUF + 2 * 18432)   // 55296 -> 2 CTAs/SM

__global__ __launch_bounds__(256, 2)
void attn_mma(const __half* __restrict__ Q1, const __half* __restrict__ K1,
              const __half* __restrict__ VT1, float* __restrict__ O)
{
    extern __shared__ char smem[];
    const uint32_t sb = smem_u32(smem);
    const int tid = threadIdx.x, wid = tid >> 5, lid = tid & 31;
    const int grp = lid >> 3, r = lid & 7;

    const int bh = blockIdx.z * NH + blockIdx.y;
    const int q0 = blockIdx.x * 128;
    const __half* Qp = Q1  + (size_t)(bh * SEQ + q0) * DEPTH;
    const __half* Kp = K1  + (size_t)bh * SEQ * DEPTH;
    const __half* Vp = VT1 + (size_t)bh * DEPTH * SEQ;
    float* Op = O + (size_t)(bh * SEQ + q0) * DEPTH;

    const int crow = tid >> 3;     // 0..31
    const int cch  = tid & 7;      // 16B chunk

    auto issue_tile = [&](int kt) {
        const uint32_t buf = sb + ABUF + (uint32_t)(kt & 1) * 18432u;
        const int s0 = kt * 64;
#pragma unroll
        for (int l = 0; l < 4; l++) {
            int mat = l >> 1;                  // 0 K, 1 VT
            int row = ((l & 1) << 5) + crow;   // 0..63
            uint32_t dst = buf + (uint32_t)mat * 9216u
                         + (uint32_t)row * AROWB + (uint32_t)cch * 16;
            const __half* src = (mat == 0)
                ? Kp + (size_t)(s0 + row) * DEPTH + cch * 8
                : Vp + (size_t)row * SEQ + s0 + cch * 8;
            CP16(dst, src);
        }
    };

    // prologue: Q persistent (128 rows x 8 chunks = 1024 chunks; 4/thread)
#pragma unroll
    for (int l = 0; l < 4; l++) {
        int row = ((l & 3) << 5) + crow;       // 0..127
        uint32_t dst = sb + AQ1 + (uint32_t)row * AROWB + (uint32_t)cch * 16;
        CP16(dst, Qp + (size_t)row * DEPTH + cch * 8);
    }
    issue_tile(0);
    CP_COMMIT();

    const uint32_t qbase = sb + AQ1
        + (uint32_t)(wid * 16 + ((grp & 1) << 3) + r) * AROWB
        + (uint32_t)(((grp >> 1) & 1) << 4);
    const uint32_t bpat  = (uint32_t)(((grp & 2) << 2) + r) * AROWB
                         + (uint32_t)((grp & 1) << 4);

    float o[8][4];
#pragma unroll
    for (int fn = 0; fn < 8; fn++)
#pragma unroll
        for (int e = 0; e < 4; e++) o[fn][e] = 0.f;
    float m1 = -1e30f, m2 = -1e30f, l1 = 0.f, l2 = 0.f;

    for (int kt = 0; kt < SEQ / 64; kt++) {
        CP_WAIT0();
        __syncthreads();
        if (kt + 1 < SEQ / 64) { issue_tile(kt + 1); CP_COMMIT(); }

        const uint32_t kvb = sb + ABUF + (uint32_t)(kt & 1) * 18432u + bpat;

        // ---- scores: s(16x64) = Q*K (single fp16) ----
        float s[8][4];
#pragma unroll
        for (int fn = 0; fn < 8; fn++)
#pragma unroll
            for (int e = 0; e < 4; e++) s[fn][e] = 0.f;

#pragma unroll
        for (int ks = 0; ks < 4; ks++) {
            uint32_t qh[4];
            LDSM4(qh, qbase + ks * 32);
            uint32_t kh[4][4];
#pragma unroll
            for (int p = 0; p < 4; p++)
                LDSM4(kh[p], kvb + p * (16 * AROWB) + ks * 32);
#pragma unroll
            for (int fn = 0; fn < 8; fn++) {
                const int p = fn >> 1, o2 = (fn & 1) << 1;
                MMA16816(s[fn], qh, kh[p][o2], kh[p][o2 + 1]);
            }
        }

        // ---- online softmax (log2 domain) ----
        float mx1 = -1e30f, mx2 = -1e30f;
#pragma unroll
        for (int fn = 0; fn < 8; fn++) {
            mx1 = fmaxf(mx1, fmaxf(s[fn][0], s[fn][1]));
            mx2 = fmaxf(mx2, fmaxf(s[fn][2], s[fn][3]));
        }
        mx1 = fmaxf(mx1, __shfl_xor_sync(0xffffffffu, mx1, 1));
        mx1 = fmaxf(mx1, __shfl_xor_sync(0xffffffffu, mx1, 2));
        mx2 = fmaxf(mx2, __shfl_xor_sync(0xffffffffu, mx2, 1));
        mx2 = fmaxf(mx2, __shfl_xor_sync(0xffffffffu, mx2, 2));

        float mn1 = fmaxf(m1, mx1), mn2 = fmaxf(m2, mx2);
        float c1 = ex2(m1 - mn1), c2 = ex2(m2 - mn2);
        m1 = mn1; m2 = mn2;

        float rs1 = 0.f, rs2 = 0.f;
#pragma unroll
        for (int fn = 0; fn < 8; fn++) {
            s[fn][0] = ex2(s[fn][0] - m1);
            s[fn][1] = ex2(s[fn][1] - m1);
            s[fn][2] = ex2(s[fn][2] - m2);
            s[fn][3] = ex2(s[fn][3] - m2);
            rs1 += s[fn][0] + s[fn][1];
            rs2 += s[fn][2] + s[fn][3];
        }
        rs1 += __shfl_xor_sync(0xffffffffu, rs1, 1);
        rs1 += __shfl_xor_sync(0xffffffffu, rs1, 2);
        rs2 += __shfl_xor_sync(0xffffffffu, rs2, 1);
        rs2 += __shfl_xor_sync(0xffffffffu, rs2, 2);
        l1 = l1 * c1 + rs1;
        l2 = l2 * c2 + rs2;
#pragma unroll
        for (int fn = 0; fn < 8; fn++) {
            o[fn][0] *= c1; o[fn][1] *= c1;
            o[fn][2] *= c2; o[fn][3] *= c2;
        }

        // ---- O += P @ V (single fp16 P) ----
#pragma unroll
        for (int ks = 0; ks < 4; ks++) {
            uint32_t pah[4];
            pah[0] = pack_h(s[2 * ks][0],     s[2 * ks][1]);
            pah[1] = pack_h(s[2 * ks][2],     s[2 * ks][3]);
            pah[2] = pack_h(s[2 * ks + 1][0], s[2 * ks + 1][1]);
            pah[3] = pack_h(s[2 * ks + 1][2], s[2 * ks + 1][3]);
            uint32_t vh[4][4];
#pragma unroll
            for (int p = 0; p < 4; p++)
                LDSM4(vh[p], kvb + 9216 + p * (16 * AROWB) + ks * 32);
#pragma unroll
            for (int fn = 0; fn < 8; fn++) {
                const int p = fn >> 1, o2 = (fn & 1) << 1;
                MMA16816(o[fn], pah, vh[p][o2], vh[p][o2 + 1]);
            }
        }
    }

    // ---- epilogue: normalize, store fp32 ----
    float inv1 = 1.f / l1, inv2 = 1.f / l2;
    int qr1 = wid * 16 + (lid >> 2);
    int qr2 = qr1 + 8;
#pragma unroll
    for (int fn = 0; fn < 8; fn++) {
        int col = fn * 8 + (lid & 3) * 2;
        *(float2*)(Op + qr1 * DEPTH + col) =
            make_float2(o[fn][0] * inv1, o[fn][1] * inv1);
        *(float2*)(Op + qr2 * DEPTH + col) =
            make_float2(o[fn][2] * inv2, o[fn][3] * inv2);
    }
}

// ---------------------------------------------------------------------------
extern "C" void kernel_launch(void* const* d_in, const int* in_sizes, int n_in,
                              void* d_out, int out_size)
{
    const float* q  = (const float*)d_in[0];
    const float* k  = (const float*)d_in[1];
    const float* v  = (const float*)d_in[2];
    const float* wq = (const float*)d_in[3];
    const float* bq = (const float*)d_in[4];
    const float* wk = (const float*)d_in[5];
    const float* bk = (const float*)d_in[6];
    const float* wv = (const float*)d_in[7];
    const float* bv = (const float*)d_in[8];
    const float* wo = (const float*)d_in[9];
    const float* bo = (const float*)d_in[10];
    float* out = (float*)d_out;

    __half *gQ1, *gK1, *gV1;
    float *gO;
    cudaGetSymbolAddress((void**)&gQ1, g_Q1);
    cudaGetSymbolAddress((void**)&gK1, g_K1);
    cudaGetSymbolAddress((void**)&gV1, g_VT1);
    cudaGetSymbolAddress((void**)&gO,  g_O);

    cudaFuncSetAttribute(gemm_mma<false, 2>,
                         cudaFuncAttributeMaxDynamicSharedMemorySize, GEMM_SMEM);
    cudaFuncSetAttribute(gemm_mma<false, 3>,
                         cudaFuncAttributeMaxDynamicSharedMemorySize, GEMM_SMEM);
    cudaFuncSetAttribute(gemm_mma<true, 0>,
                         cudaFuncAttributeMaxDynamicSharedMemorySize, GEMM_SMEM);
    cudaFuncSetAttribute(attn_mma,
                         cudaFuncAttributeMaxDynamicSharedMemorySize, ATT_SMEM);

    dim3 gproj(MTOT / 128, DM / 128);  // (32, 8)

    gemm_mma<false, 2><<<gproj, 256, GEMM_SMEM>>>(q, wq, bq, nullptr,
                                                  gQ1, QSCALE);
    gemm_mma<false, 2><<<gproj, 256, GEMM_SMEM>>>(k, wk, bk, nullptr,
                                                  gK1, 1.0f);
    gemm_mma<false, 3><<<gproj, 256, GEMM_SMEM>>>(v, wv, bv, nullptr,
                                                  gV1, 1.0f);

    attn_mma<<<dim3(SEQ / 128, NH, BATCH), 256, ATT_SMEM>>>(gQ1, gK1, gV1, gO);

    gemm_mma<true, 0><<<gproj, 256, GEMM_SMEM>>>(gO, wo, bo, out,
                                                 nullptr, 1.0f);
}

// round 13
// speedup vs baseline: 2.2004x; 1.1821x over previous
#include <cuda_runtime.h>
#include <cuda_fp16.h>
#include <cstdint>
#include <math.h>

#define BATCH 2
#define SEQ   2048
#define DM    1024
#define NH    16
#define DEPTH 64
#define MTOT  (BATCH*SEQ)   // 4096

#define QSCALE 0.1803368801111204f   // 0.125 * log2(e): scores in log2 domain

// Scratch (fp16)
__device__ __half g_Q1 [BATCH*NH*SEQ*DEPTH];  // [B,H,S,D], pre-scaled, single
__device__ __half g_K1 [BATCH*NH*SEQ*DEPTH];  // [B,H,S,D], single fp16
__device__ __half g_VT1[BATCH*NH*DEPTH*SEQ];  // [B,H,D,S], single fp16
__device__ float  g_O  [BATCH*NH*SEQ*DEPTH];  // attn out fp32 [B,H,S,D]

// ===========================================================================
// helpers
// ===========================================================================
__device__ __forceinline__ uint32_t smem_u32(const void* p) {
    uint32_t a;
    asm("{ .reg .u64 t; cvta.to.shared.u64 t, %1; cvt.u32.u64 %0, t; }"
        : "=r"(a) : "l"(p));
    return a;
}
__device__ __forceinline__ uint32_t pack_h(float x, float y) {
    __half2 h = __floats2half2_rn(x, y);
    return *(uint32_t*)&h;
}
__device__ __forceinline__ float rh(float x) {
    return __half2float(__float2half_rn(x));
}
__device__ __forceinline__ float ex2(float x) {
    float y; asm("ex2.approx.ftz.f32 %0, %1;" : "=f"(y) : "f"(x)); return y;
}

#define LDSM4(R, addr) \
    asm volatile("ldmatrix.sync.aligned.m8n8.x4.shared.b16 {%0,%1,%2,%3}, [%4];" \
        : "=r"((R)[0]), "=r"((R)[1]), "=r"((R)[2]), "=r"((R)[3]) : "r"(addr))

#define MMA16816(D, A, B0, B1) \
    asm volatile("mma.sync.aligned.m16n8k16.row.col.f32.f16.f16.f32 " \
        "{%0,%1,%2,%3}, {%4,%5,%6,%7}, {%8,%9}, {%0,%1,%2,%3};" \
        : "+f"((D)[0]), "+f"((D)[1]), "+f"((D)[2]), "+f"((D)[3]) \
        : "r"((A)[0]), "r"((A)[1]), "r"((A)[2]), "r"((A)[3]), "r"(B0), "r"(B1))

#define CP16(dst, src) \
    asm volatile("cp.async.cg.shared.global [%0], [%1], 16;" \
        :: "r"(dst), "l"(src) : "memory")
#define CP_COMMIT()  asm volatile("cp.async.commit_group;" ::: "memory")
#define CP_WAIT0()   asm volatile("cp.async.wait_group 0;" ::: "memory")

// ===========================================================================
// Single-fp16 GEMM: C = A @ W.T (+bias,*scale). A and W both single fp16,
// fp32 accumulate (1 MMA per fragment pair). fp32 staged via cp.async,
// converted inline. CTA 128x128, BK=32, 8 warps (2m x 4n), 2 CTAs/SM.
// OMODE: 0 fp32 [M,N]; 2 fp16 single [B,H,S,D]; 3 fp16 single [B,H,D,S].
// ===========================================================================
#define ROWB 80
#define OFF_A   0                        // A fp16: 10240
#define OFF_W   10240                    // W fp16: 10240
#define GSTG_A  20480                    // 2 x 16384
#define GSTG_W  53248                    // 2 x 16384
#define GEMM_SMEM 86016                  // 2 CTAs/SM

template<bool GATHER_A, int OMODE>
__global__ __launch_bounds__(256, 2)
void gemm_mma(const float* __restrict__ A, const float* __restrict__ W,
              const float* __restrict__ bias, float* __restrict__ C32,
              __half* __restrict__ Ch, float scale)
{
    extern __shared__ char smem[];
    const uint32_t sb = smem_u32(smem);

    const int tid = threadIdx.x;
    const int wid = tid >> 5, lid = tid & 31;
    const int warp_m = wid >> 2;
    const int warp_n = wid & 3;
    const int bm = blockIdx.x * 128, bn = blockIdx.y * 128;

    const int grp = lid >> 3, r = lid & 7;
    const uint32_t a_base = sb + OFF_A
        + (uint32_t)(warp_m * 64 + ((grp & 1) << 3) + r) * ROWB
        + (uint32_t)(((grp >> 1) & 1) << 4);
    const uint32_t b_base = sb + OFF_W
        + (uint32_t)(warp_n * 32 + (((grp >> 1) & 1) << 3) + r) * ROWB
        + (uint32_t)((grp & 1) << 4);

    auto issue_tile = [&](int it) {
        const int k0 = it * 32;
        const uint32_t buf = (uint32_t)(it & 1) * 16384u;
#pragma unroll
        for (int l = 0; l < 4; l++) {
            int idx = tid + l * 256;
            int row = idx >> 3;
            int cf  = (idx & 7) << 2;
            uint32_t doff = (uint32_t)row * 128 + (uint32_t)cf * 4;
            const float* srcA;
            if (GATHER_A) {
                int m = bm + row;
                int b = m >> 11, s = m & 2047;
                int h = it >> 1, dl = ((it & 1) << 5) + cf;
                srcA = A + ((((b << 4) + h) * SEQ + s) << 6) + dl;
            } else {
                srcA = A + (size_t)(bm + row) * DM + k0 + cf;
            }
            CP16(sb + GSTG_A + buf + doff, srcA);
            CP16(sb + GSTG_W + buf + doff,
                 W + (size_t)(bn + row) * DM + k0 + cf);
        }
    };

    float acc[4][4][4];
#pragma unroll
    for (int i = 0; i < 4; i++)
#pragma unroll
        for (int j = 0; j < 4; j++)
#pragma unroll
            for (int e = 0; e < 4; e++) acc[i][j][e] = 0.f;

    issue_tile(0);
    CP_COMMIT();

    for (int it = 0; it < DM / 32; it++) {
        CP_WAIT0();
        __syncthreads();
        if (it + 1 < DM / 32) { issue_tile(it + 1); CP_COMMIT(); }

        // ---- convert: A, W -> single fp16 ----
        const float* stA = (const float*)(smem + GSTG_A + (it & 1) * 16384);
        const float* stW = (const float*)(smem + GSTG_W + (it & 1) * 16384);
#pragma unroll
        for (int l = 0; l < 4; l++) {
            int idx = tid + l * 256;
            int row = idx >> 3;
            int cf  = (idx & 7) << 2;
            uint32_t soff = (uint32_t)row * ROWB + (uint32_t)cf * 2;
            float4 va = *(const float4*)(stA + row * 32 + cf);
            *(uint2*)(smem + OFF_A + soff) =
                make_uint2(pack_h(va.x, va.y), pack_h(va.z, va.w));
            float4 vw = *(const float4*)(stW + row * 32 + cf);
            *(uint2*)(smem + OFF_W + soff) =
                make_uint2(pack_h(vw.x, vw.y), pack_h(vw.z, vw.w));
        }
        __syncthreads();

#pragma unroll
        for (int ks = 0; ks < 2; ks++) {
            const uint32_t offk = (uint32_t)ks * 32;
            uint32_t ah[4][4], bh[2][4];
#pragma unroll
            for (int fm = 0; fm < 4; fm++)
                LDSM4(ah[fm], a_base + fm * (16 * ROWB) + offk);
#pragma unroll
            for (int p = 0; p < 2; p++)
                LDSM4(bh[p], b_base + p * (16 * ROWB) + offk);
#pragma unroll
            for (int fm = 0; fm < 4; fm++)
#pragma unroll
                for (int fn = 0; fn < 4; fn++) {
                    const int p = fn >> 1, o = (fn & 1) << 1;
                    MMA16816(acc[fm][fn], ah[fm], bh[p][o], bh[p][o + 1]);
                }
        }
    }

    const int qrow = lid >> 2;
    const int qcol = (lid & 3) << 1;
#pragma unroll
    for (int fm = 0; fm < 4; fm++) {
        int m1 = bm + warp_m * 64 + fm * 16 + qrow;
        int m2 = m1 + 8;
#pragma unroll
        for (int fn = 0; fn < 4; fn++) {
            int n = bn + warp_n * 32 + fn * 8 + qcol;
            float2 bb = *(const float2*)(bias + n);
            float x1 = (acc[fm][fn][0] + bb.x) * scale;
            float y1 = (acc[fm][fn][1] + bb.y) * scale;
            float x2 = (acc[fm][fn][2] + bb.x) * scale;
            float y2 = (acc[fm][fn][3] + bb.y) * scale;
            if (OMODE == 0) {
                *(float2*)(C32 + (size_t)m1 * DM + n) = make_float2(x1, y1);
                *(float2*)(C32 + (size_t)m2 * DM + n) = make_float2(x2, y2);
            } else {
                int h = n >> 6, dl = n & 63;
                int b1 = m1 >> 11, s1 = m1 & 2047;
                int b2 = m2 >> 11, s2 = m2 & 2047;
                if (OMODE == 2) {          // fp16 single [B,H,S,D]
                    size_t i1 = (size_t)((((b1 << 4) + h) * SEQ + s1) << 6) + dl;
                    size_t i2 = (size_t)((((b2 << 4) + h) * SEQ + s2) << 6) + dl;
                    *(uint32_t*)(Ch + i1) = pack_h(x1, y1);
                    *(uint32_t*)(Ch + i2) = pack_h(x2, y2);
                } else {                   // fp16 single transposed [B,H,D,S]
                    size_t t1 = ((size_t)((b1 << 4) + h) * 64 + dl) * SEQ + s1;
                    size_t t2 = ((size_t)((b2 << 4) + h) * 64 + dl) * SEQ + s2;
                    Ch[t1] = __float2half_rn(x1);
                    Ch[t1 + SEQ] = __float2half_rn(y1);
                    Ch[t2] = __float2half_rn(x2);
                    Ch[t2 + SEQ] = __float2half_rn(y2);
                }
            }
        }
    }
}

// ===========================================================================
// fp16 flash attention — round-12 kernel verbatim (validated 121.8us).
// ===========================================================================
#define AROWB 144
#define AQ1   0
#define ABUF  18432
#define ATT_SMEM (ABUF + 2 * 18432)   // 55296 -> 2 CTAs/SM

__global__ __launch_bounds__(256, 2)
void attn_mma(const __half* __restrict__ Q1, const __half* __restrict__ K1,
              const __half* __restrict__ VT1, float* __restrict__ O)
{
    extern __shared__ char smem[];
    const uint32_t sb = smem_u32(smem);
    const int tid = threadIdx.x, wid = tid >> 5, lid = tid & 31;
    const int grp = lid >> 3, r = lid & 7;

    const int bh = blockIdx.z * NH + blockIdx.y;
    const int q0 = blockIdx.x * 128;
    const __half* Qp = Q1  + (size_t)(bh * SEQ + q0) * DEPTH;
    const __half* Kp = K1  + (size_t)bh * SEQ * DEPTH;
    const __half* Vp = VT1 + (size_t)bh * DEPTH * SEQ;
    float* Op = O + (size_t)(bh * SEQ + q0) * DEPTH;

    const int crow = tid >> 3;
    const int cch  = tid & 7;

    auto issue_tile = [&](int kt) {
        const uint32_t buf = sb + ABUF + (uint32_t)(kt & 1) * 18432u;
        const int s0 = kt * 64;
#pragma unroll
        for (int l = 0; l < 4; l++) {
            int mat = l >> 1;
            int row = ((l & 1) << 5) + crow;
            uint32_t dst = buf + (uint32_t)mat * 9216u
                         + (uint32_t)row * AROWB + (uint32_t)cch * 16;
            const __half* src = (mat == 0)
                ? Kp + (size_t)(s0 + row) * DEPTH + cch * 8
                : Vp + (size_t)row * SEQ + s0 + cch * 8;
            CP16(dst, src);
        }
    };

#pragma unroll
    for (int l = 0; l < 4; l++) {
        int row = ((l & 3) << 5) + crow;
        uint32_t dst = sb + AQ1 + (uint32_t)row * AROWB + (uint32_t)cch * 16;
        CP16(dst, Qp + (size_t)row * DEPTH + cch * 8);
    }
    issue_tile(0);
    CP_COMMIT();

    const uint32_t qbase = sb + AQ1
        + (uint32_t)(wid * 16 + ((grp & 1) << 3) + r) * AROWB
        + (uint32_t)(((grp >> 1) & 1) << 4);
    const uint32_t bpat  = (uint32_t)(((grp & 2) << 2) + r) * AROWB
                         + (uint32_t)((grp & 1) << 4);

    float o[8][4];
#pragma unroll
    for (int fn = 0; fn < 8; fn++)
#pragma unroll
        for (int e = 0; e < 4; e++) o[fn][e] = 0.f;
    float m1 = -1e30f, m2 = -1e30f, l1 = 0.f, l2 = 0.f;

    for (int kt = 0; kt < SEQ / 64; kt++) {
        CP_WAIT0();
        __syncthreads();
        if (kt + 1 < SEQ / 64) { issue_tile(kt + 1); CP_COMMIT(); }

        const uint32_t kvb = sb + ABUF + (uint32_t)(kt & 1) * 18432u + bpat;

        float s[8][4];
#pragma unroll
        for (int fn = 0; fn < 8; fn++)
#pragma unroll
            for (int e = 0; e < 4; e++) s[fn][e] = 0.f;

#pragma unroll
        for (int ks = 0; ks < 4; ks++) {
            uint32_t qh[4];
            LDSM4(qh, qbase + ks * 32);
            uint32_t kh[4][4];
#pragma unroll
            for (int p = 0; p < 4; p++)
                LDSM4(kh[p], kvb + p * (16 * AROWB) + ks * 32);
#pragma unroll
            for (int fn = 0; fn < 8; fn++) {
                const int p = fn >> 1, o2 = (fn & 1) << 1;
                MMA16816(s[fn], qh, kh[p][o2], kh[p][o2 + 1]);
            }
        }

        float mx1 = -1e30f, mx2 = -1e30f;
#pragma unroll
        for (int fn = 0; fn < 8; fn++) {
            mx1 = fmaxf(mx1, fmaxf(s[fn][0], s[fn][1]));
            mx2 = fmaxf(mx2, fmaxf(s[fn][2], s[fn][3]));
        }
        mx1 = fmaxf(mx1, __shfl_xor_sync(0xffffffffu, mx1, 1));
        mx1 = fmaxf(mx1, __shfl_xor_sync(0xffffffffu, mx1, 2));
        mx2 = fmaxf(mx2, __shfl_xor_sync(0xffffffffu, mx2, 1));
        mx2 = fmaxf(mx2, __shfl_xor_sync(0xffffffffu, mx2, 2));

        float mn1 = fmaxf(m1, mx1), mn2 = fmaxf(m2, mx2);
        float c1 = ex2(m1 - mn1), c2 = ex2(m2 - mn2);
        m1 = mn1; m2 = mn2;

        float rs1 = 0.f, rs2 = 0.f;
#pragma unroll
        for (int fn = 0; fn < 8; fn++) {
            s[fn][0] = ex2(s[fn][0] - m1);
            s[fn][1] = ex2(s[fn][1] - m1);
            s[fn][2] = ex2(s[fn][2] - m2);
            s[fn][3] = ex2(s[fn][3] - m2);
            rs1 += s[fn][0] + s[fn][1];
            rs2 += s[fn][2] + s[fn][3];
        }
        rs1 += __shfl_xor_sync(0xffffffffu, rs1, 1);
        rs1 += __shfl_xor_sync(0xffffffffu, rs1, 2);
        rs2 += __shfl_xor_sync(0xffffffffu, rs2, 1);
        rs2 += __shfl_xor_sync(0xffffffffu, rs2, 2);
        l1 = l1 * c1 + rs1;
        l2 = l2 * c2 + rs2;
#pragma unroll
        for (int fn = 0; fn < 8; fn++) {
            o[fn][0] *= c1; o[fn][1] *= c1;
            o[fn][2] *= c2; o[fn][3] *= c2;
        }

#pragma unroll
        for (int ks = 0; ks < 4; ks++) {
            uint32_t pah[4];
            pah[0] = pack_h(s[2 * ks][0],     s[2 * ks][1]);
            pah[1] = pack_h(s[2 * ks][2],     s[2 * ks][3]);
            pah[2] = pack_h(s[2 * ks + 1][0], s[2 * ks + 1][1]);
            pah[3] = pack_h(s[2 * ks + 1][2], s[2 * ks + 1][3]);
            uint32_t vh[4][4];
#pragma unroll
            for (int p = 0; p < 4; p++)
                LDSM4(vh[p], kvb + 9216 + p * (16 * AROWB) + ks * 32);
#pragma unroll
            for (int fn = 0; fn < 8; fn++) {
                const int p = fn >> 1, o2 = (fn & 1) << 1;
                MMA16816(o[fn], pah, vh[p][o2], vh[p][o2 + 1]);
            }
        }
    }

    float inv1 = 1.f / l1, inv2 = 1.f / l2;
    int qr1 = wid * 16 + (lid >> 2);
    int qr2 = qr1 + 8;
#pragma unroll
    for (int fn = 0; fn < 8; fn++) {
        int col = fn * 8 + (lid & 3) * 2;
        *(float2*)(Op + qr1 * DEPTH + col) =
            make_float2(o[fn][0] * inv1, o[fn][1] * inv1);
        *(float2*)(Op + qr2 * DEPTH + col) =
            make_float2(o[fn][2] * inv2, o[fn][3] * inv2);
    }
}

// ---------------------------------------------------------------------------
extern "C" void kernel_launch(void* const* d_in, const int* in_sizes, int n_in,
                              void* d_out, int out_size)
{
    const float* q  = (const float*)d_in[0];
    const float* k  = (const float*)d_in[1];
    const float* v  = (const float*)d_in[2];
    const float* wq = (const float*)d_in[3];
    const float* bq = (const float*)d_in[4];
    const float* wk = (const float*)d_in[5];
    const float* bk = (const float*)d_in[6];
    const float* wv = (const float*)d_in[7];
    const float* bv = (const float*)d_in[8];
    const float* wo = (const float*)d_in[9];
    const float* bo = (const float*)d_in[10];
    float* out = (float*)d_out;

    __half *gQ1, *gK1, *gV1;
    float *gO;
    cudaGetSymbolAddress((void**)&gQ1, g_Q1);
    cudaGetSymbolAddress((void**)&gK1, g_K1);
    cudaGetSymbolAddress((void**)&gV1, g_VT1);
    cudaGetSymbolAddress((void**)&gO,  g_O);

    cudaFuncSetAttribute(gemm_mma<false, 2>,
                         cudaFuncAttributeMaxDynamicSharedMemorySize, GEMM_SMEM);
    cudaFuncSetAttribute(gemm_mma<false, 3>,
                         cudaFuncAttributeMaxDynamicSharedMemorySize, GEMM_SMEM);
    cudaFuncSetAttribute(gemm_mma<true, 0>,
                         cudaFuncAttributeMaxDynamicSharedMemorySize, GEMM_SMEM);
    cudaFuncSetAttribute(attn_mma,
                         cudaFuncAttributeMaxDynamicSharedMemorySize, ATT_SMEM);

    dim3 gproj(MTOT / 128, DM / 128);  // (32, 8)

    gemm_mma<false, 2><<<gproj, 256, GEMM_SMEM>>>(q, wq, bq, nullptr,
                                                  gQ1, QSCALE);
    gemm_mma<false, 2><<<gproj, 256, GEMM_SMEM>>>(k, wk, bk, nullptr,
                                                  gK1, 1.0f);
    gemm_mma<false, 3><<<gproj, 256, GEMM_SMEM>>>(v, wv, bv, nullptr,
                                                  gV1, 1.0f);

    attn_mma<<<dim3(SEQ / 128, NH, BATCH), 256, ATT_SMEM>>>(gQ1, gK1, gV1, gO);

    gemm_mma<true, 0><<<gproj, 256, GEMM_SMEM>>>(gO, wo, bo, out,
                                                 nullptr, 1.0f);
}

// round 14
// speedup vs baseline: 2.3410x; 1.0639x over previous
#include <cuda_runtime.h>
#include <cuda_fp16.h>
#include <cstdint>
#include <math.h>

#define BATCH 2
#define SEQ   2048
#define DM    1024
#define NH    16
#define DEPTH 64
#define MTOT  (BATCH*SEQ)   // 4096

#define QSCALE 0.1803368801111204f   // 0.125 * log2(e): scores in log2 domain

// Pre-converted fp16 scratch
__device__ __half g_in16[3*MTOT*DM];          // q,k,v flat [M,K] fp16
__device__ __half g_w16 [4*DM*DM];            // wq,wk,wv,wo fp16
__device__ __half g_Q1 [BATCH*NH*SEQ*DEPTH];  // [B,H,S,D], pre-scaled
__device__ __half g_K1 [BATCH*NH*SEQ*DEPTH];  // [B,H,S,D]
__device__ __half g_VT1[BATCH*NH*DEPTH*SEQ];  // [B,H,D,S]
__device__ __half g_O16[BATCH*NH*SEQ*DEPTH];  // attn out fp16 [B,H,S,D]

// ===========================================================================
// helpers
// ===========================================================================
__device__ __forceinline__ uint32_t smem_u32(const void* p) {
    uint32_t a;
    asm("{ .reg .u64 t; cvta.to.shared.u64 t, %1; cvt.u32.u64 %0, t; }"
        : "=r"(a) : "l"(p));
    return a;
}
__device__ __forceinline__ uint32_t pack_h(float x, float y) {
    __half2 h = __floats2half2_rn(x, y);
    return *(uint32_t*)&h;
}
__device__ __forceinline__ float ex2(float x) {
    float y; asm("ex2.approx.ftz.f32 %0, %1;" : "=f"(y) : "f"(x)); return y;
}

#define LDSM4(R, addr) \
    asm volatile("ldmatrix.sync.aligned.m8n8.x4.shared.b16 {%0,%1,%2,%3}, [%4];" \
        : "=r"((R)[0]), "=r"((R)[1]), "=r"((R)[2]), "=r"((R)[3]) : "r"(addr))

#define MMA16816(D, A, B0, B1) \
    asm volatile("mma.sync.aligned.m16n8k16.row.col.f32.f16.f16.f32 " \
        "{%0,%1,%2,%3}, {%4,%5,%6,%7}, {%8,%9}, {%0,%1,%2,%3};" \
        : "+f"((D)[0]), "+f"((D)[1]), "+f"((D)[2]), "+f"((D)[3]) \
        : "r"((A)[0]), "r"((A)[1]), "r"((A)[2]), "r"((A)[3]), "r"(B0), "r"(B1))

#define CP16(dst, src) \
    asm volatile("cp.async.cg.shared.global [%0], [%1], 16;" \
        :: "r"(dst), "l"(src) : "memory")
#define CP_COMMIT()  asm volatile("cp.async.commit_group;" ::: "memory")
#define CP_WAIT0()   asm volatile("cp.async.wait_group 0;" ::: "memory")

// ===========================================================================
// Pre-convert: fp32 -> fp16 (grid-stride over float4)
// ===========================================================================
__global__ __launch_bounds__(256)
void tofp16(const float* __restrict__ src, __half* __restrict__ dst, int n4)
{
    int i = blockIdx.x * 256 + threadIdx.x;
    if (i < n4) {
        float4 v = ((const float4*)src)[i];
        ((uint2*)dst)[i] = make_uint2(pack_h(v.x, v.y), pack_h(v.z, v.w));
    }
}

// ===========================================================================
// Pure-fp16 GEMM: C = A @ W.T (+bias,*scale). A, W pre-converted fp16.
// cp.async 16B chunks straight into ldmatrix layout (80B rows, 4 thr/row),
// double-buffered, ONE barrier/iter. CTA 128x128, BK=32, 8 warps (2m x 4n).
// OMODE: 0 fp32 [M,N]; 2 fp16 [B,H,S,D]; 3 fp16 [B,H,D,S] transposed.
// ===========================================================================
#define ROWB 80
#define GMAT 10240                     // 128 rows x 80B
#define OFF_W 20480                    // W buffers: 20480 + (it&1)*10240
#define GEMM_SMEM 40960                // tiny -> 2 CTAs/SM (reg-bound)

template<bool GATHER_A, int OMODE>
__global__ __launch_bounds__(256, 2)
void gemm_h(const __half* __restrict__ A, const __half* __restrict__ W,
            const float* __restrict__ bias, float* __restrict__ C32,
            __half* __restrict__ Ch, float scale)
{
    extern __shared__ char smem[];
    const uint32_t sb = smem_u32(smem);

    const int tid = threadIdx.x;
    const int wid = tid >> 5, lid = tid & 31;
    const int warp_m = wid >> 2;
    const int warp_n = wid & 3;
    const int bm = blockIdx.x * 128, bn = blockIdx.y * 128;

    const int grp = lid >> 3, r = lid & 7;
    const uint32_t apat = (uint32_t)(warp_m * 64 + ((grp & 1) << 3) + r) * ROWB
                        + (uint32_t)(((grp >> 1) & 1) << 4);
    const uint32_t wpat = (uint32_t)(warp_n * 32 + (((grp >> 1) & 1) << 3) + r) * ROWB
                        + (uint32_t)((grp & 1) << 4);

    // load coords: 4 threads per 64B row (coalesced 64B segments)
    auto issue_tile = [&](int it) {
        const int k0 = it * 32;
        const uint32_t abuf = sb + (uint32_t)(it & 1) * (uint32_t)GMAT;
        const uint32_t wbuf = sb + OFF_W + (uint32_t)(it & 1) * (uint32_t)GMAT;
#pragma unroll
        for (int l = 0; l < 2; l++) {
            int idx = tid + l * 256;       // 0..511
            int row = idx >> 2;            // 0..127
            int ch  = idx & 3;             // 16B chunk (8 fp16)
            uint32_t doff = (uint32_t)row * ROWB + (uint32_t)ch * 16;
            const __half* srcA;
            if (GATHER_A) {
                int m = bm + row;
                int b = m >> 11, s = m & 2047;
                int h = it >> 1, dl = ((it & 1) << 5) + ch * 8;
                srcA = A + ((((b << 4) + h) * SEQ + s) << 6) + dl;
            } else {
                srcA = A + (size_t)(bm + row) * DM + k0 + ch * 8;
            }
            CP16(abuf + doff, srcA);
            CP16(wbuf + doff, W + (size_t)(bn + row) * DM + k0 + ch * 8);
        }
    };

    float acc[4][4][4];
#pragma unroll
    for (int i = 0; i < 4; i++)
#pragma unroll
        for (int j = 0; j < 4; j++)
#pragma unroll
            for (int e = 0; e < 4; e++) acc[i][j][e] = 0.f;

    issue_tile(0);
    CP_COMMIT();

    for (int it = 0; it < DM / 32; it++) {
        CP_WAIT0();
        __syncthreads();   // buf[it&1] landed; prev-iter LDSM of other buf done
        if (it + 1 < DM / 32) { issue_tile(it + 1); CP_COMMIT(); }

        const uint32_t abuf = sb + (uint32_t)(it & 1) * (uint32_t)GMAT;
        const uint32_t wbuf = sb + OFF_W + (uint32_t)(it & 1) * (uint32_t)GMAT;
#pragma unroll
        for (int ks = 0; ks < 2; ks++) {
            const uint32_t offk = (uint32_t)ks * 32;
            uint32_t ah[4][4], bh[2][4];
#pragma unroll
            for (int fm = 0; fm < 4; fm++)
                LDSM4(ah[fm], abuf + apat + fm * (16 * ROWB) + offk);
#pragma unroll
            for (int p = 0; p < 2; p++)
                LDSM4(bh[p], wbuf + wpat + p * (16 * ROWB) + offk);
#pragma unroll
            for (int fm = 0; fm < 4; fm++)
#pragma unroll
                for (int fn = 0; fn < 4; fn++) {
                    const int p = fn >> 1, o = (fn & 1) << 1;
                    MMA16816(acc[fm][fn], ah[fm], bh[p][o], bh[p][o + 1]);
                }
        }
    }

    const int qrow = lid >> 2;
    const int qcol = (lid & 3) << 1;
#pragma unroll
    for (int fm = 0; fm < 4; fm++) {
        int m1 = bm + warp_m * 64 + fm * 16 + qrow;
        int m2 = m1 + 8;
#pragma unroll
        for (int fn = 0; fn < 4; fn++) {
            int n = bn + warp_n * 32 + fn * 8 + qcol;
            float2 bb = *(const float2*)(bias + n);
            float x1 = (acc[fm][fn][0] + bb.x) * scale;
            float y1 = (acc[fm][fn][1] + bb.y) * scale;
            float x2 = (acc[fm][fn][2] + bb.x) * scale;
            float y2 = (acc[fm][fn][3] + bb.y) * scale;
            if (OMODE == 0) {
                *(float2*)(C32 + (size_t)m1 * DM + n) = make_float2(x1, y1);
                *(float2*)(C32 + (size_t)m2 * DM + n) = make_float2(x2, y2);
            } else {
                int h = n >> 6, dl = n & 63;
                int b1 = m1 >> 11, s1 = m1 & 2047;
                int b2 = m2 >> 11, s2 = m2 & 2047;
                if (OMODE == 2) {          // fp16 [B,H,S,D]
                    size_t i1 = (size_t)((((b1 << 4) + h) * SEQ + s1) << 6) + dl;
                    size_t i2 = (size_t)((((b2 << 4) + h) * SEQ + s2) << 6) + dl;
                    *(uint32_t*)(Ch + i1) = pack_h(x1, y1);
                    *(uint32_t*)(Ch + i2) = pack_h(x2, y2);
                } else {                   // fp16 transposed [B,H,D,S]
                    size_t t1 = ((size_t)((b1 << 4) + h) * 64 + dl) * SEQ + s1;
                    size_t t2 = ((size_t)((b2 << 4) + h) * 64 + dl) * SEQ + s2;
                    Ch[t1] = __float2half_rn(x1);
                    Ch[t1 + SEQ] = __float2half_rn(y1);
                    Ch[t2] = __float2half_rn(x2);
                    Ch[t2 + SEQ] = __float2half_rn(y2);
                }
            }
        }
    }
}

// ===========================================================================
// fp16 flash attention (round-12/13 validated); epilogue emits fp16.
// ===========================================================================
#define AROWB 144
#define AQ1   0
#define ABUF  18432
#define ATT_SMEM (ABUF + 2 * 18432)   // 55296 -> 2 CTAs/SM

__global__ __launch_bounds__(256, 2)
void attn_mma(const __half* __restrict__ Q1, const __half* __restrict__ K1,
              const __half* __restrict__ VT1, __half* __restrict__ O)
{
    extern __shared__ char smem[];
    const uint32_t sb = smem_u32(smem);
    const int tid = threadIdx.x, wid = tid >> 5, lid = tid & 31;
    const int grp = lid >> 3, r = lid & 7;

    const int bh = blockIdx.z * NH + blockIdx.y;
    const int q0 = blockIdx.x * 128;
    const __half* Qp = Q1  + (size_t)(bh * SEQ + q0) * DEPTH;
    const __half* Kp = K1  + (size_t)bh * SEQ * DEPTH;
    const __half* Vp = VT1 + (size_t)bh * DEPTH * SEQ;
    __half* Op = O + (size_t)(bh * SEQ + q0) * DEPTH;

    const int crow = tid >> 3;
    const int cch  = tid & 7;

    auto issue_tile = [&](int kt) {
        const uint32_t buf = sb + ABUF + (uint32_t)(kt & 1) * 18432u;
        const int s0 = kt * 64;
#pragma unroll
        for (int l = 0; l < 4; l++) {
            int mat = l >> 1;
            int row = ((l & 1) << 5) + crow;
            uint32_t dst = buf + (uint32_t)mat * 9216u
                         + (uint32_t)row * AROWB + (uint32_t)cch * 16;
            const __half* src = (mat == 0)
                ? Kp + (size_t)(s0 + row) * DEPTH + cch * 8
                : Vp + (size_t)row * SEQ + s0 + cch * 8;
            CP16(dst, src);
        }
    };

#pragma unroll
    for (int l = 0; l < 4; l++) {
        int row = ((l & 3) << 5) + crow;
        uint32_t dst = sb + AQ1 + (uint32_t)row * AROWB + (uint32_t)cch * 16;
        CP16(dst, Qp + (size_t)row * DEPTH + cch * 8);
    }
    issue_tile(0);
    CP_COMMIT();

    const uint32_t qbase = sb + AQ1
        + (uint32_t)(wid * 16 + ((grp & 1) << 3) + r) * AROWB
        + (uint32_t)(((grp >> 1) & 1) << 4);
    const uint32_t bpat  = (uint32_t)(((grp & 2) << 2) + r) * AROWB
                         + (uint32_t)((grp & 1) << 4);

    float o[8][4];
#pragma unroll
    for (int fn = 0; fn < 8; fn++)
#pragma unroll
        for (int e = 0; e < 4; e++) o[fn][e] = 0.f;
    float m1 = -1e30f, m2 = -1e30f, l1 = 0.f, l2 = 0.f;

    for (int kt = 0; kt < SEQ / 64; kt++) {
        CP_WAIT0();
        __syncthreads();
        if (kt + 1 < SEQ / 64) { issue_tile(kt + 1); CP_COMMIT(); }

        const uint32_t kvb = sb + ABUF + (uint32_t)(kt & 1) * 18432u + bpat;

        float s[8][4];
#pragma unroll
        for (int fn = 0; fn < 8; fn++)
#pragma unroll
            for (int e = 0; e < 4; e++) s[fn][e] = 0.f;

#pragma unroll
        for (int ks = 0; ks < 4; ks++) {
            uint32_t qh[4];
            LDSM4(qh, qbase + ks * 32);
            uint32_t kh[4][4];
#pragma unroll
            for (int p = 0; p < 4; p++)
                LDSM4(kh[p], kvb + p * (16 * AROWB) + ks * 32);
#pragma unroll
            for (int fn = 0; fn < 8; fn++) {
                const int p = fn >> 1, o2 = (fn & 1) << 1;
                MMA16816(s[fn], qh, kh[p][o2], kh[p][o2 + 1]);
            }
        }

        float mx1 = -1e30f, mx2 = -1e30f;
#pragma unroll
        for (int fn = 0; fn < 8; fn++) {
            mx1 = fmaxf(mx1, fmaxf(s[fn][0], s[fn][1]));
            mx2 = fmaxf(mx2, fmaxf(s[fn][2], s[fn][3]));
        }
        mx1 = fmaxf(mx1, __shfl_xor_sync(0xffffffffu, mx1, 1));
        mx1 = fmaxf(mx1, __shfl_xor_sync(0xffffffffu, mx1, 2));
        mx2 = fmaxf(mx2, __shfl_xor_sync(0xffffffffu, mx2, 1));
        mx2 = fmaxf(mx2, __shfl_xor_sync(0xffffffffu, mx2, 2));

        float mn1 = fmaxf(m1, mx1), mn2 = fmaxf(m2, mx2);
        float c1 = ex2(m1 - mn1), c2 = ex2(m2 - mn2);
        m1 = mn1; m2 = mn2;

        float rs1 = 0.f, rs2 = 0.f;
#pragma unroll
        for (int fn = 0; fn < 8; fn++) {
            s[fn][0] = ex2(s[fn][0] - m1);
            s[fn][1] = ex2(s[fn][1] - m1);
            s[fn][2] = ex2(s[fn][2] - m2);
            s[fn][3] = ex2(s[fn][3] - m2);
            rs1 += s[fn][0] + s[fn][1];
            rs2 += s[fn][2] + s[fn][3];
        }
        rs1 += __shfl_xor_sync(0xffffffffu, rs1, 1);
        rs1 += __shfl_xor_sync(0xffffffffu, rs1, 2);
        rs2 += __shfl_xor_sync(0xffffffffu, rs2, 1);
        rs2 += __shfl_xor_sync(0xffffffffu, rs2, 2);
        l1 = l1 * c1 + rs1;
        l2 = l2 * c2 + rs2;
#pragma unroll
        for (int fn = 0; fn < 8; fn++) {
            o[fn][0] *= c1; o[fn][1] *= c1;
            o[fn][2] *= c2; o[fn][3] *= c2;
        }

#pragma unroll
        for (int ks = 0; ks < 4; ks++) {
            uint32_t pah[4];
            pah[0] = pack_h(s[2 * ks][0],     s[2 * ks][1]);
            pah[1] = pack_h(s[2 * ks][2],     s[2 * ks][3]);
            pah[2] = pack_h(s[2 * ks + 1][0], s[2 * ks + 1][1]);
            pah[3] = pack_h(s[2 * ks + 1][2], s[2 * ks + 1][3]);
            uint32_t vh[4][4];
#pragma unroll
            for (int p = 0; p < 4; p++)
                LDSM4(vh[p], kvb + 9216 + p * (16 * AROWB) + ks * 32);
#pragma unroll
            for (int fn = 0; fn < 8; fn++) {
                const int p = fn >> 1, o2 = (fn & 1) << 1;
                MMA16816(o[fn], pah, vh[p][o2], vh[p][o2 + 1]);
            }
        }
    }

    // ---- epilogue: normalize, store fp16 ----
    float inv1 = 1.f / l1, inv2 = 1.f / l2;
    int qr1 = wid * 16 + (lid >> 2);
    int qr2 = qr1 + 8;
#pragma unroll
    for (int fn = 0; fn < 8; fn++) {
        int col = fn * 8 + (lid & 3) * 2;
        *(uint32_t*)(Op + qr1 * DEPTH + col) =
            pack_h(o[fn][0] * inv1, o[fn][1] * inv1);
        *(uint32_t*)(Op + qr2 * DEPTH + col) =
            pack_h(o[fn][2] * inv2, o[fn][3] * inv2);
    }
}

// ---------------------------------------------------------------------------
extern "C" void kernel_launch(void* const* d_in, const int* in_sizes, int n_in,
                              void* d_out, int out_size)
{
    const float* q  = (const float*)d_in[0];
    const float* k  = (const float*)d_in[1];
    const float* v  = (const float*)d_in[2];
    const float* wq = (const float*)d_in[3];
    const float* bq = (const float*)d_in[4];
    const float* wk = (const float*)d_in[5];
    const float* bk = (const float*)d_in[6];
    const float* wv = (const float*)d_in[7];
    const float* bv = (const float*)d_in[8];
    const float* wo = (const float*)d_in[9];
    const float* bo = (const float*)d_in[10];
    float* out = (float*)d_out;

    __half *gI, *gW, *gQ1, *gK1, *gV1, *gO16;
    cudaGetSymbolAddress((void**)&gI,   g_in16);
    cudaGetSymbolAddress((void**)&gW,   g_w16);
    cudaGetSymbolAddress((void**)&gQ1,  g_Q1);
    cudaGetSymbolAddress((void**)&gK1,  g_K1);
    cudaGetSymbolAddress((void**)&gV1,  g_VT1);
    cudaGetSymbolAddress((void**)&gO16, g_O16);

    cudaFuncSetAttribute(gemm_h<false, 2>,
                         cudaFuncAttributeMaxDynamicSharedMemorySize, GEMM_SMEM);
    cudaFuncSetAttribute(gemm_h<false, 3>,
                         cudaFuncAttributeMaxDynamicSharedMemorySize, GEMM_SMEM);
    cudaFuncSetAttribute(gemm_h<true, 0>,
                         cudaFuncAttributeMaxDynamicSharedMemorySize, GEMM_SMEM);
    cudaFuncSetAttribute(attn_mma,
                         cudaFuncAttributeMaxDynamicSharedMemorySize, ATT_SMEM);

    // Pre-convert inputs + weights to fp16
    const int NIN = MTOT * DM / 4;   // 1M float4
    const int NW  = DM * DM / 4;     // 256K float4
    tofp16<<<NIN / 256, 256>>>(q, gI,               NIN);
    tofp16<<<NIN / 256, 256>>>(k, gI + MTOT*DM,     NIN);
    tofp16<<<NIN / 256, 256>>>(v, gI + 2*MTOT*DM,   NIN);
    tofp16<<<NW / 256, 256>>>(wq, gW,               NW);
    tofp16<<<NW / 256, 256>>>(wk, gW + DM*DM,       NW);
    tofp16<<<NW / 256, 256>>>(wv, gW + 2*DM*DM,     NW);
    tofp16<<<NW / 256, 256>>>(wo, gW + 3*DM*DM,     NW);

    dim3 gproj(MTOT / 128, DM / 128);  // (32, 8)

    gemm_h<false, 2><<<gproj, 256, GEMM_SMEM>>>(gI, gW, bq, nullptr,
                                                gQ1, QSCALE);
    gemm_h<false, 2><<<gproj, 256, GEMM_SMEM>>>(gI + MTOT*DM, gW + DM*DM, bk,
                                                nullptr, gK1, 1.0f);
    gemm_h<false, 3><<<gproj, 256, GEMM_SMEM>>>(gI + 2*MTOT*DM, gW + 2*DM*DM,
                                                bv, nullptr, gV1, 1.0f);

    attn_mma<<<dim3(SEQ / 128, NH, BATCH), 256, ATT_SMEM>>>(gQ1, gK1, gV1,
                                                            gO16);

    gemm_h<true, 0><<<gproj, 256, GEMM_SMEM>>>(gO16, gW + 3*DM*DM, bo, out,
                                               nullptr, 1.0f);
}

// round 15
// speedup vs baseline: 2.5147x; 1.0742x over previous
#include <cuda_runtime.h>
#include <cuda_fp16.h>
#include <cstdint>
#include <math.h>

#define BATCH 2
#define SEQ   2048
#define DM    1024
#define NH    16
#define DEPTH 64
#define MTOT  (BATCH*SEQ)   // 4096

#define QSCALE 0.1803368801111204f   // 0.125 * log2(e): scores in log2 domain

// Pre-converted fp16 scratch
__device__ __half g_in16[3*MTOT*DM];          // q,k,v flat [M,K] fp16
__device__ __half g_w16 [4*DM*DM];            // wq,wk,wv,wo fp16
__device__ __half g_Q1 [BATCH*NH*SEQ*DEPTH];  // [B,H,S,D], pre-scaled
__device__ __half g_K1 [BATCH*NH*SEQ*DEPTH];  // [B,H,S,D]
__device__ __half g_VT1[BATCH*NH*DEPTH*SEQ];  // [B,H,D,S]
__device__ __half g_O16[BATCH*NH*SEQ*DEPTH];  // attn out fp16 [B,H,S,D]

// ===========================================================================
// helpers
// ===========================================================================
__device__ __forceinline__ uint32_t smem_u32(const void* p) {
    uint32_t a;
    asm("{ .reg .u64 t; cvta.to.shared.u64 t, %1; cvt.u32.u64 %0, t; }"
        : "=r"(a) : "l"(p));
    return a;
}
__device__ __forceinline__ uint32_t pack_h(float x, float y) {
    __half2 h = __floats2half2_rn(x, y);
    return *(uint32_t*)&h;
}
__device__ __forceinline__ float ex2(float x) {
    float y; asm("ex2.approx.ftz.f32 %0, %1;" : "=f"(y) : "f"(x)); return y;
}

#define LDSM4(R, addr) \
    asm volatile("ldmatrix.sync.aligned.m8n8.x4.shared.b16 {%0,%1,%2,%3}, [%4];" \
        : "=r"((R)[0]), "=r"((R)[1]), "=r"((R)[2]), "=r"((R)[3]) : "r"(addr))

#define MMA16816(D, A, B0, B1) \
    asm volatile("mma.sync.aligned.m16n8k16.row.col.f32.f16.f16.f32 " \
        "{%0,%1,%2,%3}, {%4,%5,%6,%7}, {%8,%9}, {%0,%1,%2,%3};" \
        : "+f"((D)[0]), "+f"((D)[1]), "+f"((D)[2]), "+f"((D)[3]) \
        : "r"((A)[0]), "r"((A)[1]), "r"((A)[2]), "r"((A)[3]), "r"(B0), "r"(B1))

#define CP16(dst, src) \
    asm volatile("cp.async.cg.shared.global [%0], [%1], 16;" \
        :: "r"(dst), "l"(src) : "memory")
#define CP_COMMIT()  asm volatile("cp.async.commit_group;" ::: "memory")
#define CP_WAIT0()   asm volatile("cp.async.wait_group 0;" ::: "memory")

// ===========================================================================
// Pre-convert: fp32 -> fp16, z-batched (grid.z selects source)
// ===========================================================================
__global__ __launch_bounds__(256)
void tofp16_z(const float* __restrict__ s0, const float* __restrict__ s1,
              const float* __restrict__ s2, const float* __restrict__ s3,
              __half* __restrict__ dst, int n4each)
{
    const float* src = (blockIdx.z == 0) ? s0 : (blockIdx.z == 1) ? s1
                     : (blockIdx.z == 2) ? s2 : s3;
    int i = blockIdx.x * 256 + threadIdx.x;
    if (i < n4each) {
        float4 v = ((const float4*)src)[i];
        ((uint2*)dst)[(size_t)blockIdx.z * n4each + i] =
            make_uint2(pack_h(v.x, v.y), pack_h(v.z, v.w));
    }
}

// ===========================================================================
// Pure-fp16 GEMM, BK=64: C = A @ W.T (+bias,*scale). 16 K-iterations.
// cp.async raw fp16 into ldmatrix layout (144B row stride, 128B data/row),
// double-buffered, ONE barrier/iter; 64 MMA + 24 LDSM per warp-iter.
// CTA 128x128, 8 warps (2m x 4n), 2 CTAs/SM.
// OMODE: 0 fp32 [M,N]; 2 fp16 [B,H,S,D]; 3 fp16 [B,H,D,S] transposed.
// ===========================================================================
#define GROWB 144
#define GMAT  18432                    // 128 rows x 144B
#define GBUF  36864                    // A + W per buffer
#define GEMM_SMEM (2 * GBUF)           // 73728 -> 2 CTAs/SM

template<bool GATHER_A, int OMODE>
__global__ __launch_bounds__(256, 2)
void gemm_h(const __half* __restrict__ A, const __half* __restrict__ W,
            const float* __restrict__ bias, float* __restrict__ C32,
            __half* __restrict__ Ch, float scale)
{
    extern __shared__ char smem[];
    const uint32_t sb = smem_u32(smem);

    const int tid = threadIdx.x;
    const int wid = tid >> 5, lid = tid & 31;
    const int warp_m = wid >> 2;
    const int warp_n = wid & 3;
    const int bm = blockIdx.x * 128, bn = blockIdx.y * 128;

    const int grp = lid >> 3, r = lid & 7;
    const uint32_t apat = (uint32_t)(warp_m * 64 + ((grp & 1) << 3) + r) * GROWB
                        + (uint32_t)(((grp >> 1) & 1) << 4);
    const uint32_t wpat = (uint32_t)(warp_n * 32 + (((grp >> 1) & 1) << 3) + r) * GROWB
                        + (uint32_t)((grp & 1) << 4);

    const int crow = tid >> 3;     // 0..31
    const int cch  = tid & 7;      // 16B chunk (8 fp16) within 128B row

    auto issue_tile = [&](int it) {
        const int k0 = it * 64;
        const uint32_t buf = sb + (uint32_t)(it & 1) * (uint32_t)GBUF;
        // 2 mats x 128 rows x 8 chunks = 2048 chunks; 8 per thread
#pragma unroll
        for (int l = 0; l < 8; l++) {
            int mat = l >> 2;                   // 0 A, 1 W
            int row = ((l & 3) << 5) + crow;    // 0..127
            uint32_t dst = buf + (uint32_t)mat * (uint32_t)GMAT
                         + (uint32_t)row * GROWB + (uint32_t)cch * 16;
            const __half* src;
            if (mat == 0) {
                if (GATHER_A) {
                    int m = bm + row;
                    int b = m >> 11, s = m & 2047;
                    // k0 = it*64 => head = it, d = cch*8
                    src = A + ((((b << 4) + it) * SEQ + s) << 6) + cch * 8;
                } else {
                    src = A + (size_t)(bm + row) * DM + k0 + cch * 8;
                }
            } else {
                src = W + (size_t)(bn + row) * DM + k0 + cch * 8;
            }
            CP16(dst, src);
        }
    };

    float acc[4][4][4];
#pragma unroll
    for (int i = 0; i < 4; i++)
#pragma unroll
        for (int j = 0; j < 4; j++)
#pragma unroll
            for (int e = 0; e < 4; e++) acc[i][j][e] = 0.f;

    issue_tile(0);
    CP_COMMIT();

    for (int it = 0; it < DM / 64; it++) {
        CP_WAIT0();
        __syncthreads();   // buf[it&1] landed; prev-iter LDSM done
        if (it + 1 < DM / 64) { issue_tile(it + 1); CP_COMMIT(); }

        const uint32_t abuf = sb + (uint32_t)(it & 1) * (uint32_t)GBUF;
        const uint32_t wbuf = abuf + GMAT;
#pragma unroll
        for (int ks = 0; ks < 4; ks++) {
            const uint32_t offk = (uint32_t)ks * 32;
            uint32_t ah[4][4], bh[2][4];
#pragma unroll
            for (int fm = 0; fm < 4; fm++)
                LDSM4(ah[fm], abuf + apat + fm * (16 * GROWB) + offk);
#pragma unroll
            for (int p = 0; p < 2; p++)
                LDSM4(bh[p], wbuf + wpat + p * (16 * GROWB) + offk);
#pragma unroll
            for (int fm = 0; fm < 4; fm++)
#pragma unroll
                for (int fn = 0; fn < 4; fn++) {
                    const int p = fn >> 1, o = (fn & 1) << 1;
                    MMA16816(acc[fm][fn], ah[fm], bh[p][o], bh[p][o + 1]);
                }
        }
    }

    const int qrow = lid >> 2;
    const int qcol = (lid & 3) << 1;
#pragma unroll
    for (int fm = 0; fm < 4; fm++) {
        int m1 = bm + warp_m * 64 + fm * 16 + qrow;
        int m2 = m1 + 8;
#pragma unroll
        for (int fn = 0; fn < 4; fn++) {
            int n = bn + warp_n * 32 + fn * 8 + qcol;
            float2 bb = *(const float2*)(bias + n);
            float x1 = (acc[fm][fn][0] + bb.x) * scale;
            float y1 = (acc[fm][fn][1] + bb.y) * scale;
            float x2 = (acc[fm][fn][2] + bb.x) * scale;
            float y2 = (acc[fm][fn][3] + bb.y) * scale;
            if (OMODE == 0) {
                *(float2*)(C32 + (size_t)m1 * DM + n) = make_float2(x1, y1);
                *(float2*)(C32 + (size_t)m2 * DM + n) = make_float2(x2, y2);
            } else {
                int h = n >> 6, dl = n & 63;
                int b1 = m1 >> 11, s1 = m1 & 2047;
                int b2 = m2 >> 11, s2 = m2 & 2047;
                if (OMODE == 2) {          // fp16 [B,H,S,D]
                    size_t i1 = (size_t)((((b1 << 4) + h) * SEQ + s1) << 6) + dl;
                    size_t i2 = (size_t)((((b2 << 4) + h) * SEQ + s2) << 6) + dl;
                    *(uint32_t*)(Ch + i1) = pack_h(x1, y1);
                    *(uint32_t*)(Ch + i2) = pack_h(x2, y2);
                } else {                   // fp16 transposed [B,H,D,S]
                    size_t t1 = ((size_t)((b1 << 4) + h) * 64 + dl) * SEQ + s1;
                    size_t t2 = ((size_t)((b2 << 4) + h) * 64 + dl) * SEQ + s2;
                    Ch[t1] = __float2half_rn(x1);
                    Ch[t1 + SEQ] = __float2half_rn(y1);
                    Ch[t2] = __float2half_rn(x2);
                    Ch[t2 + SEQ] = __float2half_rn(y2);
                }
            }
        }
    }
}

// ===========================================================================
// fp16 flash attention — round-14 kernel verbatim (validated 122us).
// ===========================================================================
#define AROWB 144
#define AQ1   0
#define ABUF  18432
#define ATT_SMEM (ABUF + 2 * 18432)   // 55296 -> 2 CTAs/SM

__global__ __launch_bounds__(256, 2)
void attn_mma(const __half* __restrict__ Q1, const __half* __restrict__ K1,
              const __half* __restrict__ VT1, __half* __restrict__ O)
{
    extern __shared__ char smem[];
    const uint32_t sb = smem_u32(smem);
    const int tid = threadIdx.x, wid = tid >> 5, lid = tid & 31;
    const int grp = lid >> 3, r = lid & 7;

    const int bh = blockIdx.z * NH + blockIdx.y;
    const int q0 = blockIdx.x * 128;
    const __half* Qp = Q1  + (size_t)(bh * SEQ + q0) * DEPTH;
    const __half* Kp = K1  + (size_t)bh * SEQ * DEPTH;
    const __half* Vp = VT1 + (size_t)bh * DEPTH * SEQ;
    __half* Op = O + (size_t)(bh * SEQ + q0) * DEPTH;

    const int crow = tid >> 3;
    const int cch  = tid & 7;

    auto issue_tile = [&](int kt) {
        const uint32_t buf = sb + ABUF + (uint32_t)(kt & 1) * 18432u;
        const int s0 = kt * 64;
#pragma unroll
        for (int l = 0; l < 4; l++) {
            int mat = l >> 1;
            int row = ((l & 1) << 5) + crow;
            uint32_t dst = buf + (uint32_t)mat * 9216u
                         + (uint32_t)row * AROWB + (uint32_t)cch * 16;
            const __half* src = (mat == 0)
                ? Kp + (size_t)(s0 + row) * DEPTH + cch * 8
                : Vp + (size_t)row * SEQ + s0 + cch * 8;
            CP16(dst, src);
        }
    };

#pragma unroll
    for (int l = 0; l < 4; l++) {
        int row = ((l & 3) << 5) + crow;
        uint32_t dst = sb + AQ1 + (uint32_t)row * AROWB + (uint32_t)cch * 16;
        CP16(dst, Qp + (size_t)row * DEPTH + cch * 8);
    }
    issue_tile(0);
    CP_COMMIT();

    const uint32_t qbase = sb + AQ1
        + (uint32_t)(wid * 16 + ((grp & 1) << 3) + r) * AROWB
        + (uint32_t)(((grp >> 1) & 1) << 4);
    const uint32_t bpat  = (uint32_t)(((grp & 2) << 2) + r) * AROWB
                         + (uint32_t)((grp & 1) << 4);

    float o[8][4];
#pragma unroll
    for (int fn = 0; fn < 8; fn++)
#pragma unroll
        for (int e = 0; e < 4; e++) o[fn][e] = 0.f;
    float m1 = -1e30f, m2 = -1e30f, l1 = 0.f, l2 = 0.f;

    for (int kt = 0; kt < SEQ / 64; kt++) {
        CP_WAIT0();
        __syncthreads();
        if (kt + 1 < SEQ / 64) { issue_tile(kt + 1); CP_COMMIT(); }

        const uint32_t kvb = sb + ABUF + (uint32_t)(kt & 1) * 18432u + bpat;

        float s[8][4];
#pragma unroll
        for (int fn = 0; fn < 8; fn++)
#pragma unroll
            for (int e = 0; e < 4; e++) s[fn][e] = 0.f;

#pragma unroll
        for (int ks = 0; ks < 4; ks++) {
            uint32_t qh[4];
            LDSM4(qh, qbase + ks * 32);
            uint32_t kh[4][4];
#pragma unroll
            for (int p = 0; p < 4; p++)
                LDSM4(kh[p], kvb + p * (16 * AROWB) + ks * 32);
#pragma unroll
            for (int fn = 0; fn < 8; fn++) {
                const int p = fn >> 1, o2 = (fn & 1) << 1;
                MMA16816(s[fn], qh, kh[p][o2], kh[p][o2 + 1]);
            }
        }

        float mx1 = -1e30f, mx2 = -1e30f;
#pragma unroll
        for (int fn = 0; fn < 8; fn++) {
            mx1 = fmaxf(mx1, fmaxf(s[fn][0], s[fn][1]));
            mx2 = fmaxf(mx2, fmaxf(s[fn][2], s[fn][3]));
        }
        mx1 = fmaxf(mx1, __shfl_xor_sync(0xffffffffu, mx1, 1));
        mx1 = fmaxf(mx1, __shfl_xor_sync(0xffffffffu, mx1, 2));
        mx2 = fmaxf(mx2, __shfl_xor_sync(0xffffffffu, mx2, 1));
        mx2 = fmaxf(mx2, __shfl_xor_sync(0xffffffffu, mx2, 2));

        float mn1 = fmaxf(m1, mx1), mn2 = fmaxf(m2, mx2);
        float c1 = ex2(m1 - mn1), c2 = ex2(m2 - mn2);
        m1 = mn1; m2 = mn2;

        float rs1 = 0.f, rs2 = 0.f;
#pragma unroll
        for (int fn = 0; fn < 8; fn++) {
            s[fn][0] = ex2(s[fn][0] - m1);
            s[fn][1] = ex2(s[fn][1] - m1);
            s[fn][2] = ex2(s[fn][2] - m2);
            s[fn][3] = ex2(s[fn][3] - m2);
            rs1 += s[fn][0] + s[fn][1];
            rs2 += s[fn][2] + s[fn][3];
        }
        rs1 += __shfl_xor_sync(0xffffffffu, rs1, 1);
        rs1 += __shfl_xor_sync(0xffffffffu, rs1, 2);
        rs2 += __shfl_xor_sync(0xffffffffu, rs2, 1);
        rs2 += __shfl_xor_sync(0xffffffffu, rs2, 2);
        l1 = l1 * c1 + rs1;
        l2 = l2 * c2 + rs2;
#pragma unroll
        for (int fn = 0; fn < 8; fn++) {
            o[fn][0] *= c1; o[fn][1] *= c1;
            o[fn][2] *= c2; o[fn][3] *= c2;
        }

#pragma unroll
        for (int ks = 0; ks < 4; ks++) {
            uint32_t pah[4];
            pah[0] = pack_h(s[2 * ks][0],     s[2 * ks][1]);
            pah[1] = pack_h(s[2 * ks][2],     s[2 * ks][3]);
            pah[2] = pack_h(s[2 * ks + 1][0], s[2 * ks + 1][1]);
            pah[3] = pack_h(s[2 * ks + 1][2], s[2 * ks + 1][3]);
            uint32_t vh[4][4];
#pragma unroll
            for (int p = 0; p < 4; p++)
                LDSM4(vh[p], kvb + 9216 + p * (16 * AROWB) + ks * 32);
#pragma unroll
            for (int fn = 0; fn < 8; fn++) {
                const int p = fn >> 1, o2 = (fn & 1) << 1;
                MMA16816(o[fn], pah, vh[p][o2], vh[p][o2 + 1]);
            }
        }
    }

    float inv1 = 1.f / l1, inv2 = 1.f / l2;
    int qr1 = wid * 16 + (lid >> 2);
    int qr2 = qr1 + 8;
#pragma unroll
    for (int fn = 0; fn < 8; fn++) {
        int col = fn * 8 + (lid & 3) * 2;
        *(uint32_t*)(Op + qr1 * DEPTH + col) =
            pack_h(o[fn][0] * inv1, o[fn][1] * inv1);
        *(uint32_t*)(Op + qr2 * DEPTH + col) =
            pack_h(o[fn][2] * inv2, o[fn][3] * inv2);
    }
}

// ---------------------------------------------------------------------------
extern "C" void kernel_launch(void* const* d_in, const int* in_sizes, int n_in,
                              void* d_out, int out_size)
{
    const float* q  = (const float*)d_in[0];
    const float* k  = (const float*)d_in[1];
    const float* v  = (const float*)d_in[2];
    const float* wq = (const float*)d_in[3];
    const float* bq = (const float*)d_in[4];
    const float* wk = (const float*)d_in[5];
    const float* bk = (const float*)d_in[6];
    const float* wv = (const float*)d_in[7];
    const float* bv = (const float*)d_in[8];
    const float* wo = (const float*)d_in[9];
    const float* bo = (const float*)d_in[10];
    float* out = (float*)d_out;

    __half *gI, *gW, *gQ1, *gK1, *gV1, *gO16;
    cudaGetSymbolAddress((void**)&gI,   g_in16);
    cudaGetSymbolAddress((void**)&gW,   g_w16);
    cudaGetSymbolAddress((void**)&gQ1,  g_Q1);
    cudaGetSymbolAddress((void**)&gK1,  g_K1);
    cudaGetSymbolAddress((void**)&gV1,  g_VT1);
    cudaGetSymbolAddress((void**)&gO16, g_O16);

    cudaFuncSetAttribute(gemm_h<false, 2>,
                         cudaFuncAttributeMaxDynamicSharedMemorySize, GEMM_SMEM);
    cudaFuncSetAttribute(gemm_h<false, 3>,
                         cudaFuncAttributeMaxDynamicSharedMemorySize, GEMM_SMEM);
    cudaFuncSetAttribute(gemm_h<true, 0>,
                         cudaFuncAttributeMaxDynamicSharedMemorySize, GEMM_SMEM);
    cudaFuncSetAttribute(attn_mma,
                         cudaFuncAttributeMaxDynamicSharedMemorySize, ATT_SMEM);

    // Pre-convert: inputs (z=0..2) and weights (z=0..3), 2 launches
    const int NIN = MTOT * DM / 4;   // 1M float4 each
    const int NW  = DM * DM / 4;     // 256K float4 each
    tofp16_z<<<dim3(NIN / 256, 1, 3), 256>>>(q, k, v, nullptr, gI, NIN);
    tofp16_z<<<dim3(NW / 256, 1, 4), 256>>>(wq, wk, wv, wo, gW, NW);

    dim3 gproj(MTOT / 128, DM / 128);  // (32, 8)

    gemm_h<false, 2><<<gproj, 256, GEMM_SMEM>>>(gI, gW, bq, nullptr,
                                                gQ1, QSCALE);
    gemm_h<false, 2><<<gproj, 256, GEMM_SMEM>>>(gI + MTOT*DM, gW + DM*DM, bk,
                                                nullptr, gK1, 1.0f);
    gemm_h<false, 3><<<gproj, 256, GEMM_SMEM>>>(gI + 2*MTOT*DM, gW + 2*DM*DM,
                                                bv, nullptr, gV1, 1.0f);

    attn_mma<<<dim3(SEQ / 128, NH, BATCH), 256, ATT_SMEM>>>(gQ1, gK1, gV1,
                                                            gO16);

    gemm_h<true, 0><<<gproj, 256, GEMM_SMEM>>>(gO16, gW + 3*DM*DM, bo, out,
                                               nullptr, 1.0f);
}

// round 16
// speedup vs baseline: 2.5213x; 1.0026x over previous
#include <cuda_runtime.h>
#include <cuda_fp16.h>
#include <cstdint>
#include <math.h>

#define BATCH 2
#define SEQ   2048
#define DM    1024
#define NH    16
#define DEPTH 64
#define MTOT  (BATCH*SEQ)   // 4096

#define QSCALE 0.1803368801111204f   // 0.125 * log2(e): scores in log2 domain

// Pre-converted fp16 scratch
__device__ __half g_in16[3*MTOT*DM];          // q,k,v flat [M,K] fp16
__device__ __half g_w16 [4*DM*DM];            // wq,wk,wv,wo fp16
__device__ __half g_Q1 [BATCH*NH*SEQ*DEPTH];  // [B,H,S,D], pre-scaled
__device__ __half g_K1 [BATCH*NH*SEQ*DEPTH];  // [B,H,S,D]
__device__ __half g_VT1[BATCH*NH*DEPTH*SEQ];  // [B,H,D,S]
__device__ __half g_O16[BATCH*NH*SEQ*DEPTH];  // attn out fp16 [B,H,S,D]

// ===========================================================================
// helpers
// ===========================================================================
__device__ __forceinline__ uint32_t smem_u32(const void* p) {
    uint32_t a;
    asm("{ .reg .u64 t; cvta.to.shared.u64 t, %1; cvt.u32.u64 %0, t; }"
        : "=r"(a) : "l"(p));
    return a;
}
__device__ __forceinline__ uint32_t pack_h(float x, float y) {
    __half2 h = __floats2half2_rn(x, y);
    return *(uint32_t*)&h;
}
__device__ __forceinline__ float ex2(float x) {
    float y; asm("ex2.approx.ftz.f32 %0, %1;" : "=f"(y) : "f"(x)); return y;
}

#define LDSM4(R, addr) \
    asm volatile("ldmatrix.sync.aligned.m8n8.x4.shared.b16 {%0,%1,%2,%3}, [%4];" \
        : "=r"((R)[0]), "=r"((R)[1]), "=r"((R)[2]), "=r"((R)[3]) : "r"(addr))

#define MMA16816(D, A, B0, B1) \
    asm volatile("mma.sync.aligned.m16n8k16.row.col.f32.f16.f16.f32 " \
        "{%0,%1,%2,%3}, {%4,%5,%6,%7}, {%8,%9}, {%0,%1,%2,%3};" \
        : "+f"((D)[0]), "+f"((D)[1]), "+f"((D)[2]), "+f"((D)[3]) \
        : "r"((A)[0]), "r"((A)[1]), "r"((A)[2]), "r"((A)[3]), "r"(B0), "r"(B1))

#define CP16(dst, src) \
    asm volatile("cp.async.cg.shared.global [%0], [%1], 16;" \
        :: "r"(dst), "l"(src) : "memory")
#define CP_COMMIT()  asm volatile("cp.async.commit_group;" ::: "memory")
#define CP_WAIT1()   asm volatile("cp.async.wait_group 1;" ::: "memory")

// ===========================================================================
// Pre-convert: fp32 -> fp16, z-batched
// ===========================================================================
__global__ __launch_bounds__(256)
void tofp16_z(const float* __restrict__ s0, const float* __restrict__ s1,
              const float* __restrict__ s2, const float* __restrict__ s3,
              __half* __restrict__ dst, int n4each)
{
    const float* src = (blockIdx.z == 0) ? s0 : (blockIdx.z == 1) ? s1
                     : (blockIdx.z == 2) ? s2 : s3;
    int i = blockIdx.x * 256 + threadIdx.x;
    if (i < n4each) {
        float4 v = ((const float4*)src)[i];
        ((uint2*)dst)[(size_t)blockIdx.z * n4each + i] =
            make_uint2(pack_h(v.x, v.y), pack_h(v.z, v.w));
    }
}

// ===========================================================================
// Pure-fp16 GEMM, BK=64, 3-stage cp.async pipeline (wait_group 1).
// CTA 128x128, 8 warps (2m x 4n), 2 CTAs/SM.
// OMODE: 0 fp32 [M,N]; 2 fp16 [B,H,S,D]; 3 fp16 [B,H,D,S] transposed.
// ===========================================================================
#define GROWB 144
#define GMAT  18432                    // 128 rows x 144B
#define GBUF  36864                    // A + W per buffer
#define GEMM_SMEM (3 * GBUF)           // 110592 -> 2 CTAs/SM (216 KB)
#define GNIT  (DM / 64)                // 16

template<bool GATHER_A, int OMODE>
__global__ __launch_bounds__(256, 2)
void gemm_h(const __half* __restrict__ A, const __half* __restrict__ W,
            const float* __restrict__ bias, float* __restrict__ C32,
            __half* __restrict__ Ch, float scale)
{
    extern __shared__ char smem[];
    const uint32_t sb = smem_u32(smem);

    const int tid = threadIdx.x;
    const int wid = tid >> 5, lid = tid & 31;
    const int warp_m = wid >> 2;
    const int warp_n = wid & 3;
    const int bm = blockIdx.x * 128, bn = blockIdx.y * 128;

    const int grp = lid >> 3, r = lid & 7;
    const uint32_t apat = (uint32_t)(warp_m * 64 + ((grp & 1) << 3) + r) * GROWB
                        + (uint32_t)(((grp >> 1) & 1) << 4);
    const uint32_t wpat = (uint32_t)(warp_n * 32 + (((grp >> 1) & 1) << 3) + r) * GROWB
                        + (uint32_t)((grp & 1) << 4);

    const int crow = tid >> 3;     // 0..31
    const int cch  = tid & 7;      // 16B chunk within 128B row

    auto issue_tile = [&](int it) {
        const int k0 = it * 64;
        const uint32_t buf = sb + (uint32_t)(it % 3) * (uint32_t)GBUF;
#pragma unroll
        for (int l = 0; l < 8; l++) {
            int mat = l >> 2;                   // 0 A, 1 W
            int row = ((l & 3) << 5) + crow;    // 0..127
            uint32_t dst = buf + (uint32_t)mat * (uint32_t)GMAT
                         + (uint32_t)row * GROWB + (uint32_t)cch * 16;
            const __half* src;
            if (mat == 0) {
                if (GATHER_A) {
                    int m = bm + row;
                    int b = m >> 11, s = m & 2047;
                    src = A + ((((b << 4) + it) * SEQ + s) << 6) + cch * 8;
                } else {
                    src = A + (size_t)(bm + row) * DM + k0 + cch * 8;
                }
            } else {
                src = W + (size_t)(bn + row) * DM + k0 + cch * 8;
            }
            CP16(dst, src);
        }
    };

    float acc[4][4][4];
#pragma unroll
    for (int i = 0; i < 4; i++)
#pragma unroll
        for (int j = 0; j < 4; j++)
#pragma unroll
            for (int e = 0; e < 4; e++) acc[i][j][e] = 0.f;

    issue_tile(0);
    CP_COMMIT();
    issue_tile(1);
    CP_COMMIT();

    for (int it = 0; it < GNIT; it++) {
        CP_WAIT1();        // group(it) done; group(it+1) may be in flight
        __syncthreads();   // all warps past iter it-1 LDSM -> buf (it+2)%3 free
        if (it + 2 < GNIT) issue_tile(it + 2);
        CP_COMMIT();       // empty commits at tail keep the window math correct

        const uint32_t abuf = sb + (uint32_t)(it % 3) * (uint32_t)GBUF;
        const uint32_t wbuf = abuf + GMAT;
#pragma unroll
        for (int ks = 0; ks < 4; ks++) {
            const uint32_t offk = (uint32_t)ks * 32;
            uint32_t ah[4][4], bh[2][4];
#pragma unroll
            for (int fm = 0; fm < 4; fm++)
                LDSM4(ah[fm], abuf + apat + fm * (16 * GROWB) + offk);
#pragma unroll
            for (int p = 0; p < 2; p++)
                LDSM4(bh[p], wbuf + wpat + p * (16 * GROWB) + offk);
#pragma unroll
            for (int fm = 0; fm < 4; fm++)
#pragma unroll
                for (int fn = 0; fn < 4; fn++) {
                    const int p = fn >> 1, o = (fn & 1) << 1;
                    MMA16816(acc[fm][fn], ah[fm], bh[p][o], bh[p][o + 1]);
                }
        }
    }

    const int qrow = lid >> 2;
    const int qcol = (lid & 3) << 1;
#pragma unroll
    for (int fm = 0; fm < 4; fm++) {
        int m1 = bm + warp_m * 64 + fm * 16 + qrow;
        int m2 = m1 + 8;
#pragma unroll
        for (int fn = 0; fn < 4; fn++) {
            int n = bn + warp_n * 32 + fn * 8 + qcol;
            float2 bb = *(const float2*)(bias + n);
            float x1 = (acc[fm][fn][0] + bb.x) * scale;
            float y1 = (acc[fm][fn][1] + bb.y) * scale;
            float x2 = (acc[fm][fn][2] + bb.x) * scale;
            float y2 = (acc[fm][fn][3] + bb.y) * scale;
            if (OMODE == 0) {
                *(float2*)(C32 + (size_t)m1 * DM + n) = make_float2(x1, y1);
                *(float2*)(C32 + (size_t)m2 * DM + n) = make_float2(x2, y2);
            } else {
                int h = n >> 6, dl = n & 63;
                int b1 = m1 >> 11, s1 = m1 & 2047;
                int b2 = m2 >> 11, s2 = m2 & 2047;
                if (OMODE == 2) {
                    size_t i1 = (size_t)((((b1 << 4) + h) * SEQ + s1) << 6) + dl;
                    size_t i2 = (size_t)((((b2 << 4) + h) * SEQ + s2) << 6) + dl;
                    *(uint32_t*)(Ch + i1) = pack_h(x1, y1);
                    *(uint32_t*)(Ch + i2) = pack_h(x2, y2);
                } else {
                    size_t t1 = ((size_t)((b1 << 4) + h) * 64 + dl) * SEQ + s1;
                    size_t t2 = ((size_t)((b2 << 4) + h) * 64 + dl) * SEQ + s2;
                    Ch[t1] = __float2half_rn(x1);
                    Ch[t1 + SEQ] = __float2half_rn(y1);
                    Ch[t2] = __float2half_rn(x2);
                    Ch[t2 + SEQ] = __float2half_rn(y2);
                }
            }
        }
    }
}

// ===========================================================================
// fp16 flash attention, 3-stage K/VT pipeline (wait_group 1).
// ===========================================================================
#define AROWB 144
#define AQ1   0
#define ABUF  18432
#define ATT_SMEM (ABUF + 3 * 18432)   // 73728 -> 2 CTAs/SM
#define ANIT  (SEQ / 64)              // 32

__global__ __launch_bounds__(256, 2)
void attn_mma(const __half* __restrict__ Q1, const __half* __restrict__ K1,
              const __half* __restrict__ VT1, __half* __restrict__ O)
{
    extern __shared__ char smem[];
    const uint32_t sb = smem_u32(smem);
    const int tid = threadIdx.x, wid = tid >> 5, lid = tid & 31;
    const int grp = lid >> 3, r = lid & 7;

    const int bh = blockIdx.z * NH + blockIdx.y;
    const int q0 = blockIdx.x * 128;
    const __half* Qp = Q1  + (size_t)(bh * SEQ + q0) * DEPTH;
    const __half* Kp = K1  + (size_t)bh * SEQ * DEPTH;
    const __half* Vp = VT1 + (size_t)bh * DEPTH * SEQ;
    __half* Op = O + (size_t)(bh * SEQ + q0) * DEPTH;

    const int crow = tid >> 3;
    const int cch  = tid & 7;

    auto issue_tile = [&](int kt) {
        const uint32_t buf = sb + ABUF + (uint32_t)(kt % 3) * 18432u;
        const int s0 = kt * 64;
#pragma unroll
        for (int l = 0; l < 4; l++) {
            int mat = l >> 1;
            int row = ((l & 1) << 5) + crow;
            uint32_t dst = buf + (uint32_t)mat * 9216u
                         + (uint32_t)row * AROWB + (uint32_t)cch * 16;
            const __half* src = (mat == 0)
                ? Kp + (size_t)(s0 + row) * DEPTH + cch * 8
                : Vp + (size_t)row * SEQ + s0 + cch * 8;
            CP16(dst, src);
        }
    };

    // prologue: group0 = Q + tile0, group1 = tile1
#pragma unroll
    for (int l = 0; l < 4; l++) {
        int row = ((l & 3) << 5) + crow;
        uint32_t dst = sb + AQ1 + (uint32_t)row * AROWB + (uint32_t)cch * 16;
        CP16(dst, Qp + (size_t)row * DEPTH + cch * 8);
    }
    issue_tile(0);
    CP_COMMIT();
    issue_tile(1);
    CP_COMMIT();

    const uint32_t qbase = sb + AQ1
        + (uint32_t)(wid * 16 + ((grp & 1) << 3) + r) * AROWB
        + (uint32_t)(((grp >> 1) & 1) << 4);
    const uint32_t bpat  = (uint32_t)(((grp & 2) << 2) + r) * AROWB
                         + (uint32_t)((grp & 1) << 4);

    float o[8][4];
#pragma unroll
    for (int fn = 0; fn < 8; fn++)
#pragma unroll
        for (int e = 0; e < 4; e++) o[fn][e] = 0.f;
    float m1 = -1e30f, m2 = -1e30f, l1 = 0.f, l2 = 0.f;

    for (int kt = 0; kt < ANIT; kt++) {
        CP_WAIT1();        // group(kt) done (incl. Q at kt=0)
        __syncthreads();   // all warps past kt-1 LDSM -> buf (kt+2)%3 free
        if (kt + 2 < ANIT) issue_tile(kt + 2);
        CP_COMMIT();

        const uint32_t kvb = sb + ABUF + (uint32_t)(kt % 3) * 18432u + bpat;

        float s[8][4];
#pragma unroll
        for (int fn = 0; fn < 8; fn++)
#pragma unroll
            for (int e = 0; e < 4; e++) s[fn][e] = 0.f;

#pragma unroll
        for (int ks = 0; ks < 4; ks++) {
            uint32_t qh[4];
            LDSM4(qh, qbase + ks * 32);
            uint32_t kh[4][4];
#pragma unroll
            for (int p = 0; p < 4; p++)
                LDSM4(kh[p], kvb + p * (16 * AROWB) + ks * 32);
#pragma unroll
            for (int fn = 0; fn < 8; fn++) {
                const int p = fn >> 1, o2 = (fn & 1) << 1;
                MMA16816(s[fn], qh, kh[p][o2], kh[p][o2 + 1]);
            }
        }

        float mx1 = -1e30f, mx2 = -1e30f;
#pragma unroll
        for (int fn = 0; fn < 8; fn++) {
            mx1 = fmaxf(mx1, fmaxf(s[fn][0], s[fn][1]));
            mx2 = fmaxf(mx2, fmaxf(s[fn][2], s[fn][3]));
        }
        mx1 = fmaxf(mx1, __shfl_xor_sync(0xffffffffu, mx1, 1));
        mx1 = fmaxf(mx1, __shfl_xor_sync(0xffffffffu, mx1, 2));
        mx2 = fmaxf(mx2, __shfl_xor_sync(0xffffffffu, mx2, 1));
        mx2 = fmaxf(mx2, __shfl_xor_sync(0xffffffffu, mx2, 2));

        float mn1 = fmaxf(m1, mx1), mn2 = fmaxf(m2, mx2);
        float c1 = ex2(m1 - mn1), c2 = ex2(m2 - mn2);
        m1 = mn1; m2 = mn2;

        float rs1 = 0.f, rs2 = 0.f;
#pragma unroll
        for (int fn = 0; fn < 8; fn++) {
            s[fn][0] = ex2(s[fn][0] - m1);
            s[fn][1] = ex2(s[fn][1] - m1);
            s[fn][2] = ex2(s[fn][2] - m2);
            s[fn][3] = ex2(s[fn][3] - m2);
            rs1 += s[fn][0] + s[fn][1];
            rs2 += s[fn][2] + s[fn][3];
        }
        rs1 += __shfl_xor_sync(0xffffffffu, rs1, 1);
        rs1 += __shfl_xor_sync(0xffffffffu, rs1, 2);
        rs2 += __shfl_xor_sync(0xffffffffu, rs2, 1);
        rs2 += __shfl_xor_sync(0xffffffffu, rs2, 2);
        l1 = l1 * c1 + rs1;
        l2 = l2 * c2 + rs2;
#pragma unroll
        for (int fn = 0; fn < 8; fn++) {
            o[fn][0] *= c1; o[fn][1] *= c1;
            o[fn][2] *= c2; o[fn][3] *= c2;
        }

#pragma unroll
        for (int ks = 0; ks < 4; ks++) {
            uint32_t pah[4];
            pah[0] = pack_h(s[2 * ks][0],     s[2 * ks][1]);
            pah[1] = pack_h(s[2 * ks][2],     s[2 * ks][3]);
            pah[2] = pack_h(s[2 * ks + 1][0], s[2 * ks + 1][1]);
            pah[3] = pack_h(s[2 * ks + 1][2], s[2 * ks + 1][3]);
            uint32_t vh[4][4];
#pragma unroll
            for (int p = 0; p < 4; p++)
                LDSM4(vh[p], kvb + 9216 + p * (16 * AROWB) + ks * 32);
#pragma unroll
            for (int fn = 0; fn < 8; fn++) {
                const int p = fn >> 1, o2 = (fn & 1) << 1;
                MMA16816(o[fn], pah, vh[p][o2], vh[p][o2 + 1]);
            }
        }
    }

    float inv1 = 1.f / l1, inv2 = 1.f / l2;
    int qr1 = wid * 16 + (lid >> 2);
    int qr2 = qr1 + 8;
#pragma unroll
    for (int fn = 0; fn < 8; fn++) {
        int col = fn * 8 + (lid & 3) * 2;
        *(uint32_t*)(Op + qr1 * DEPTH + col) =
            pack_h(o[fn][0] * inv1, o[fn][1] * inv1);
        *(uint32_t*)(Op + qr2 * DEPTH + col) =
            pack_h(o[fn][2] * inv2, o[fn][3] * inv2);
    }
}

// ---------------------------------------------------------------------------
extern "C" void kernel_launch(void* const* d_in, const int* in_sizes, int n_in,
                              void* d_out, int out_size)
{
    const float* q  = (const float*)d_in[0];
    const float* k  = (const float*)d_in[1];
    const float* v  = (const float*)d_in[2];
    const float* wq = (const float*)d_in[3];
    const float* bq = (const float*)d_in[4];
    const float* wk = (const float*)d_in[5];
    const float* bk = (const float*)d_in[6];
    const float* wv = (const float*)d_in[7];
    const float* bv = (const float*)d_in[8];
    const float* wo = (const float*)d_in[9];
    const float* bo = (const float*)d_in[10];
    float* out = (float*)d_out;

    __half *gI, *gW, *gQ1, *gK1, *gV1, *gO16;
    cudaGetSymbolAddress((void**)&gI,   g_in16);
    cudaGetSymbolAddress((void**)&gW,   g_w16);
    cudaGetSymbolAddress((void**)&gQ1,  g_Q1);
    cudaGetSymbolAddress((void**)&gK1,  g_K1);
    cudaGetSymbolAddress((void**)&gV1,  g_VT1);
    cudaGetSymbolAddress((void**)&gO16, g_O16);

    cudaFuncSetAttribute(gemm_h<false, 2>,
                         cudaFuncAttributeMaxDynamicSharedMemorySize, GEMM_SMEM);
    cudaFuncSetAttribute(gemm_h<false, 3>,
                         cudaFuncAttributeMaxDynamicSharedMemorySize, GEMM_SMEM);
    cudaFuncSetAttribute(gemm_h<true, 0>,
                         cudaFuncAttributeMaxDynamicSharedMemorySize, GEMM_SMEM);
    cudaFuncSetAttribute(attn_mma,
                         cudaFuncAttributeMaxDynamicSharedMemorySize, ATT_SMEM);

    const int NIN = MTOT * DM / 4;
    const int NW  = DM * DM / 4;
    tofp16_z<<<dim3(NIN / 256, 1, 3), 256>>>(q, k, v, nullptr, gI, NIN);
    tofp16_z<<<dim3(NW / 256, 1, 4), 256>>>(wq, wk, wv, wo, gW, NW);

    dim3 gproj(MTOT / 128, DM / 128);  // (32, 8)

    gemm_h<false, 2><<<gproj, 256, GEMM_SMEM>>>(gI, gW, bq, nullptr,
                                                gQ1, QSCALE);
    gemm_h<false, 2><<<gproj, 256, GEMM_SMEM>>>(gI + MTOT*DM, gW + DM*DM, bk,
                                                nullptr, gK1, 1.0f);
    gemm_h<false, 3><<<gproj, 256, GEMM_SMEM>>>(gI + 2*MTOT*DM, gW + 2*DM*DM,
                                                bv, nullptr, gV1, 1.0f);

    attn_mma<<<dim3(SEQ / 128, NH, BATCH), 256, ATT_SMEM>>>(gQ1, gK1, gV1,
                                                            gO16);

    gemm_h<true, 0><<<gproj, 256, GEMM_SMEM>>>(gO16, gW + 3*DM*DM, bo, out,
                                               nullptr, 1.0f);
}

// round 17
// speedup vs baseline: 2.5216x; 1.0001x over previous
#include <cuda_runtime.h>
#include <cuda_fp16.h>
#include <cstdint>
#include <math.h>

#define BATCH 2
#define SEQ   2048
#define DM    1024
#define NH    16
#define DEPTH 64
#define MTOT  (BATCH*SEQ)   // 4096

#define QSCALE 0.1803368801111204f   // 0.125 * log2(e): scores in log2 domain

// Pre-converted fp16 scratch
__device__ __half g_in16[3*MTOT*DM];          // q,k,v flat [M,K] fp16
__device__ __half g_w16 [4*DM*DM];            // wq,wk,wv,wo fp16
__device__ __half g_Q1 [BATCH*NH*SEQ*DEPTH];  // [B,H,S,D], pre-scaled
__device__ __half g_K1 [BATCH*NH*SEQ*DEPTH];  // [B,H,S,D]
__device__ __half g_VT1[BATCH*NH*DEPTH*SEQ];  // [B,H,D,S]
__device__ __half g_O16[BATCH*NH*SEQ*DEPTH];  // attn out fp16 [B,H,S,D]

// ===========================================================================
// helpers
// ===========================================================================
__device__ __forceinline__ uint32_t smem_u32(const void* p) {
    uint32_t a;
    asm("{ .reg .u64 t; cvta.to.shared.u64 t, %1; cvt.u32.u64 %0, t; }"
        : "=r"(a) : "l"(p));
    return a;
}
__device__ __forceinline__ uint32_t pack_h(float x, float y) {
    __half2 h = __floats2half2_rn(x, y);
    return *(uint32_t*)&h;
}
__device__ __forceinline__ float ex2(float x) {
    float y; asm("ex2.approx.ftz.f32 %0, %1;" : "=f"(y) : "f"(x)); return y;
}
__device__ __forceinline__ uint32_t h2ex2(uint32_t x) {   // exp2 on half2
    uint32_t y; asm("ex2.approx.f16x2 %0, %1;" : "=r"(y) : "r"(x)); return y;
}

#define LDSM4(R, addr) \
    asm volatile("ldmatrix.sync.aligned.m8n8.x4.shared.b16 {%0,%1,%2,%3}, [%4];" \
        : "=r"((R)[0]), "=r"((R)[1]), "=r"((R)[2]), "=r"((R)[3]) : "r"(addr))

#define MMA16816(D, A, B0, B1) \
    asm volatile("mma.sync.aligned.m16n8k16.row.col.f32.f16.f16.f32 " \
        "{%0,%1,%2,%3}, {%4,%5,%6,%7}, {%8,%9}, {%0,%1,%2,%3};" \
        : "+f"((D)[0]), "+f"((D)[1]), "+f"((D)[2]), "+f"((D)[3]) \
        : "r"((A)[0]), "r"((A)[1]), "r"((A)[2]), "r"((A)[3]), "r"(B0), "r"(B1))

#define CP16(dst, src) \
    asm volatile("cp.async.cg.shared.global [%0], [%1], 16;" \
        :: "r"(dst), "l"(src) : "memory")
#define CP_COMMIT()  asm volatile("cp.async.commit_group;" ::: "memory")
#define CP_WAIT1()   asm volatile("cp.async.wait_group 1;" ::: "memory")

// ===========================================================================
// Pre-convert: fp32 -> fp16, z-batched
// ===========================================================================
__global__ __launch_bounds__(256)
void tofp16_z(const float* __restrict__ s0, const float* __restrict__ s1,
              const float* __restrict__ s2, const float* __restrict__ s3,
              __half* __restrict__ dst, int n4each)
{
    const float* src = (blockIdx.z == 0) ? s0 : (blockIdx.z == 1) ? s1
                     : (blockIdx.z == 2) ? s2 : s3;
    int i = blockIdx.x * 256 + threadIdx.x;
    if (i < n4each) {
        float4 v = ((const float4*)src)[i];
        ((uint2*)dst)[(size_t)blockIdx.z * n4each + i] =
            make_uint2(pack_h(v.x, v.y), pack_h(v.z, v.w));
    }
}

// ===========================================================================
// Pure-fp16 GEMM core, BK=64, 3-stage cp.async pipeline. 8 warps (2m x 4n).
// ===========================================================================
#define GROWB 144
#define GMAT  18432
#define GBUF  36864
#define GEMM_SMEM (3 * GBUF)           // 110592 -> 2 CTAs/SM
#define GNIT  (DM / 64)                // 16

// Fused QKV projection: blockIdx.z selects input/weight/bias/output.
__global__ __launch_bounds__(256, 2)
void gemm_qkv(const __half* __restrict__ I, const __half* __restrict__ Wall,
              const float* __restrict__ bq, const float* __restrict__ bk,
              const float* __restrict__ bv,
              __half* __restrict__ Q1, __half* __restrict__ K1,
              __half* __restrict__ VT1)
{
    extern __shared__ char smem[];
    const uint32_t sb = smem_u32(smem);

    const int z = blockIdx.z;
    const __half* A = I + (size_t)z * MTOT * DM;
    const __half* W = Wall + (size_t)z * DM * DM;
    const float* bias = (z == 0) ? bq : (z == 1) ? bk : bv;
    const float scale = (z == 0) ? QSCALE : 1.0f;

    const int tid = threadIdx.x;
    const int wid = tid >> 5, lid = tid & 31;
    const int warp_m = wid >> 2;
    const int warp_n = wid & 3;
    const int bm = blockIdx.x * 128, bn = blockIdx.y * 128;

    const int grp = lid >> 3, r = lid & 7;
    const uint32_t apat = (uint32_t)(warp_m * 64 + ((grp & 1) << 3) + r) * GROWB
                        + (uint32_t)(((grp >> 1) & 1) << 4);
    const uint32_t wpat = (uint32_t)(warp_n * 32 + (((grp >> 1) & 1) << 3) + r) * GROWB
                        + (uint32_t)((grp & 1) << 4);

    const int crow = tid >> 3;
    const int cch  = tid & 7;

    auto issue_tile = [&](int it) {
        const int k0 = it * 64;
        const uint32_t buf = sb + (uint32_t)(it % 3) * (uint32_t)GBUF;
#pragma unroll
        for (int l = 0; l < 8; l++) {
            int mat = l >> 2;
            int row = ((l & 3) << 5) + crow;
            uint32_t dst = buf + (uint32_t)mat * (uint32_t)GMAT
                         + (uint32_t)row * GROWB + (uint32_t)cch * 16;
            const __half* src = (mat == 0)
                ? A + (size_t)(bm + row) * DM + k0 + cch * 8
                : W + (size_t)(bn + row) * DM + k0 + cch * 8;
            CP16(dst, src);
        }
    };

    float acc[4][4][4];
#pragma unroll
    for (int i = 0; i < 4; i++)
#pragma unroll
        for (int j = 0; j < 4; j++)
#pragma unroll
            for (int e = 0; e < 4; e++) acc[i][j][e] = 0.f;

    issue_tile(0); CP_COMMIT();
    issue_tile(1); CP_COMMIT();

    for (int it = 0; it < GNIT; it++) {
        CP_WAIT1();
        __syncthreads();
        if (it + 2 < GNIT) issue_tile(it + 2);
        CP_COMMIT();

        const uint32_t abuf = sb + (uint32_t)(it % 3) * (uint32_t)GBUF;
        const uint32_t wbuf = abuf + GMAT;
#pragma unroll
        for (int ks = 0; ks < 4; ks++) {
            const uint32_t offk = (uint32_t)ks * 32;
            uint32_t ah[4][4], bh[2][4];
#pragma unroll
            for (int fm = 0; fm < 4; fm++)
                LDSM4(ah[fm], abuf + apat + fm * (16 * GROWB) + offk);
#pragma unroll
            for (int p = 0; p < 2; p++)
                LDSM4(bh[p], wbuf + wpat + p * (16 * GROWB) + offk);
#pragma unroll
            for (int fm = 0; fm < 4; fm++)
#pragma unroll
                for (int fn = 0; fn < 4; fn++) {
                    const int p = fn >> 1, o = (fn & 1) << 1;
                    MMA16816(acc[fm][fn], ah[fm], bh[p][o], bh[p][o + 1]);
                }
        }
    }

    const int qrow = lid >> 2;
    const int qcol = (lid & 3) << 1;
#pragma unroll
    for (int fm = 0; fm < 4; fm++) {
        int m1 = bm + warp_m * 64 + fm * 16 + qrow;
        int m2 = m1 + 8;
#pragma unroll
        for (int fn = 0; fn < 4; fn++) {
            int n = bn + warp_n * 32 + fn * 8 + qcol;
            float2 bb = *(const float2*)(bias + n);
            float x1 = (acc[fm][fn][0] + bb.x) * scale;
            float y1 = (acc[fm][fn][1] + bb.y) * scale;
            float x2 = (acc[fm][fn][2] + bb.x) * scale;
            float y2 = (acc[fm][fn][3] + bb.y) * scale;
            int h = n >> 6, dl = n & 63;
            int b1 = m1 >> 11, s1 = m1 & 2047;
            int b2 = m2 >> 11, s2 = m2 & 2047;
            if (z != 2) {
                __half* Ch = (z == 0) ? Q1 : K1;
                size_t i1 = (size_t)((((b1 << 4) + h) * SEQ + s1) << 6) + dl;
                size_t i2 = (size_t)((((b2 << 4) + h) * SEQ + s2) << 6) + dl;
                *(uint32_t*)(Ch + i1) = pack_h(x1, y1);
                *(uint32_t*)(Ch + i2) = pack_h(x2, y2);
            } else {
                size_t t1 = ((size_t)((b1 << 4) + h) * 64 + dl) * SEQ + s1;
                size_t t2 = ((size_t)((b2 << 4) + h) * 64 + dl) * SEQ + s2;
                VT1[t1] = __float2half_rn(x1);
                VT1[t1 + SEQ] = __float2half_rn(y1);
                VT1[t2] = __float2half_rn(x2);
                VT1[t2 + SEQ] = __float2half_rn(y2);
            }
        }
    }
}

// Output projection (GATHER_A from [B,H,S,D] fp16, fp32 out)
__global__ __launch_bounds__(256, 2)
void gemm_out(const __half* __restrict__ A, const __half* __restrict__ W,
              const float* __restrict__ bias, float* __restrict__ C32)
{
    extern __shared__ char smem[];
    const uint32_t sb = smem_u32(smem);

    const int tid = threadIdx.x;
    const int wid = tid >> 5, lid = tid & 31;
    const int warp_m = wid >> 2;
    const int warp_n = wid & 3;
    const int bm = blockIdx.x * 128, bn = blockIdx.y * 128;

    const int grp = lid >> 3, r = lid & 7;
    const uint32_t apat = (uint32_t)(warp_m * 64 + ((grp & 1) << 3) + r) * GROWB
                        + (uint32_t)(((grp >> 1) & 1) << 4);
    const uint32_t wpat = (uint32_t)(warp_n * 32 + (((grp >> 1) & 1) << 3) + r) * GROWB
                        + (uint32_t)((grp & 1) << 4);

    const int crow = tid >> 3;
    const int cch  = tid & 7;

    auto issue_tile = [&](int it) {
        const int k0 = it * 64;
        const uint32_t buf = sb + (uint32_t)(it % 3) * (uint32_t)GBUF;
#pragma unroll
        for (int l = 0; l < 8; l++) {
            int mat = l >> 2;
            int row = ((l & 3) << 5) + crow;
            uint32_t dst = buf + (uint32_t)mat * (uint32_t)GMAT
                         + (uint32_t)row * GROWB + (uint32_t)cch * 16;
            const __half* src;
            if (mat == 0) {
                int m = bm + row;
                int b = m >> 11, s = m & 2047;
                src = A + ((((b << 4) + it) * SEQ + s) << 6) + cch * 8;
            } else {
                src = W + (size_t)(bn + row) * DM + k0 + cch * 8;
            }
            CP16(dst, src);
        }
    };

    float acc[4][4][4];
#pragma unroll
    for (int i = 0; i < 4; i++)
#pragma unroll
        for (int j = 0; j < 4; j++)
#pragma unroll
            for (int e = 0; e < 4; e++) acc[i][j][e] = 0.f;

    issue_tile(0); CP_COMMIT();
    issue_tile(1); CP_COMMIT();

    for (int it = 0; it < GNIT; it++) {
        CP_WAIT1();
        __syncthreads();
        if (it + 2 < GNIT) issue_tile(it + 2);
        CP_COMMIT();

        const uint32_t abuf = sb + (uint32_t)(it % 3) * (uint32_t)GBUF;
        const uint32_t wbuf = abuf + GMAT;
#pragma unroll
        for (int ks = 0; ks < 4; ks++) {
            const uint32_t offk = (uint32_t)ks * 32;
            uint32_t ah[4][4], bh[2][4];
#pragma unroll
            for (int fm = 0; fm < 4; fm++)
                LDSM4(ah[fm], abuf + apat + fm * (16 * GROWB) + offk);
#pragma unroll
            for (int p = 0; p < 2; p++)
                LDSM4(bh[p], wbuf + wpat + p * (16 * GROWB) + offk);
#pragma unroll
            for (int fm = 0; fm < 4; fm++)
#pragma unroll
                for (int fn = 0; fn < 4; fn++) {
                    const int p = fn >> 1, o = (fn & 1) << 1;
                    MMA16816(acc[fm][fn], ah[fm], bh[p][o], bh[p][o + 1]);
                }
        }
    }

    const int qrow = lid >> 2;
    const int qcol = (lid & 3) << 1;
#pragma unroll
    for (int fm = 0; fm < 4; fm++) {
        int m1 = bm + warp_m * 64 + fm * 16 + qrow;
        int m2 = m1 + 8;
#pragma unroll
        for (int fn = 0; fn < 4; fn++) {
            int n = bn + warp_n * 32 + fn * 8 + qcol;
            float2 bb = *(const float2*)(bias + n);
            *(float2*)(C32 + (size_t)m1 * DM + n) =
                make_float2(acc[fm][fn][0] + bb.x, acc[fm][fn][1] + bb.y);
            *(float2*)(C32 + (size_t)m2 * DM + n) =
                make_float2(acc[fm][fn][2] + bb.x, acc[fm][fn][3] + bb.y);
        }
    }
}

// ===========================================================================
// fp16 flash attention, 3-stage pipeline, f16x2 exp2 softmax.
// ===========================================================================
#define AROWB 144
#define AQ1   0
#define ABUF  18432
#define ATT_SMEM (ABUF + 3 * 18432)   // 73728 -> 2 CTAs/SM
#define ANIT  (SEQ / 64)              // 32

__global__ __launch_bounds__(256, 2)
void attn_mma(const __half* __restrict__ Q1, const __half* __restrict__ K1,
              const __half* __restrict__ VT1, __half* __restrict__ O)
{
    extern __shared__ char smem[];
    const uint32_t sb = smem_u32(smem);
    const int tid = threadIdx.x, wid = tid >> 5, lid = tid & 31;
    const int grp = lid >> 3, r = lid & 7;

    const int bh = blockIdx.z * NH + blockIdx.y;
    const int q0 = blockIdx.x * 128;
    const __half* Qp = Q1  + (size_t)(bh * SEQ + q0) * DEPTH;
    const __half* Kp = K1  + (size_t)bh * SEQ * DEPTH;
    const __half* Vp = VT1 + (size_t)bh * DEPTH * SEQ;
    __half* Op = O + (size_t)(bh * SEQ + q0) * DEPTH;

    const int crow = tid >> 3;
    const int cch  = tid & 7;

    auto issue_tile = [&](int kt) {
        const uint32_t buf = sb + ABUF + (uint32_t)(kt % 3) * 18432u;
        const int s0 = kt * 64;
#pragma unroll
        for (int l = 0; l < 4; l++) {
            int mat = l >> 1;
            int row = ((l & 1) << 5) + crow;
            uint32_t dst = buf + (uint32_t)mat * 9216u
                         + (uint32_t)row * AROWB + (uint32_t)cch * 16;
            const __half* src = (mat == 0)
                ? Kp + (size_t)(s0 + row) * DEPTH + cch * 8
                : Vp + (size_t)row * SEQ + s0 + cch * 8;
            CP16(dst, src);
        }
    };

#pragma unroll
    for (int l = 0; l < 4; l++) {
        int row = ((l & 3) << 5) + crow;
        uint32_t dst = sb + AQ1 + (uint32_t)row * AROWB + (uint32_t)cch * 16;
        CP16(dst, Qp + (size_t)row * DEPTH + cch * 8);
    }
    issue_tile(0); CP_COMMIT();
    issue_tile(1); CP_COMMIT();

    const uint32_t qbase = sb + AQ1
        + (uint32_t)(wid * 16 + ((grp & 1) << 3) + r) * AROWB
        + (uint32_t)(((grp >> 1) & 1) << 4);
    const uint32_t bpat  = (uint32_t)(((grp & 2) << 2) + r) * AROWB
                         + (uint32_t)((grp & 1) << 4);

    float o[8][4];
#pragma unroll
    for (int fn = 0; fn < 8; fn++)
#pragma unroll
        for (int e = 0; e < 4; e++) o[fn][e] = 0.f;
    float m1 = -1e30f, m2 = -1e30f, l1 = 0.f, l2 = 0.f;

    for (int kt = 0; kt < ANIT; kt++) {
        CP_WAIT1();
        __syncthreads();
        if (kt + 2 < ANIT) issue_tile(kt + 2);
        CP_COMMIT();

        const uint32_t kvb = sb + ABUF + (uint32_t)(kt % 3) * 18432u + bpat;

        float s[8][4];
#pragma unroll
        for (int fn = 0; fn < 8; fn++)
#pragma unroll
            for (int e = 0; e < 4; e++) s[fn][e] = 0.f;

#pragma unroll
        for (int ks = 0; ks < 4; ks++) {
            uint32_t qh[4];
            LDSM4(qh, qbase + ks * 32);
            uint32_t kh[4][4];
#pragma unroll
            for (int p = 0; p < 4; p++)
                LDSM4(kh[p], kvb + p * (16 * AROWB) + ks * 32);
#pragma unroll
            for (int fn = 0; fn < 8; fn++) {
                const int p = fn >> 1, o2 = (fn & 1) << 1;
                MMA16816(s[fn], qh, kh[p][o2], kh[p][o2 + 1]);
            }
        }

        // ---- online softmax, exp2 in f16x2 ----
        float mx1 = -1e30f, mx2 = -1e30f;
#pragma unroll
        for (int fn = 0; fn < 8; fn++) {
            mx1 = fmaxf(mx1, fmaxf(s[fn][0], s[fn][1]));
            mx2 = fmaxf(mx2, fmaxf(s[fn][2], s[fn][3]));
        }
        mx1 = fmaxf(mx1, __shfl_xor_sync(0xffffffffu, mx1, 1));
        mx1 = fmaxf(mx1, __shfl_xor_sync(0xffffffffu, mx1, 2));
        mx2 = fmaxf(mx2, __shfl_xor_sync(0xffffffffu, mx2, 1));
        mx2 = fmaxf(mx2, __shfl_xor_sync(0xffffffffu, mx2, 2));

        float mn1 = fmaxf(m1, mx1), mn2 = fmaxf(m2, mx2);
        float c1 = ex2(m1 - mn1), c2 = ex2(m2 - mn2);
        m1 = mn1; m2 = mn2;

        // p = exp2(s - m) as packed half2 (these ARE the PV A-fragments)
        uint32_t e01[8], e23[8];
        float rs1 = 0.f, rs2 = 0.f;
#pragma unroll
        for (int fn = 0; fn < 8; fn++) {
            e01[fn] = h2ex2(pack_h(s[fn][0] - m1, s[fn][1] - m1));
            e23[fn] = h2ex2(pack_h(s[fn][2] - m2, s[fn][3] - m2));
            float2 f01 = __half22float2(*(__half2*)&e01[fn]);
            float2 f23 = __half22float2(*(__half2*)&e23[fn]);
            rs1 += f01.x + f01.y;
            rs2 += f23.x + f23.y;
        }
        rs1 += __shfl_xor_sync(0xffffffffu, rs1, 1);
        rs1 += __shfl_xor_sync(0xffffffffu, rs1, 2);
        rs2 += __shfl_xor_sync(0xffffffffu, rs2, 1);
        rs2 += __shfl_xor_sync(0xffffffffu, rs2, 2);
        l1 = l1 * c1 + rs1;
        l2 = l2 * c2 + rs2;
#pragma unroll
        for (int fn = 0; fn < 8; fn++) {
            o[fn][0] *= c1; o[fn][1] *= c1;
            o[fn][2] *= c2; o[fn][3] *= c2;
        }

        // ---- O += P @ V ----
#pragma unroll
        for (int ks = 0; ks < 4; ks++) {
            uint32_t pah[4];
            pah[0] = e01[2 * ks];
            pah[1] = e23[2 * ks];
            pah[2] = e01[2 * ks + 1];
            pah[3] = e23[2 * ks + 1];
            uint32_t vh[4][4];
#pragma unroll
            for (int p = 0; p < 4; p++)
                LDSM4(vh[p], kvb + 9216 + p * (16 * AROWB) + ks * 32);
#pragma unroll
            for (int fn = 0; fn < 8; fn++) {
                const int p = fn >> 1, o2 = (fn & 1) << 1;
                MMA16816(o[fn], pah, vh[p][o2], vh[p][o2 + 1]);
            }
        }
    }

    float inv1 = 1.f / l1, inv2 = 1.f / l2;
    int qr1 = wid * 16 + (lid >> 2);
    int qr2 = qr1 + 8;
#pragma unroll
    for (int fn = 0; fn < 8; fn++) {
        int col = fn * 8 + (lid & 3) * 2;
        *(uint32_t*)(Op + qr1 * DEPTH + col) =
            pack_h(o[fn][0] * inv1, o[fn][1] * inv1);
        *(uint32_t*)(Op + qr2 * DEPTH + col) =
            pack_h(o[fn][2] * inv2, o[fn][3] * inv2);
    }
}

// ---------------------------------------------------------------------------
extern "C" void kernel_launch(void* const* d_in, const int* in_sizes, int n_in,
                              void* d_out, int out_size)
{
    const float* q  = (const float*)d_in[0];
    const float* k  = (const float*)d_in[1];
    const float* v  = (const float*)d_in[2];
    const float* wq = (const float*)d_in[3];
    const float* bq = (const float*)d_in[4];
    const float* wk = (const float*)d_in[5];
    const float* bk = (const float*)d_in[6];
    const float* wv = (const float*)d_in[7];
    const float* bv = (const float*)d_in[8];
    const float* wo = (const float*)d_in[9];
    const float* bo = (const float*)d_in[10];
    float* out = (float*)d_out;

    __half *gI, *gW, *gQ1, *gK1, *gV1, *gO16;
    cudaGetSymbolAddress((void**)&gI,   g_in16);
    cudaGetSymbolAddress((void**)&gW,   g_w16);
    cudaGetSymbolAddress((void**)&gQ1,  g_Q1);
    cudaGetSymbolAddress((void**)&gK1,  g_K1);
    cudaGetSymbolAddress((void**)&gV1,  g_VT1);
    cudaGetSymbolAddress((void**)&gO16, g_O16);

    cudaFuncSetAttribute(gemm_qkv,
                         cudaFuncAttributeMaxDynamicSharedMemorySize, GEMM_SMEM);
    cudaFuncSetAttribute(gemm_out,
                         cudaFuncAttributeMaxDynamicSharedMemorySize, GEMM_SMEM);
    cudaFuncSetAttribute(attn_mma,
                         cudaFuncAttributeMaxDynamicSharedMemorySize, ATT_SMEM);

    const int NIN = MTOT * DM / 4;
    const int NW  = DM * DM / 4;
    tofp16_z<<<dim3(NIN / 256, 1, 3), 256>>>(q, k, v, nullptr, gI, NIN);
    tofp16_z<<<dim3(NW / 256, 1, 4), 256>>>(wq, wk, wv, wo, gW, NW);

    gemm_qkv<<<dim3(MTOT / 128, DM / 128, 3), 256, GEMM_SMEM>>>(
        gI, gW, bq, bk, bv, gQ1, gK1, gV1);

    attn_mma<<<dim3(SEQ / 128, NH, BATCH), 256, ATT_SMEM>>>(gQ1, gK1, gV1,
                                                            gO16);

    gemm_out<<<dim3(MTOT / 128, DM / 128), 256, GEMM_SMEM>>>(gO16, gW + 3*DM*DM,
                                                             bo, out);
}